// round 8
// baseline (speedup 1.0000x reference)
#include <cuda_runtime.h>
#include <math.h>

#define Bn 16
#define Tn 12
#define Nn 325
#define Fn 64
#define KHn 4
#define Dn 16
#define KDn 3
#define BTn (Bn*Tn)            // 192
#define BTNn (BTn*Nn)          // 62400
#define NNn (Nn*Nn)            // 105625

// ---------------- scratch (device globals; no allocation allowed) ----------------
__device__ float g_q [KHn*BTNn*Dn + 16];
__device__ float g_k [KHn*BTNn*Dn + 16];
__device__ float g_ks[KHn*BTNn*Dn + 16];
__device__ float g_v [KHn*BTNn*Dn + 16];
__device__ float g_vs[KHn*BTNn*Dn + 16];
__device__ float g_biasT[KHn*NNn + 2048];   // transposed [h][m][n]
__device__ float g_val[BTNn*Fn];

// work-stealing counters (reset by bias_kernel each launch; stream order guarantees visibility)
__device__ int g_ctr_proj[5];
__device__ int g_ctr_attn;
__device__ int g_ctr_ffn;

// ---------------- kernel 1: graph-diffusion bias, transposed output ----------------
__global__ void bias_kernel(const float* __restrict__ A, const float* __restrict__ AT,
                            const float* __restrict__ Wdi, const float* __restrict__ Wdo)
{
    if (blockIdx.x == 0 && blockIdx.y == 0 && blockIdx.z == 0 &&
        threadIdx.x == 0 && threadIdx.y == 0) {
        g_ctr_proj[0] = 0; g_ctr_proj[1] = 0; g_ctr_proj[2] = 0;
        g_ctr_proj[3] = 0; g_ctr_proj[4] = 0;
        g_ctr_attn = 0; g_ctr_ffn = 0;
    }

    __shared__ float tile[32][33];
    int h = blockIdx.z;
    int n0 = blockIdx.x*32, m0 = blockIdx.y*32;
    int tx = threadIdx.x, ty = threadIdx.y;    // 32 x 8

#pragma unroll
    for (int k = 0; k < 4; ++k) {
        int n = n0 + ty + 8*k, m = m0 + tx;
        float s = 0.f;
        if (n < Nn && m < Nn) {
            int nm = n*Nn + m;
            if (h < 2) {
#pragma unroll
                for (int j = 0; j < KDn; ++j) s = fmaf(Wdi[(h*KDn+j)*NNn+nm], A[j*NNn+nm], s);
            } else {
#pragma unroll
                for (int j = 0; j < KDn; ++j) s = fmaf(Wdo[((h-2)*KDn+j)*NNn+nm], AT[j*NNn+nm], s);
            }
        }
        tile[ty + 8*k][tx] = s;
    }
    __syncthreads();
#pragma unroll
    for (int k = 0; k < 4; ++k) {
        int m = m0 + ty + 8*k, n = n0 + tx;
        if (m < Nn && n < Nn)
            g_biasT[(size_t)h*NNn + (size_t)m*Nn + n] = tile[tx][ty + 8*k];
    }
}

// ---------------- kernel 2: projection (persistent; per-warp dynamic chunks) ----------------
__global__ __launch_bounds__(256, 4) void proj_kernel(
    const float* __restrict__ x,
    const float* __restrict__ Wq,  const float* __restrict__ bq,
    const float* __restrict__ Wk,  const float* __restrict__ bk,
    const float* __restrict__ Wks, const float* __restrict__ bks,
    const float* __restrict__ Wv,  const float* __restrict__ bv,
    const float* __restrict__ Wvs, const float* __restrict__ bvs)
{
    extern __shared__ float sm[];
    float* sW   = sm;                 // 64*68 = 4352
    float* sb   = sm + 4352;          // 64
    float* srow = sm + 4416;          // 8 warps * 512 = 4096

    int p = blockIdx.y;
    const float* W = (p==0)?Wq:(p==1)?Wk:(p==2)?Wks:(p==3)?Wv:Wvs;
    const float* bb = (p==0)?bq:(p==1)?bk:(p==2)?bks:(p==3)?bv:bvs;
    float* o = (p==0)?g_q:(p==1)?g_k:(p==2)?g_ks:(p==3)?g_v:g_vs;

    for (int i = threadIdx.x; i < 4096; i += 256) {
        int f = i >> 6, c = i & 63;
        sW[f*68 + c] = W[i];
    }
    if (threadIdx.x < 64) sb[threadIdx.x] = bb[threadIdx.x];
    __syncthreads();

    int warp = threadIdx.x >> 5, lane = threadIdx.x & 31;
    float* myrow = srow + warp*512;
    int f0 = lane, f1 = lane + 32;
    int h0 = f0 >> 4, d0 = f0 & 15;
    int h1 = f1 >> 4, d1 = f1 & 15;
    float bb0 = sb[f0], bb1 = sb[f1];

    for (;;) {
        int chunk;
        if (lane == 0) chunk = atomicAdd(&g_ctr_proj[p], 1);
        chunk = __shfl_sync(0xffffffffu, chunk, 0);
        if (chunk >= 7800) break;           // 62400/8 chunks of 8 rows
        int r0 = chunk * 8;
        {
            const float* xs = x + (size_t)r0*64;
            for (int i = lane; i < 512; i += 32) myrow[i] = xs[i];
        }
        __syncwarp();

        float acc0[8], acc1[8];
#pragma unroll
        for (int r = 0; r < 8; ++r) { acc0[r] = bb0; acc1[r] = bb1; }
#pragma unroll 4
        for (int c = 0; c < 64; c += 4) {
            float4 w0 = *(const float4*)(sW + f0*68 + c);
            float4 w1 = *(const float4*)(sW + f1*68 + c);
#pragma unroll
            for (int r = 0; r < 8; ++r) {
                float4 xv = *(const float4*)(myrow + r*64 + c);
                acc0[r] = fmaf(xv.x, w0.x, acc0[r]);
                acc1[r] = fmaf(xv.x, w1.x, acc1[r]);
                acc0[r] = fmaf(xv.y, w0.y, acc0[r]);
                acc1[r] = fmaf(xv.y, w1.y, acc1[r]);
                acc0[r] = fmaf(xv.z, w0.z, acc0[r]);
                acc1[r] = fmaf(xv.z, w1.z, acc1[r]);
                acc0[r] = fmaf(xv.w, w0.w, acc0[r]);
                acc1[r] = fmaf(xv.w, w1.w, acc1[r]);
            }
        }
#pragma unroll
        for (int r = 0; r < 8; ++r) {
            size_t rr = (size_t)(r0 + r);
            o[((size_t)h0*BTNn + rr)*Dn + d0] = acc0[r];
            o[((size_t)h1*BTNn + rr)*Dn + d1] = acc1[r];
        }
        __syncwarp();
    }
}

// ---------------- kernel 3: attention (persistent blocks, dynamic (bt,h) tiles) ----------------
#define ATH 352
__global__ __launch_bounds__(ATH, 3) void attn_kernel()
{
    extern __shared__ float sm[];
    float* sk = sm;              // 325*16 = 5200
    float* sv = sm + 5200;       // 5200
    __shared__ int s_tile;

    int n = threadIdx.x;

    for (;;) {
        if (threadIdx.x == 0) s_tile = atomicAdd(&g_ctr_attn, 1);
        __syncthreads();                       // publishes s_tile; also fences smem reuse
        int tile = s_tile;
        if (tile >= BTn*KHn) break;
        int h = tile / BTn;
        int bt = tile - h*BTn;
        size_t base = ((size_t)h*BTNn + (size_t)bt*Nn)*Dn;

        {
            const float4* kb = (const float4*)(g_k + base);
            const float4* vb = (const float4*)(g_v + base);
            float4* k4 = (float4*)sk;
            float4* v4 = (float4*)sv;
            for (int i = threadIdx.x; i < Nn*Dn/4; i += ATH) {
                k4[i] = kb[i];
                v4[i] = vb[i];
            }
        }
        __syncthreads();

        if (n < Nn) {
            float q[16], o[16];
            float l = 0.f;
            float es;
            {
                const float4* qp = (const float4*)(g_q  + base + (size_t)n*Dn);
                const float4* kp = (const float4*)(g_ks + base + (size_t)n*Dn);
                float s = 0.f;
#pragma unroll
                for (int i = 0; i < 4; ++i) {
                    float4 qv = qp[i], kv = kp[i];
                    q[i*4+0]=qv.x; q[i*4+1]=qv.y; q[i*4+2]=qv.z; q[i*4+3]=qv.w;
                    s = fmaf(qv.x,kv.x, fmaf(qv.y,kv.y, fmaf(qv.z,kv.z, fmaf(qv.w,kv.w, s))));
                }
                es = 1.f/(1.f + __expf(-s*0.25f));
#pragma unroll
                for (int d = 0; d < 16; ++d) o[d] = 0.f;
            }

            const float* bT = g_biasT + (size_t)h*NNn + n;

#pragma unroll 5
            for (int m = 0; m < Nn; ++m) {
                float bval = __ldg(bT + (size_t)m*Nn);
                const float4* kr = (const float4*)(sk + m*16);
                float4 k0 = kr[0], k1 = kr[1], k2 = kr[2], k3 = kr[3];
                float s;
                s  = q[0]*k0.x;             s = fmaf(q[1],k0.y,s);
                s = fmaf(q[2],k0.z,s);      s = fmaf(q[3],k0.w,s);
                s = fmaf(q[4],k1.x,s);      s = fmaf(q[5],k1.y,s);
                s = fmaf(q[6],k1.z,s);      s = fmaf(q[7],k1.w,s);
                s = fmaf(q[8],k2.x,s);      s = fmaf(q[9],k2.y,s);
                s = fmaf(q[10],k2.z,s);     s = fmaf(q[11],k2.w,s);
                s = fmaf(q[12],k3.x,s);     s = fmaf(q[13],k3.y,s);
                s = fmaf(q[14],k3.z,s);     s = fmaf(q[15],k3.w,s);
                float e = fmaf(s, 0.25f, bval);
                float p = __expf(e);
                l += p;
                const float4* vr = (const float4*)(sv + m*16);
                float4 v0 = vr[0], v1 = vr[1], v2 = vr[2], v3 = vr[3];
                o[0]  = fmaf(p, v0.x, o[0]);  o[1]  = fmaf(p, v0.y, o[1]);
                o[2]  = fmaf(p, v0.z, o[2]);  o[3]  = fmaf(p, v0.w, o[3]);
                o[4]  = fmaf(p, v1.x, o[4]);  o[5]  = fmaf(p, v1.y, o[5]);
                o[6]  = fmaf(p, v1.z, o[6]);  o[7]  = fmaf(p, v1.w, o[7]);
                o[8]  = fmaf(p, v2.x, o[8]);  o[9]  = fmaf(p, v2.y, o[9]);
                o[10] = fmaf(p, v2.z, o[10]); o[11] = fmaf(p, v2.w, o[11]);
                o[12] = fmaf(p, v3.x, o[12]); o[13] = fmaf(p, v3.y, o[13]);
                o[14] = fmaf(p, v3.z, o[14]); o[15] = fmaf(p, v3.w, o[15]);
            }

            {
                float inv = 1.f/(es + l);
                const float4* vsp = (const float4*)(g_vs + base + (size_t)n*Dn);
                float* outp = g_val + ((size_t)bt*Nn + n)*Fn + h*Dn;
#pragma unroll
                for (int i = 0; i < 4; ++i) {
                    float4 vs = vsp[i];
                    float4 r;
                    r.x = fmaf(o[i*4+0] - l*vs.x, inv, vs.x);
                    r.y = fmaf(o[i*4+1] - l*vs.y, inv, vs.y);
                    r.z = fmaf(o[i*4+2] - l*vs.z, inv, vs.z);
                    r.w = fmaf(o[i*4+3] - l*vs.w, inv, vs.w);
                    *(float4*)(outp + i*4) = r;
                }
            }
        }
        __syncthreads();       // compute done before next tile's staging overwrites smem
    }
}

// ---------------- kernel 4: FFN(gelu) + residual + LayerNorm (per-warp dynamic chunks) ----------------
__global__ __launch_bounds__(256, 4) void ffn_kernel(
    const float* __restrict__ x,
    const float* __restrict__ Wf1, const float* __restrict__ bf1,
    const float* __restrict__ Wf2, const float* __restrict__ bf2,
    const float* __restrict__ gln, const float* __restrict__ bln,
    float* __restrict__ out)
{
    extern __shared__ float sm[];
    float* sW1 = sm;            // 4352
    float* sW2 = sm + 4352;     // 4352
    float* sb1 = sm + 8704;     // 64
    float* sb2 = sm + 8768;     // 64
    float* sg  = sm + 8832;     // 64
    float* sbl = sm + 8896;     // 64
    float* srow = sm + 8960;    // 8 * 512 = 4096

    for (int i = threadIdx.x; i < 4096; i += 256) {
        int f = i >> 6, c = i & 63;
        sW1[f*68+c] = Wf1[i];
        sW2[f*68+c] = Wf2[i];
    }
    if (threadIdx.x < 64) {
        sb1[threadIdx.x] = bf1[threadIdx.x];
        sb2[threadIdx.x] = bf2[threadIdx.x];
        sg [threadIdx.x] = gln[threadIdx.x];
        sbl[threadIdx.x] = bln[threadIdx.x];
    }
    __syncthreads();

    int warp = threadIdx.x >> 5, lane = threadIdx.x & 31;
    float* myrow = srow + warp*512;
    int f0 = lane, f1 = lane + 32;

    for (;;) {
        int chunk;
        if (lane == 0) chunk = atomicAdd(&g_ctr_ffn, 1);
        chunk = __shfl_sync(0xffffffffu, chunk, 0);
        if (chunk >= 7800) break;           // 62400/8
        int r0 = chunk * 8;
        {
            const float* vs = g_val + (size_t)r0*64;
            for (int i = lane; i < 512; i += 32) myrow[i] = vs[i];
        }
        __syncwarp();

        float t0[8], t1[8];
#pragma unroll
        for (int r = 0; r < 8; ++r) { t0[r] = sb1[f0]; t1[r] = sb1[f1]; }
#pragma unroll 4
        for (int c = 0; c < 64; c += 4) {
            float4 w0 = *(const float4*)(sW1 + f0*68 + c);
            float4 w1 = *(const float4*)(sW1 + f1*68 + c);
#pragma unroll
            for (int r = 0; r < 8; ++r) {
                float4 xv = *(const float4*)(myrow + r*64 + c);
                t0[r] = fmaf(xv.x, w0.x, t0[r]);  t1[r] = fmaf(xv.x, w1.x, t1[r]);
                t0[r] = fmaf(xv.y, w0.y, t0[r]);  t1[r] = fmaf(xv.y, w1.y, t1[r]);
                t0[r] = fmaf(xv.z, w0.z, t0[r]);  t1[r] = fmaf(xv.z, w1.z, t1[r]);
                t0[r] = fmaf(xv.w, w0.w, t0[r]);  t1[r] = fmaf(xv.w, w1.w, t1[r]);
            }
        }
        // exact gelu
#pragma unroll
        for (int r = 0; r < 8; ++r) {
            t0[r] = 0.5f*t0[r]*(1.f + erff(t0[r]*0.7071067811865476f));
            t1[r] = 0.5f*t1[r]*(1.f + erff(t1[r]*0.7071067811865476f));
        }
        __syncwarp();
#pragma unroll
        for (int r = 0; r < 8; ++r) { myrow[r*64+f0] = t0[r]; myrow[r*64+f1] = t1[r]; }
        __syncwarp();

        float h0[8], h1[8];
        const float* xr = x + (size_t)r0*64;
#pragma unroll
        for (int r = 0; r < 8; ++r) {
            h0[r] = sb2[f0] + xr[r*64+f0];
            h1[r] = sb2[f1] + xr[r*64+f1];
        }
#pragma unroll 4
        for (int c = 0; c < 64; c += 4) {
            float4 w0 = *(const float4*)(sW2 + f0*68 + c);
            float4 w1 = *(const float4*)(sW2 + f1*68 + c);
#pragma unroll
            for (int r = 0; r < 8; ++r) {
                float4 xv = *(const float4*)(myrow + r*64 + c);
                h0[r] = fmaf(xv.x, w0.x, h0[r]);  h1[r] = fmaf(xv.x, w1.x, h1[r]);
                h0[r] = fmaf(xv.y, w0.y, h0[r]);  h1[r] = fmaf(xv.y, w1.y, h1[r]);
                h0[r] = fmaf(xv.z, w0.z, h0[r]);  h1[r] = fmaf(xv.z, w1.z, h1[r]);
                h0[r] = fmaf(xv.w, w0.w, h0[r]);  h1[r] = fmaf(xv.w, w1.w, h1[r]);
            }
        }
#pragma unroll
        for (int r = 0; r < 8; ++r) {
            float s1 = h0[r] + h1[r];
            float s2 = fmaf(h0[r], h0[r], h1[r]*h1[r]);
#pragma unroll
            for (int oo = 16; oo; oo >>= 1) {
                s1 += __shfl_xor_sync(0xffffffffu, s1, oo);
                s2 += __shfl_xor_sync(0xffffffffu, s2, oo);
            }
            float mean = s1 * (1.f/64.f);
            float var  = s2 * (1.f/64.f) - mean*mean;
            float rs   = rsqrtf(var + 1e-5f);
            out[(size_t)(r0+r)*64 + f0] = fmaf(sg[f0], (h0[r]-mean)*rs, sbl[f0]);
            out[(size_t)(r0+r)*64 + f1] = fmaf(sg[f1], (h1[r]-mean)*rs, sbl[f1]);
        }
        __syncwarp();
    }
}

// ---------------- launch ----------------
extern "C" void kernel_launch(void* const* d_in, const int* in_sizes, int n_in,
                              void* d_out, int out_size)
{
    const float* x   = (const float*)d_in[0];
    const float* A   = (const float*)d_in[1];
    const float* AT  = (const float*)d_in[2];
    const float* Wq  = (const float*)d_in[3];
    const float* bq  = (const float*)d_in[4];
    const float* Wk  = (const float*)d_in[5];
    const float* bk  = (const float*)d_in[6];
    const float* Wks = (const float*)d_in[7];
    const float* bks = (const float*)d_in[8];
    const float* Wv  = (const float*)d_in[9];
    const float* bv  = (const float*)d_in[10];
    const float* Wvs = (const float*)d_in[11];
    const float* bvs = (const float*)d_in[12];
    const float* Wdi = (const float*)d_in[13];
    const float* Wdo = (const float*)d_in[14];
    const float* Wf1 = (const float*)d_in[15];
    const float* bf1 = (const float*)d_in[16];
    const float* Wf2 = (const float*)d_in[17];
    const float* bf2 = (const float*)d_in[18];
    const float* gln = (const float*)d_in[19];
    const float* bln = (const float*)d_in[20];
    float* out = (float*)d_out;

    cudaFuncSetAttribute(proj_kernel, cudaFuncAttributeMaxDynamicSharedMemorySize, 34048);
    cudaFuncSetAttribute(attn_kernel, cudaFuncAttributeMaxDynamicSharedMemorySize, 41600);
    cudaFuncSetAttribute(ffn_kernel,  cudaFuncAttributeMaxDynamicSharedMemorySize, 52224);

    dim3 bg(11, 11, 4);
    bias_kernel<<<bg, dim3(32, 8)>>>(A, AT, Wdi, Wdo);
    dim3 pg(118, 5);
    proj_kernel<<<pg, 256, 34048>>>(x, Wq, bq, Wk, bk, Wks, bks, Wv, bv, Wvs, bvs);
    attn_kernel<<<444, ATH, 41600>>>();
    ffn_kernel<<<592, 256, 52224>>>(x, Wf1, bf1, Wf2, bf2, gln, bln, out);
}

// round 9
// speedup vs baseline: 1.3878x; 1.3878x over previous
#include <cuda_runtime.h>
#include <cuda_fp16.h>
#include <math.h>

#define Bn 16
#define Tn 12
#define Nn 325
#define Fn 64
#define KHn 4
#define Dn 16
#define KDn 3
#define BTn (Bn*Tn)            // 192
#define BTNn (BTn*Nn)          // 62400
#define NNn (Nn*Nn)            // 105625

// ---------------- scratch (device globals; no allocation allowed) ----------------
__device__ float g_q [KHn*BTNn*Dn + 16];
__device__ float g_k [KHn*BTNn*Dn + 16];
__device__ float g_ks[KHn*BTNn*Dn + 16];
__device__ float g_v [KHn*BTNn*Dn + 16];
__device__ float g_vs[KHn*BTNn*Dn + 16];
__device__ float g_biasT[KHn*NNn + 2048];   // transposed [h][m][n]
__device__ float g_val[BTNn*Fn];

// ---------------- kernel 1: graph-diffusion bias, transposed output ----------------
__global__ void bias_kernel(const float* __restrict__ A, const float* __restrict__ AT,
                            const float* __restrict__ Wdi, const float* __restrict__ Wdo)
{
    __shared__ float tile[32][33];
    int h = blockIdx.z;
    int n0 = blockIdx.x*32, m0 = blockIdx.y*32;
    int tx = threadIdx.x, ty = threadIdx.y;    // 32 x 8

#pragma unroll
    for (int k = 0; k < 4; ++k) {
        int n = n0 + ty + 8*k, m = m0 + tx;
        float s = 0.f;
        if (n < Nn && m < Nn) {
            int nm = n*Nn + m;
            if (h < 2) {
#pragma unroll
                for (int j = 0; j < KDn; ++j) s = fmaf(Wdi[(h*KDn+j)*NNn+nm], A[j*NNn+nm], s);
            } else {
#pragma unroll
                for (int j = 0; j < KDn; ++j) s = fmaf(Wdo[((h-2)*KDn+j)*NNn+nm], AT[j*NNn+nm], s);
            }
        }
        tile[ty + 8*k][tx] = s;
    }
    __syncthreads();
#pragma unroll
    for (int k = 0; k < 4; ++k) {
        int m = m0 + ty + 8*k, n = n0 + tx;
        if (m < Nn && n < Nn)
            g_biasT[(size_t)h*NNn + (size_t)m*Nn + n] = tile[tx][ty + 8*k];
    }
}

// ---------------- kernel 2: projection (persistent; grid (148,5)) ----------------
__global__ __launch_bounds__(256) void proj_kernel(
    const float* __restrict__ x,
    const float* __restrict__ Wq,  const float* __restrict__ bq,
    const float* __restrict__ Wk,  const float* __restrict__ bk,
    const float* __restrict__ Wks, const float* __restrict__ bks,
    const float* __restrict__ Wv,  const float* __restrict__ bv,
    const float* __restrict__ Wvs, const float* __restrict__ bvs)
{
    extern __shared__ float sm[];
    float* sW   = sm;                 // 64*68 = 4352
    float* sb   = sm + 4352;          // 64
    float* srow = sm + 4416;          // 8 warps * 512 = 4096

    int p = blockIdx.y;
    const float* W = (p==0)?Wq:(p==1)?Wk:(p==2)?Wks:(p==3)?Wv:Wvs;
    const float* bb = (p==0)?bq:(p==1)?bk:(p==2)?bks:(p==3)?bv:bvs;
    float* o = (p==0)?g_q:(p==1)?g_k:(p==2)?g_ks:(p==3)?g_v:g_vs;

    for (int i = threadIdx.x; i < 4096; i += 256) {
        int f = i >> 6, c = i & 63;
        sW[f*68 + c] = W[i];
    }
    if (threadIdx.x < 64) sb[threadIdx.x] = bb[threadIdx.x];
    __syncthreads();

    int warp = threadIdx.x >> 5, lane = threadIdx.x & 31;
    float* myrow = srow + warp*512;
    int f0 = lane, f1 = lane + 32;
    int h0 = f0 >> 4, d0 = f0 & 15;
    int h1 = f1 >> 4, d1 = f1 & 15;
    float bb0 = sb[f0], bb1 = sb[f1];

    for (int blk = blockIdx.x; blk < 975; blk += 148) {
        int r0 = blk * 64 + warp * 8;
        {
            const float* xs = x + (size_t)r0*64;
            for (int i = lane; i < 512; i += 32) myrow[i] = xs[i];
        }
        __syncwarp();

        float acc0[8], acc1[8];
#pragma unroll
        for (int r = 0; r < 8; ++r) { acc0[r] = bb0; acc1[r] = bb1; }
#pragma unroll 4
        for (int c = 0; c < 64; c += 4) {
            float4 w0 = *(const float4*)(sW + f0*68 + c);
            float4 w1 = *(const float4*)(sW + f1*68 + c);
#pragma unroll
            for (int r = 0; r < 8; ++r) {
                float4 xv = *(const float4*)(myrow + r*64 + c);
                acc0[r] = fmaf(xv.x, w0.x, acc0[r]);
                acc1[r] = fmaf(xv.x, w1.x, acc1[r]);
                acc0[r] = fmaf(xv.y, w0.y, acc0[r]);
                acc1[r] = fmaf(xv.y, w1.y, acc1[r]);
                acc0[r] = fmaf(xv.z, w0.z, acc0[r]);
                acc1[r] = fmaf(xv.z, w1.z, acc1[r]);
                acc0[r] = fmaf(xv.w, w0.w, acc0[r]);
                acc1[r] = fmaf(xv.w, w1.w, acc1[r]);
            }
        }
#pragma unroll
        for (int r = 0; r < 8; ++r) {
            size_t rr = (size_t)(r0 + r);
            o[((size_t)h0*BTNn + rr)*Dn + d0] = acc0[r];
            o[((size_t)h1*BTNn + rr)*Dn + d1] = acc1[r];
        }
        __syncwarp();
    }
}

// ---------------- kernel 3: attention (thread per query; fp16 scores, fp32 AV) ----------------
#define ATH 352
__global__ __launch_bounds__(ATH, 3) void attn_kernel()
{
    extern __shared__ float sm[];
    float*  sv  = sm;                        // 325*16 floats = 20800 B
    __half* skh = (__half*)(sm + 5200);      // 325*16 halves = 10400 B

    int bt = blockIdx.x, h = blockIdx.y;
    size_t base = ((size_t)h*BTNn + (size_t)bt*Nn)*Dn;

    {
        const float4* kb = (const float4*)(g_k + base);
        const float4* vb = (const float4*)(g_v + base);
        float4* v4 = (float4*)sv;
        __half2* k2 = (__half2*)skh;
        for (int i = threadIdx.x; i < Nn*Dn/4; i += ATH) {
            float4 kv = kb[i];
            v4[i] = vb[i];
            k2[2*i+0] = __floats2half2_rn(kv.x, kv.y);
            k2[2*i+1] = __floats2half2_rn(kv.z, kv.w);
        }
    }
    __syncthreads();

    int n = threadIdx.x;
    if (n >= Nn) return;

    __half2 qh[8];
    float o[16];
    float l = 0.f;
    float es;
    {
        const float4* qp = (const float4*)(g_q  + base + (size_t)n*Dn);
        const float4* kp = (const float4*)(g_ks + base + (size_t)n*Dn);
        float s = 0.f;
#pragma unroll
        for (int i = 0; i < 4; ++i) {
            float4 qv = qp[i], kv = kp[i];
            qh[2*i+0] = __floats2half2_rn(qv.x, qv.y);
            qh[2*i+1] = __floats2half2_rn(qv.z, qv.w);
            s = fmaf(qv.x,kv.x, fmaf(qv.y,kv.y, fmaf(qv.z,kv.z, fmaf(qv.w,kv.w, s))));
        }
        es = 1.f/(1.f + __expf(-s*0.25f));
#pragma unroll
        for (int d = 0; d < 16; ++d) o[d] = 0.f;
    }

    const float* bT = g_biasT + (size_t)h*NNn + n;

#pragma unroll 5
    for (int m = 0; m < Nn; ++m) {
        float bval = __ldg(bT + (size_t)m*Nn);
        const uint4* kr = (const uint4*)(skh + m*16);
        uint4 A = kr[0], B = kr[1];
        __half2 a0 = __hmul2(qh[0], *(__half2*)&A.x);
        a0 = __hfma2(qh[1], *(__half2*)&A.y, a0);
        a0 = __hfma2(qh[2], *(__half2*)&A.z, a0);
        a0 = __hfma2(qh[3], *(__half2*)&A.w, a0);
        __half2 a1 = __hmul2(qh[4], *(__half2*)&B.x);
        a1 = __hfma2(qh[5], *(__half2*)&B.y, a1);
        a1 = __hfma2(qh[6], *(__half2*)&B.z, a1);
        a1 = __hfma2(qh[7], *(__half2*)&B.w, a1);
        __half2 acc = __hadd2(a0, a1);
        float s = __low2float(acc) + __high2float(acc);
        float e = fmaf(s, 0.25f, bval);
        float p = __expf(e);
        l += p;
        const float4* vr = (const float4*)(sv + m*16);
        float4 v0 = vr[0], v1 = vr[1], v2 = vr[2], v3 = vr[3];
        o[0]  = fmaf(p, v0.x, o[0]);  o[1]  = fmaf(p, v0.y, o[1]);
        o[2]  = fmaf(p, v0.z, o[2]);  o[3]  = fmaf(p, v0.w, o[3]);
        o[4]  = fmaf(p, v1.x, o[4]);  o[5]  = fmaf(p, v1.y, o[5]);
        o[6]  = fmaf(p, v1.z, o[6]);  o[7]  = fmaf(p, v1.w, o[7]);
        o[8]  = fmaf(p, v2.x, o[8]);  o[9]  = fmaf(p, v2.y, o[9]);
        o[10] = fmaf(p, v2.z, o[10]); o[11] = fmaf(p, v2.w, o[11]);
        o[12] = fmaf(p, v3.x, o[12]); o[13] = fmaf(p, v3.y, o[13]);
        o[14] = fmaf(p, v3.z, o[14]); o[15] = fmaf(p, v3.w, o[15]);
    }

    {
        float inv = 1.f/(es + l);
        const float4* vsp = (const float4*)(g_vs + base + (size_t)n*Dn);
        float* outp = g_val + ((size_t)bt*Nn + n)*Fn + h*Dn;
#pragma unroll
        for (int i = 0; i < 4; ++i) {
            float4 vs = vsp[i];
            float4 r;
            r.x = fmaf(o[i*4+0] - l*vs.x, inv, vs.x);
            r.y = fmaf(o[i*4+1] - l*vs.y, inv, vs.y);
            r.z = fmaf(o[i*4+2] - l*vs.z, inv, vs.z);
            r.w = fmaf(o[i*4+3] - l*vs.w, inv, vs.w);
            *(float4*)(outp + i*4) = r;
        }
    }
}

// ---------------- kernel 4: FFN(gelu) + residual + LayerNorm (persistent, grid 444) ----------------
__global__ __launch_bounds__(256) void ffn_kernel(
    const float* __restrict__ x,
    const float* __restrict__ Wf1, const float* __restrict__ bf1,
    const float* __restrict__ Wf2, const float* __restrict__ bf2,
    const float* __restrict__ gln, const float* __restrict__ bln,
    float* __restrict__ out)
{
    extern __shared__ float sm[];
    float* sW1 = sm;            // 4352
    float* sW2 = sm + 4352;     // 4352
    float* sb1 = sm + 8704;     // 64
    float* sb2 = sm + 8768;     // 64
    float* sg  = sm + 8832;     // 64
    float* sbl = sm + 8896;     // 64
    float* srow = sm + 8960;    // 8 * 512 = 4096

    for (int i = threadIdx.x; i < 4096; i += 256) {
        int f = i >> 6, c = i & 63;
        sW1[f*68+c] = Wf1[i];
        sW2[f*68+c] = Wf2[i];
    }
    if (threadIdx.x < 64) {
        sb1[threadIdx.x] = bf1[threadIdx.x];
        sb2[threadIdx.x] = bf2[threadIdx.x];
        sg [threadIdx.x] = gln[threadIdx.x];
        sbl[threadIdx.x] = bln[threadIdx.x];
    }
    __syncthreads();

    int warp = threadIdx.x >> 5, lane = threadIdx.x & 31;
    float* myrow = srow + warp*512;
    int f0 = lane, f1 = lane + 32;

    for (int blk = blockIdx.x; blk < 975; blk += 444) {
        int r0 = blk*64 + warp*8;
        {
            const float* vs = g_val + (size_t)r0*64;
            for (int i = lane; i < 512; i += 32) myrow[i] = vs[i];
        }
        __syncwarp();

        float t0[8], t1[8];
#pragma unroll
        for (int r = 0; r < 8; ++r) { t0[r] = sb1[f0]; t1[r] = sb1[f1]; }
#pragma unroll 4
        for (int c = 0; c < 64; c += 4) {
            float4 w0 = *(const float4*)(sW1 + f0*68 + c);
            float4 w1 = *(const float4*)(sW1 + f1*68 + c);
#pragma unroll
            for (int r = 0; r < 8; ++r) {
                float4 xv = *(const float4*)(myrow + r*64 + c);
                t0[r] = fmaf(xv.x, w0.x, t0[r]);  t1[r] = fmaf(xv.x, w1.x, t1[r]);
                t0[r] = fmaf(xv.y, w0.y, t0[r]);  t1[r] = fmaf(xv.y, w1.y, t1[r]);
                t0[r] = fmaf(xv.z, w0.z, t0[r]);  t1[r] = fmaf(xv.z, w1.z, t1[r]);
                t0[r] = fmaf(xv.w, w0.w, t0[r]);  t1[r] = fmaf(xv.w, w1.w, t1[r]);
            }
        }
        // exact gelu
#pragma unroll
        for (int r = 0; r < 8; ++r) {
            t0[r] = 0.5f*t0[r]*(1.f + erff(t0[r]*0.7071067811865476f));
            t1[r] = 0.5f*t1[r]*(1.f + erff(t1[r]*0.7071067811865476f));
        }
        __syncwarp();
#pragma unroll
        for (int r = 0; r < 8; ++r) { myrow[r*64+f0] = t0[r]; myrow[r*64+f1] = t1[r]; }
        __syncwarp();

        float h0[8], h1[8];
        const float* xr = x + (size_t)r0*64;
#pragma unroll
        for (int r = 0; r < 8; ++r) {
            h0[r] = sb2[f0] + xr[r*64+f0];
            h1[r] = sb2[f1] + xr[r*64+f1];
        }
#pragma unroll 4
        for (int c = 0; c < 64; c += 4) {
            float4 w0 = *(const float4*)(sW2 + f0*68 + c);
            float4 w1 = *(const float4*)(sW2 + f1*68 + c);
#pragma unroll
            for (int r = 0; r < 8; ++r) {
                float4 xv = *(const float4*)(myrow + r*64 + c);
                h0[r] = fmaf(xv.x, w0.x, h0[r]);  h1[r] = fmaf(xv.x, w1.x, h1[r]);
                h0[r] = fmaf(xv.y, w0.y, h0[r]);  h1[r] = fmaf(xv.y, w1.y, h1[r]);
                h0[r] = fmaf(xv.z, w0.z, h0[r]);  h1[r] = fmaf(xv.z, w1.z, h1[r]);
                h0[r] = fmaf(xv.w, w0.w, h0[r]);  h1[r] = fmaf(xv.w, w1.w, h1[r]);
            }
        }
#pragma unroll
        for (int r = 0; r < 8; ++r) {
            float s1 = h0[r] + h1[r];
            float s2 = fmaf(h0[r], h0[r], h1[r]*h1[r]);
#pragma unroll
            for (int oo = 16; oo; oo >>= 1) {
                s1 += __shfl_xor_sync(0xffffffffu, s1, oo);
                s2 += __shfl_xor_sync(0xffffffffu, s2, oo);
            }
            float mean = s1 * (1.f/64.f);
            float var  = s2 * (1.f/64.f) - mean*mean;
            float rs   = rsqrtf(var + 1e-5f);
            out[(size_t)(r0+r)*64 + f0] = fmaf(sg[f0], (h0[r]-mean)*rs, sbl[f0]);
            out[(size_t)(r0+r)*64 + f1] = fmaf(sg[f1], (h1[r]-mean)*rs, sbl[f1]);
        }
        __syncwarp();
    }
}

// ---------------- launch ----------------
extern "C" void kernel_launch(void* const* d_in, const int* in_sizes, int n_in,
                              void* d_out, int out_size)
{
    const float* x   = (const float*)d_in[0];
    const float* A   = (const float*)d_in[1];
    const float* AT  = (const float*)d_in[2];
    const float* Wq  = (const float*)d_in[3];
    const float* bq  = (const float*)d_in[4];
    const float* Wk  = (const float*)d_in[5];
    const float* bk  = (const float*)d_in[6];
    const float* Wks = (const float*)d_in[7];
    const float* bks = (const float*)d_in[8];
    const float* Wv  = (const float*)d_in[9];
    const float* bv  = (const float*)d_in[10];
    const float* Wvs = (const float*)d_in[11];
    const float* bvs = (const float*)d_in[12];
    const float* Wdi = (const float*)d_in[13];
    const float* Wdo = (const float*)d_in[14];
    const float* Wf1 = (const float*)d_in[15];
    const float* bf1 = (const float*)d_in[16];
    const float* Wf2 = (const float*)d_in[17];
    const float* bf2 = (const float*)d_in[18];
    const float* gln = (const float*)d_in[19];
    const float* bln = (const float*)d_in[20];
    float* out = (float*)d_out;

    cudaFuncSetAttribute(proj_kernel, cudaFuncAttributeMaxDynamicSharedMemorySize, 34048);
    cudaFuncSetAttribute(attn_kernel, cudaFuncAttributeMaxDynamicSharedMemorySize, 31232);
    cudaFuncSetAttribute(ffn_kernel,  cudaFuncAttributeMaxDynamicSharedMemorySize, 52224);

    dim3 bg(11, 11, 4);
    bias_kernel<<<bg, dim3(32, 8)>>>(A, AT, Wdi, Wdo);
    dim3 pg(148, 5);
    proj_kernel<<<pg, 256, 34048>>>(x, Wq, bq, Wk, bk, Wks, bks, Wv, bv, Wvs, bvs);
    dim3 ag(BTn, KHn);
    attn_kernel<<<ag, ATH, 31232>>>();
    ffn_kernel<<<444, 256, 52224>>>(x, Wf1, bf1, Wf2, bf2, gln, bln, out);
}

// round 10
// speedup vs baseline: 1.6255x; 1.1713x over previous
#include <cuda_runtime.h>
#include <cuda_fp16.h>
#include <math.h>
#include <stdint.h>

#define Bn 16
#define Tn 12
#define Nn 325
#define Fn 64
#define KHn 4
#define Dn 16
#define KDn 3
#define BTn (Bn*Tn)            // 192
#define BTNn (BTn*Nn)          // 62400
#define NNn (Nn*Nn)            // 105625
#define QPAD 336               // padded node count (21*16)
#define BPAD 336
#define KSTRIDE 24             // halves per K row in smem (conflict-free quad pattern)
#define VSTRIDE 344            // halves per Vt row in smem

// ---------------- scratch (device globals; zero-initialized, no allocation) ----------------
__device__ float g_q [KHn*BTNn*Dn + 256];
__device__ float g_k [KHn*BTNn*Dn + 256];
__device__ float g_ks[KHn*BTNn*Dn + 256];
__device__ float g_v [KHn*BTNn*Dn + 256];
__device__ float g_vs[KHn*BTNn*Dn + 256];
__device__ float g_bias2[KHn*BPAD*BPAD];     // [h][q][k], padded; pad region stays zero
__device__ float g_val[BTNn*Fn];

// ---------------- mma helper: m16n8k16 row.col f32 += f16*f16 ----------------
__device__ __forceinline__ void mma16816(float d[4],
    uint32_t a0, uint32_t a1, uint32_t a2, uint32_t a3,
    uint32_t b0, uint32_t b1)
{
    asm volatile(
        "mma.sync.aligned.m16n8k16.row.col.f32.f16.f16.f32 "
        "{%0,%1,%2,%3}, {%4,%5,%6,%7}, {%8,%9}, {%0,%1,%2,%3};"
        : "+f"(d[0]), "+f"(d[1]), "+f"(d[2]), "+f"(d[3])
        : "r"(a0), "r"(a1), "r"(a2), "r"(a3), "r"(b0), "r"(b1));
}
__device__ __forceinline__ uint32_t f2h2(float x, float y) {
    __half2 h = __floats2half2_rn(x, y);
    return *(uint32_t*)&h;
}

// ---------------- kernel 1: graph-diffusion bias into padded [h][q][k] ----------------
__global__ void bias_kernel(const float* __restrict__ A, const float* __restrict__ AT,
                            const float* __restrict__ Wdi, const float* __restrict__ Wdo)
{
    int idx = blockIdx.x*blockDim.x + threadIdx.x;
    if (idx >= KHn*NNn) return;
    int h = idx / NNn, nm = idx - h*NNn;
    int n = nm / Nn, m = nm - n*Nn;
    float s = 0.f;
    if (h < 2) {
#pragma unroll
        for (int j = 0; j < KDn; ++j) s = fmaf(Wdi[(h*KDn+j)*NNn+nm], A[j*NNn+nm], s);
    } else {
#pragma unroll
        for (int j = 0; j < KDn; ++j) s = fmaf(Wdo[((h-2)*KDn+j)*NNn+nm], AT[j*NNn+nm], s);
    }
    g_bias2[((size_t)h*BPAD + n)*BPAD + m] = s;
}

// ---------------- kernel 2: projection (persistent; grid (148,5)) ----------------
__global__ __launch_bounds__(256) void proj_kernel(
    const float* __restrict__ x,
    const float* __restrict__ Wq,  const float* __restrict__ bq,
    const float* __restrict__ Wk,  const float* __restrict__ bk,
    const float* __restrict__ Wks, const float* __restrict__ bks,
    const float* __restrict__ Wv,  const float* __restrict__ bv,
    const float* __restrict__ Wvs, const float* __restrict__ bvs)
{
    extern __shared__ float sm[];
    float* sW   = sm;                 // 64*68 = 4352
    float* sb   = sm + 4352;          // 64
    float* srow = sm + 4416;          // 8 warps * 512 = 4096

    int p = blockIdx.y;
    const float* W = (p==0)?Wq:(p==1)?Wk:(p==2)?Wks:(p==3)?Wv:Wvs;
    const float* bb = (p==0)?bq:(p==1)?bk:(p==2)?bks:(p==3)?bv:bvs;
    float* o = (p==0)?g_q:(p==1)?g_k:(p==2)?g_ks:(p==3)?g_v:g_vs;

    for (int i = threadIdx.x; i < 4096; i += 256) {
        int f = i >> 6, c = i & 63;
        sW[f*68 + c] = W[i];
    }
    if (threadIdx.x < 64) sb[threadIdx.x] = bb[threadIdx.x];
    __syncthreads();

    int warp = threadIdx.x >> 5, lane = threadIdx.x & 31;
    float* myrow = srow + warp*512;
    int f0 = lane, f1 = lane + 32;
    int h0 = f0 >> 4, d0 = f0 & 15;
    int h1 = f1 >> 4, d1 = f1 & 15;
    float bb0 = sb[f0], bb1 = sb[f1];

    for (int blk = blockIdx.x; blk < 975; blk += 148) {
        int r0 = blk * 64 + warp * 8;
        {
            const float* xs = x + (size_t)r0*64;
            for (int i = lane; i < 512; i += 32) myrow[i] = xs[i];
        }
        __syncwarp();

        float acc0[8], acc1[8];
#pragma unroll
        for (int r = 0; r < 8; ++r) { acc0[r] = bb0; acc1[r] = bb1; }
#pragma unroll 4
        for (int c = 0; c < 64; c += 4) {
            float4 w0 = *(const float4*)(sW + f0*68 + c);
            float4 w1 = *(const float4*)(sW + f1*68 + c);
#pragma unroll
            for (int r = 0; r < 8; ++r) {
                float4 xv = *(const float4*)(myrow + r*64 + c);
                acc0[r] = fmaf(xv.x, w0.x, acc0[r]);
                acc1[r] = fmaf(xv.x, w1.x, acc1[r]);
                acc0[r] = fmaf(xv.y, w0.y, acc0[r]);
                acc1[r] = fmaf(xv.y, w1.y, acc1[r]);
                acc0[r] = fmaf(xv.z, w0.z, acc0[r]);
                acc1[r] = fmaf(xv.z, w1.z, acc1[r]);
                acc0[r] = fmaf(xv.w, w0.w, acc0[r]);
                acc1[r] = fmaf(xv.w, w1.w, acc1[r]);
            }
        }
#pragma unroll
        for (int r = 0; r < 8; ++r) {
            size_t rr = (size_t)(r0 + r);
            o[((size_t)h0*BTNn + rr)*Dn + d0] = acc0[r];
            o[((size_t)h1*BTNn + rr)*Dn + d1] = acc1[r];
        }
        __syncwarp();
    }
}

// ---------------- kernel 3: attention via tensor-core mma (fp16 in, fp32 acc) ----------------
#define ATH 352
__global__ __launch_bounds__(ATH, 2) void attn_kernel()
{
    extern __shared__ char smem_raw[];
    __half* sKs = (__half*)smem_raw;                  // [336][24] halves = 16128 B
    __half* sVt = (__half*)(smem_raw + 16128);        // [16][344] halves = 11008 B

    int bt = blockIdx.x, h = blockIdx.y;
    size_t base = ((size_t)h*BTNn + (size_t)bt*Nn)*Dn;
    const float* gk  = g_k  + base;
    const float* gv  = g_v  + base;
    const float* gq  = g_q  + base;
    const float* gks = g_ks + base;
    const float* gvs = g_vs + base;
    int tid = threadIdx.x;

    // stage K (row-major, stride 24) and V (transposed, stride 344) as fp16; zero-pad keys>=325
    for (int i = tid; i < QPAD*Dn; i += ATH) {
        int key = i >> 4, d = i & 15;
        __half kh = __float2half(0.f), vh = __float2half(0.f);
        if (key < Nn) {
            kh = __float2half(gk[key*16 + d]);
            vh = __float2half(gv[key*16 + d]);
        }
        sKs[key*KSTRIDE + d] = kh;
        sVt[d*VSTRIDE + key] = vh;
    }
    __syncthreads();

    int warp = tid >> 5, lane = tid & 31;
    int gid = lane >> 2, tig = lane & 3;
    const float* bias = g_bias2 + (size_t)h*BPAD*BPAD;

    for (int rb = warp; rb <= 20; rb += 11) {
        int q0 = rb*16;
        int qA = q0 + gid, qB = q0 + gid + 8;
        bool vA = qA < Nn, vB = qB < Nn;

        // Q fragment (A of score mma): rows qA/qB, cols 2tig(+1), +8
        uint32_t qa0 = 0, qa1 = 0, qa2 = 0, qa3 = 0;
        if (vA) {
            float2 f0 = *(const float2*)(gq + qA*16 + 2*tig);
            float2 f2 = *(const float2*)(gq + qA*16 + 2*tig + 8);
            qa0 = f2h2(f0.x, f0.y);  qa2 = f2h2(f2.x, f2.y);
        }
        if (vB) {
            float2 f1 = *(const float2*)(gq + qB*16 + 2*tig);
            float2 f3 = *(const float2*)(gq + qB*16 + 2*tig + 8);
            qa1 = f2h2(f1.x, f1.y);  qa3 = f2h2(f3.x, f3.y);
        }

        // es = sigmoid(q . ks * 0.25) per query; lanes 0..15 compute one query each
        float esv = 1.f;
        {
            int q = q0 + lane;
            if (lane < 16 && q < Nn) {
                float s = 0.f;
#pragma unroll
                for (int d = 0; d < 16; ++d) s = fmaf(gq[q*16+d], gks[q*16+d], s);
                esv = 1.f/(1.f + __expf(-s*0.25f));
            }
        }
        float esA = __shfl_sync(0xffffffffu, esv, gid);
        float esB = __shfl_sync(0xffffffffu, esv, gid + 8);

        float o0[4] = {0.f,0.f,0.f,0.f};   // dims 0-7
        float o1[4] = {0.f,0.f,0.f,0.f};   // dims 8-15
        float LA = 0.f, LB = 0.f;

#pragma unroll 1
        for (int kb = 0; kb < 21; ++kb) {
            int k0 = kb*16;
            // scores: S[16q x 16k] via two n8 MMAs; B frag = K rows (keys), pairs over dim
            uint32_t b0a = *(const uint32_t*)(sKs + (k0+gid)*KSTRIDE + 2*tig);
            uint32_t b1a = *(const uint32_t*)(sKs + (k0+gid)*KSTRIDE + 2*tig + 8);
            uint32_t b0b = *(const uint32_t*)(sKs + (k0+8+gid)*KSTRIDE + 2*tig);
            uint32_t b1b = *(const uint32_t*)(sKs + (k0+8+gid)*KSTRIDE + 2*tig + 8);
            float c0[4] = {0.f,0.f,0.f,0.f};
            float c1[4] = {0.f,0.f,0.f,0.f};
            mma16816(c0, qa0, qa1, qa2, qa3, b0a, b1a);
            mma16816(c1, qa0, qa1, qa2, qa3, b0b, b1b);

            // bias + exp + row-sum + pack into A frag of P@V
            uint32_t pa0, pa1, pa2, pa3;
            {
                int kc = k0 + 2*tig;
                float2 bA2 = *(const float2*)(bias + (size_t)qA*BPAD + kc);
                float2 bB2 = *(const float2*)(bias + (size_t)qB*BPAD + kc);
                bool u0 = kc < Nn, u1 = (kc+1) < Nn;
                float p00 = u0 ? __expf(fmaf(c0[0], 0.25f, bA2.x)) : 0.f;
                float p01 = u1 ? __expf(fmaf(c0[1], 0.25f, bA2.y)) : 0.f;
                float p10 = u0 ? __expf(fmaf(c0[2], 0.25f, bB2.x)) : 0.f;
                float p11 = u1 ? __expf(fmaf(c0[3], 0.25f, bB2.y)) : 0.f;
                LA += p00 + p01;  LB += p10 + p11;
                pa0 = f2h2(p00, p01);  pa1 = f2h2(p10, p11);
            }
            {
                int kc = k0 + 8 + 2*tig;
                float2 bA2 = *(const float2*)(bias + (size_t)qA*BPAD + kc);
                float2 bB2 = *(const float2*)(bias + (size_t)qB*BPAD + kc);
                bool u0 = kc < Nn, u1 = (kc+1) < Nn;
                float p00 = u0 ? __expf(fmaf(c1[0], 0.25f, bA2.x)) : 0.f;
                float p01 = u1 ? __expf(fmaf(c1[1], 0.25f, bA2.y)) : 0.f;
                float p10 = u0 ? __expf(fmaf(c1[2], 0.25f, bB2.x)) : 0.f;
                float p11 = u1 ? __expf(fmaf(c1[3], 0.25f, bB2.y)) : 0.f;
                LA += p00 + p01;  LB += p10 + p11;
                pa2 = f2h2(p00, p01);  pa3 = f2h2(p10, p11);
            }

            // O += P @ V : B frag from Vt, pairs over key
            uint32_t vb0 = *(const uint32_t*)(sVt + gid*VSTRIDE + k0 + 2*tig);
            uint32_t vb1 = *(const uint32_t*)(sVt + gid*VSTRIDE + k0 + 2*tig + 8);
            mma16816(o0, pa0, pa1, pa2, pa3, vb0, vb1);
            uint32_t vb2 = *(const uint32_t*)(sVt + (8+gid)*VSTRIDE + k0 + 2*tig);
            uint32_t vb3 = *(const uint32_t*)(sVt + (8+gid)*VSTRIDE + k0 + 2*tig + 8);
            mma16816(o1, pa0, pa1, pa2, pa3, vb2, vb3);
        }

        // row sums across the 4-lane quad
        LA += __shfl_xor_sync(0xffffffffu, LA, 1);
        LA += __shfl_xor_sync(0xffffffffu, LA, 2);
        LB += __shfl_xor_sync(0xffffffffu, LB, 1);
        LB += __shfl_xor_sync(0xffffffffu, LB, 2);

        if (vA) {
            float inv = 1.f/(esA + LA);
            float* op = g_val + ((size_t)bt*Nn + qA)*Fn + h*16;
            float2 vs0 = *(const float2*)(gvs + qA*16 + 2*tig);
            float2 vs1 = *(const float2*)(gvs + qA*16 + 8 + 2*tig);
            float2 r0, r1;
            r0.x = fmaf(o0[0] - LA*vs0.x, inv, vs0.x);
            r0.y = fmaf(o0[1] - LA*vs0.y, inv, vs0.y);
            r1.x = fmaf(o1[0] - LA*vs1.x, inv, vs1.x);
            r1.y = fmaf(o1[1] - LA*vs1.y, inv, vs1.y);
            *(float2*)(op + 2*tig) = r0;
            *(float2*)(op + 8 + 2*tig) = r1;
        }
        if (vB) {
            float inv = 1.f/(esB + LB);
            float* op = g_val + ((size_t)bt*Nn + qB)*Fn + h*16;
            float2 vs0 = *(const float2*)(gvs + qB*16 + 2*tig);
            float2 vs1 = *(const float2*)(gvs + qB*16 + 8 + 2*tig);
            float2 r0, r1;
            r0.x = fmaf(o0[2] - LB*vs0.x, inv, vs0.x);
            r0.y = fmaf(o0[3] - LB*vs0.y, inv, vs0.y);
            r1.x = fmaf(o1[2] - LB*vs1.x, inv, vs1.x);
            r1.y = fmaf(o1[3] - LB*vs1.y, inv, vs1.y);
            *(float2*)(op + 2*tig) = r0;
            *(float2*)(op + 8 + 2*tig) = r1;
        }
    }
}

// ---------------- kernel 4: FFN(gelu) + residual + LayerNorm (persistent, grid 444) ----------------
__global__ __launch_bounds__(256) void ffn_kernel(
    const float* __restrict__ x,
    const float* __restrict__ Wf1, const float* __restrict__ bf1,
    const float* __restrict__ Wf2, const float* __restrict__ bf2,
    const float* __restrict__ gln, const float* __restrict__ bln,
    float* __restrict__ out)
{
    extern __shared__ float sm[];
    float* sW1 = sm;            // 4352
    float* sW2 = sm + 4352;     // 4352
    float* sb1 = sm + 8704;     // 64
    float* sb2 = sm + 8768;     // 64
    float* sg  = sm + 8832;     // 64
    float* sbl = sm + 8896;     // 64
    float* srow = sm + 8960;    // 8 * 512 = 4096

    for (int i = threadIdx.x; i < 4096; i += 256) {
        int f = i >> 6, c = i & 63;
        sW1[f*68+c] = Wf1[i];
        sW2[f*68+c] = Wf2[i];
    }
    if (threadIdx.x < 64) {
        sb1[threadIdx.x] = bf1[threadIdx.x];
        sb2[threadIdx.x] = bf2[threadIdx.x];
        sg [threadIdx.x] = gln[threadIdx.x];
        sbl[threadIdx.x] = bln[threadIdx.x];
    }
    __syncthreads();

    int warp = threadIdx.x >> 5, lane = threadIdx.x & 31;
    float* myrow = srow + warp*512;
    int f0 = lane, f1 = lane + 32;

    for (int blk = blockIdx.x; blk < 975; blk += 444) {
        int r0 = blk*64 + warp*8;
        {
            const float* vs = g_val + (size_t)r0*64;
            for (int i = lane; i < 512; i += 32) myrow[i] = vs[i];
        }
        __syncwarp();

        float t0[8], t1[8];
#pragma unroll
        for (int r = 0; r < 8; ++r) { t0[r] = sb1[f0]; t1[r] = sb1[f1]; }
#pragma unroll 4
        for (int c = 0; c < 64; c += 4) {
            float4 w0 = *(const float4*)(sW1 + f0*68 + c);
            float4 w1 = *(const float4*)(sW1 + f1*68 + c);
#pragma unroll
            for (int r = 0; r < 8; ++r) {
                float4 xv = *(const float4*)(myrow + r*64 + c);
                t0[r] = fmaf(xv.x, w0.x, t0[r]);  t1[r] = fmaf(xv.x, w1.x, t1[r]);
                t0[r] = fmaf(xv.y, w0.y, t0[r]);  t1[r] = fmaf(xv.y, w1.y, t1[r]);
                t0[r] = fmaf(xv.z, w0.z, t0[r]);  t1[r] = fmaf(xv.z, w1.z, t1[r]);
                t0[r] = fmaf(xv.w, w0.w, t0[r]);  t1[r] = fmaf(xv.w, w1.w, t1[r]);
            }
        }
#pragma unroll
        for (int r = 0; r < 8; ++r) {
            t0[r] = 0.5f*t0[r]*(1.f + erff(t0[r]*0.7071067811865476f));
            t1[r] = 0.5f*t1[r]*(1.f + erff(t1[r]*0.7071067811865476f));
        }
        __syncwarp();
#pragma unroll
        for (int r = 0; r < 8; ++r) { myrow[r*64+f0] = t0[r]; myrow[r*64+f1] = t1[r]; }
        __syncwarp();

        float h0[8], h1[8];
        const float* xr = x + (size_t)r0*64;
#pragma unroll
        for (int r = 0; r < 8; ++r) {
            h0[r] = sb2[f0] + xr[r*64+f0];
            h1[r] = sb2[f1] + xr[r*64+f1];
        }
#pragma unroll 4
        for (int c = 0; c < 64; c += 4) {
            float4 w0 = *(const float4*)(sW2 + f0*68 + c);
            float4 w1 = *(const float4*)(sW2 + f1*68 + c);
#pragma unroll
            for (int r = 0; r < 8; ++r) {
                float4 xv = *(const float4*)(myrow + r*64 + c);
                h0[r] = fmaf(xv.x, w0.x, h0[r]);  h1[r] = fmaf(xv.x, w1.x, h1[r]);
                h0[r] = fmaf(xv.y, w0.y, h0[r]);  h1[r] = fmaf(xv.y, w1.y, h1[r]);
                h0[r] = fmaf(xv.z, w0.z, h0[r]);  h1[r] = fmaf(xv.z, w1.z, h1[r]);
                h0[r] = fmaf(xv.w, w0.w, h0[r]);  h1[r] = fmaf(xv.w, w1.w, h1[r]);
            }
        }
#pragma unroll
        for (int r = 0; r < 8; ++r) {
            float s1 = h0[r] + h1[r];
            float s2 = fmaf(h0[r], h0[r], h1[r]*h1[r]);
#pragma unroll
            for (int oo = 16; oo; oo >>= 1) {
                s1 += __shfl_xor_sync(0xffffffffu, s1, oo);
                s2 += __shfl_xor_sync(0xffffffffu, s2, oo);
            }
            float mean = s1 * (1.f/64.f);
            float var  = s2 * (1.f/64.f) - mean*mean;
            float rs   = rsqrtf(var + 1e-5f);
            out[(size_t)(r0+r)*64 + f0] = fmaf(sg[f0], (h0[r]-mean)*rs, sbl[f0]);
            out[(size_t)(r0+r)*64 + f1] = fmaf(sg[f1], (h1[r]-mean)*rs, sbl[f1]);
        }
        __syncwarp();
    }
}

// ---------------- launch ----------------
extern "C" void kernel_launch(void* const* d_in, const int* in_sizes, int n_in,
                              void* d_out, int out_size)
{
    const float* x   = (const float*)d_in[0];
    const float* A   = (const float*)d_in[1];
    const float* AT  = (const float*)d_in[2];
    const float* Wq  = (const float*)d_in[3];
    const float* bq  = (const float*)d_in[4];
    const float* Wk  = (const float*)d_in[5];
    const float* bk  = (const float*)d_in[6];
    const float* Wks = (const float*)d_in[7];
    const float* bks = (const float*)d_in[8];
    const float* Wv  = (const float*)d_in[9];
    const float* bv  = (const float*)d_in[10];
    const float* Wvs = (const float*)d_in[11];
    const float* bvs = (const float*)d_in[12];
    const float* Wdi = (const float*)d_in[13];
    const float* Wdo = (const float*)d_in[14];
    const float* Wf1 = (const float*)d_in[15];
    const float* bf1 = (const float*)d_in[16];
    const float* Wf2 = (const float*)d_in[17];
    const float* bf2 = (const float*)d_in[18];
    const float* gln = (const float*)d_in[19];
    const float* bln = (const float*)d_in[20];
    float* out = (float*)d_out;

    cudaFuncSetAttribute(proj_kernel, cudaFuncAttributeMaxDynamicSharedMemorySize, 34048);
    cudaFuncSetAttribute(attn_kernel, cudaFuncAttributeMaxDynamicSharedMemorySize, 27136);
    cudaFuncSetAttribute(ffn_kernel,  cudaFuncAttributeMaxDynamicSharedMemorySize, 52224);

    bias_kernel<<<(KHn*NNn + 255)/256, 256>>>(A, AT, Wdi, Wdo);
    dim3 pg(148, 5);
    proj_kernel<<<pg, 256, 34048>>>(x, Wq, bq, Wk, bk, Wks, bks, Wv, bv, Wvs, bvs);
    dim3 ag(BTn, KHn);
    attn_kernel<<<ag, ATH, 27136>>>();
    ffn_kernel<<<444, 256, 52224>>>(x, Wf1, bf1, Wf2, bf2, gln, bln, out);
}

// round 11
// speedup vs baseline: 2.0985x; 1.2909x over previous
#include <cuda_runtime.h>
#include <cuda_fp16.h>
#include <math.h>
#include <stdint.h>

#define Bn 16
#define Tn 12
#define Nn 325
#define Fn 64
#define KHn 4
#define Dn 16
#define KDn 3
#define BTn (Bn*Tn)            // 192
#define BTNn (BTn*Nn)          // 62400
#define NNn (Nn*Nn)            // 105625
#define QPAD 336               // padded node count (21*16)
#define BPAD 336
#define KSTRIDE 24             // halves per K row in smem
#define VSTRIDE 344            // halves per Vt row in smem
#define WSTRIDE 72             // halves per weight row in smem (bank-mult 4, conflict-free)

// ---------------- scratch (device globals; zero-initialized, no allocation) ----------------
__device__ float  g_q [KHn*BTNn*Dn + 256];
__device__ float  g_k [KHn*BTNn*Dn + 256];
__device__ float  g_ks[KHn*BTNn*Dn + 256];
__device__ float  g_v [KHn*BTNn*Dn + 256];
__device__ float  g_vs[KHn*BTNn*Dn + 256];
__device__ __half g_bias2[KHn*BPAD*BPAD];    // [h][q][k] fp16, pad region stays zero
__device__ float  g_val[BTNn*Fn];

// ---------------- mma helper: m16n8k16 row.col f32 += f16*f16 ----------------
__device__ __forceinline__ void mma16816(float d[4],
    uint32_t a0, uint32_t a1, uint32_t a2, uint32_t a3,
    uint32_t b0, uint32_t b1)
{
    asm volatile(
        "mma.sync.aligned.m16n8k16.row.col.f32.f16.f16.f32 "
        "{%0,%1,%2,%3}, {%4,%5,%6,%7}, {%8,%9}, {%0,%1,%2,%3};"
        : "+f"(d[0]), "+f"(d[1]), "+f"(d[2]), "+f"(d[3])
        : "r"(a0), "r"(a1), "r"(a2), "r"(a3), "r"(b0), "r"(b1));
}
__device__ __forceinline__ uint32_t f2h2(float x, float y) {
    __half2 h = __floats2half2_rn(x, y);
    return *(uint32_t*)&h;
}

// ---------------- kernel 1: graph-diffusion bias -> fp16 padded [h][q][k] ----------------
__global__ void bias_kernel(const float* __restrict__ A, const float* __restrict__ AT,
                            const float* __restrict__ Wdi, const float* __restrict__ Wdo)
{
    int idx = blockIdx.x*blockDim.x + threadIdx.x;
    if (idx >= KHn*NNn) return;
    int h = idx / NNn, nm = idx - h*NNn;
    int n = nm / Nn, m = nm - n*Nn;
    float s = 0.f;
    if (h < 2) {
#pragma unroll
        for (int j = 0; j < KDn; ++j) s = fmaf(Wdi[(h*KDn+j)*NNn+nm], A[j*NNn+nm], s);
    } else {
#pragma unroll
        for (int j = 0; j < KDn; ++j) s = fmaf(Wdo[((h-2)*KDn+j)*NNn+nm], AT[j*NNn+nm], s);
    }
    g_bias2[((size_t)h*BPAD + n)*BPAD + m] = __float2half(s);
}

// ---------------- kernel 2: fused 5-way projection via tensor-core MMA ----------------
// block 256 = 8 warps; warp tile = 16 rows x all 320 outputs. Weights fp16 in smem
// [f][WSTRIDE]; A-frags converted from x on the fly. grid 244 = one wave @ 4/SM.
__global__ __launch_bounds__(256) void proj_kernel(
    const float* __restrict__ x,
    const float* __restrict__ Wq,  const float* __restrict__ bq,
    const float* __restrict__ Wk,  const float* __restrict__ bk,
    const float* __restrict__ Wks, const float* __restrict__ bks,
    const float* __restrict__ Wv,  const float* __restrict__ bv,
    const float* __restrict__ Wvs, const float* __restrict__ bvs)
{
    extern __shared__ char smraw[];
    __half* sW = (__half*)smraw;                  // 5 * 64*72 halves = 46080 B
    float* sbias = (float*)(smraw + 46080);       // 5 * 64 floats = 1280 B

    const float* Ws[5] = {Wq, Wk, Wks, Wv, Wvs};
    const float* bs[5] = {bq, bk, bks, bv, bvs};
    for (int i = threadIdx.x; i < 5*4096; i += 256) {
        int p = i >> 12, idx = i & 4095;
        int f = idx >> 6, c = idx & 63;
        sW[p*4608 + f*WSTRIDE + c] = __float2half(Ws[p][f*64 + c]);
    }
    for (int i = threadIdx.x; i < 5*64; i += 256)
        sbias[i] = bs[i >> 6][i & 63];
    __syncthreads();

    int warp = threadIdx.x >> 5, lane = threadIdx.x & 31;
    int gid = lane >> 2, tig = lane & 3;
    float* outp[5] = {g_q, g_k, g_ks, g_v, g_vs};

    int wglobal = blockIdx.x*8 + warp;
    for (int tile = wglobal; tile < 3900; tile += 244*8) {
        int r0 = tile*16;
        int rA = r0 + gid, rB = r0 + gid + 8;

        // A fragments: 4 k-steps of 16 input dims
        uint32_t a[4][4];
#pragma unroll
        for (int j = 0; j < 4; ++j) {
            float2 fA0 = *(const float2*)(x + (size_t)rA*64 + 16*j + 2*tig);
            float2 fB0 = *(const float2*)(x + (size_t)rB*64 + 16*j + 2*tig);
            float2 fA8 = *(const float2*)(x + (size_t)rA*64 + 16*j + 2*tig + 8);
            float2 fB8 = *(const float2*)(x + (size_t)rB*64 + 16*j + 2*tig + 8);
            a[j][0] = f2h2(fA0.x, fA0.y);
            a[j][1] = f2h2(fB0.x, fB0.y);
            a[j][2] = f2h2(fA8.x, fA8.y);
            a[j][3] = f2h2(fB8.x, fB8.y);
        }

#pragma unroll 1
        for (int p = 0; p < 5; ++p) {
            const __half* wp = sW + p*4608;
            float* o = outp[p];
#pragma unroll
            for (int nch = 0; nch < 8; ++nch) {
                float d[4] = {0.f, 0.f, 0.f, 0.f};
#pragma unroll
                for (int j = 0; j < 4; ++j) {
                    uint32_t b0 = *(const uint32_t*)(wp + (nch*8+gid)*WSTRIDE + 16*j + 2*tig);
                    uint32_t b1 = *(const uint32_t*)(wp + (nch*8+gid)*WSTRIDE + 16*j + 2*tig + 8);
                    mma16816(d, a[j][0], a[j][1], a[j][2], a[j][3], b0, b1);
                }
                int f = nch*8 + 2*tig;            // output feature (even)
                int hh = f >> 4, dd = f & 15;
                float bb0 = sbias[p*64 + f], bb1 = sbias[p*64 + f + 1];
                float2 rA2, rB2;
                rA2.x = d[0] + bb0;  rA2.y = d[1] + bb1;
                rB2.x = d[2] + bb0;  rB2.y = d[3] + bb1;
                *(float2*)(o + ((size_t)hh*BTNn + rA)*Dn + dd) = rA2;
                *(float2*)(o + ((size_t)hh*BTNn + rB)*Dn + dd) = rB2;
            }
        }
    }
}

// ---------------- kernel 3: attention via tensor-core mma (fp16 in, fp32 acc) ----------------
#define ATH 352
__global__ __launch_bounds__(ATH, 2) void attn_kernel()
{
    extern __shared__ char smem_raw[];
    __half* sKs = (__half*)smem_raw;                  // [336][24] halves = 16128 B
    __half* sVt = (__half*)(smem_raw + 16128);        // [16][344] halves = 11008 B

    int bt = blockIdx.x, h = blockIdx.y;
    size_t base = ((size_t)h*BTNn + (size_t)bt*Nn)*Dn;
    const float* gk  = g_k  + base;
    const float* gv  = g_v  + base;
    const float* gq  = g_q  + base;
    const float* gks = g_ks + base;
    const float* gvs = g_vs + base;
    int tid = threadIdx.x;

    for (int i = tid; i < QPAD*Dn; i += ATH) {
        int key = i >> 4, d = i & 15;
        __half kh = __float2half(0.f), vh = __float2half(0.f);
        if (key < Nn) {
            kh = __float2half(gk[key*16 + d]);
            vh = __float2half(gv[key*16 + d]);
        }
        sKs[key*KSTRIDE + d] = kh;
        sVt[d*VSTRIDE + key] = vh;
    }
    __syncthreads();

    int warp = tid >> 5, lane = tid & 31;
    int gid = lane >> 2, tig = lane & 3;
    const __half* bias = g_bias2 + (size_t)h*BPAD*BPAD;

    for (int rb = warp; rb <= 20; rb += 11) {
        int q0 = rb*16;
        int qA = q0 + gid, qB = q0 + gid + 8;
        bool vA = qA < Nn, vB = qB < Nn;

        uint32_t qa0 = 0, qa1 = 0, qa2 = 0, qa3 = 0;
        if (vA) {
            float2 f0 = *(const float2*)(gq + qA*16 + 2*tig);
            float2 f2 = *(const float2*)(gq + qA*16 + 2*tig + 8);
            qa0 = f2h2(f0.x, f0.y);  qa2 = f2h2(f2.x, f2.y);
        }
        if (vB) {
            float2 f1 = *(const float2*)(gq + qB*16 + 2*tig);
            float2 f3 = *(const float2*)(gq + qB*16 + 2*tig + 8);
            qa1 = f2h2(f1.x, f1.y);  qa3 = f2h2(f3.x, f3.y);
        }

        float esv = 1.f;
        {
            int q = q0 + lane;
            if (lane < 16 && q < Nn) {
                float s = 0.f;
#pragma unroll
                for (int d = 0; d < 16; ++d) s = fmaf(gq[q*16+d], gks[q*16+d], s);
                esv = 1.f/(1.f + __expf(-s*0.25f));
            }
        }
        float esA = __shfl_sync(0xffffffffu, esv, gid);
        float esB = __shfl_sync(0xffffffffu, esv, gid + 8);

        float o0[4] = {0.f,0.f,0.f,0.f};
        float o1[4] = {0.f,0.f,0.f,0.f};
        float LA = 0.f, LB = 0.f;

#pragma unroll 1
        for (int kb = 0; kb < 21; ++kb) {
            int k0 = kb*16;
            uint32_t b0a = *(const uint32_t*)(sKs + (k0+gid)*KSTRIDE + 2*tig);
            uint32_t b1a = *(const uint32_t*)(sKs + (k0+gid)*KSTRIDE + 2*tig + 8);
            uint32_t b0b = *(const uint32_t*)(sKs + (k0+8+gid)*KSTRIDE + 2*tig);
            uint32_t b1b = *(const uint32_t*)(sKs + (k0+8+gid)*KSTRIDE + 2*tig + 8);
            float c0[4] = {0.f,0.f,0.f,0.f};
            float c1[4] = {0.f,0.f,0.f,0.f};
            mma16816(c0, qa0, qa1, qa2, qa3, b0a, b1a);
            mma16816(c1, qa0, qa1, qa2, qa3, b0b, b1b);

            uint32_t pa0, pa1, pa2, pa3;
            {
                int kc = k0 + 2*tig;
                float2 bA2 = __half22float2(*(const __half2*)(bias + (size_t)qA*BPAD + kc));
                float2 bB2 = __half22float2(*(const __half2*)(bias + (size_t)qB*BPAD + kc));
                bool u0 = kc < Nn, u1 = (kc+1) < Nn;
                float p00 = u0 ? __expf(fmaf(c0[0], 0.25f, bA2.x)) : 0.f;
                float p01 = u1 ? __expf(fmaf(c0[1], 0.25f, bA2.y)) : 0.f;
                float p10 = u0 ? __expf(fmaf(c0[2], 0.25f, bB2.x)) : 0.f;
                float p11 = u1 ? __expf(fmaf(c0[3], 0.25f, bB2.y)) : 0.f;
                LA += p00 + p01;  LB += p10 + p11;
                pa0 = f2h2(p00, p01);  pa1 = f2h2(p10, p11);
            }
            {
                int kc = k0 + 8 + 2*tig;
                float2 bA2 = __half22float2(*(const __half2*)(bias + (size_t)qA*BPAD + kc));
                float2 bB2 = __half22float2(*(const __half2*)(bias + (size_t)qB*BPAD + kc));
                bool u0 = kc < Nn, u1 = (kc+1) < Nn;
                float p00 = u0 ? __expf(fmaf(c1[0], 0.25f, bA2.x)) : 0.f;
                float p01 = u1 ? __expf(fmaf(c1[1], 0.25f, bA2.y)) : 0.f;
                float p10 = u0 ? __expf(fmaf(c1[2], 0.25f, bB2.x)) : 0.f;
                float p11 = u1 ? __expf(fmaf(c1[3], 0.25f, bB2.y)) : 0.f;
                LA += p00 + p01;  LB += p10 + p11;
                pa2 = f2h2(p00, p01);  pa3 = f2h2(p10, p11);
            }

            uint32_t vb0 = *(const uint32_t*)(sVt + gid*VSTRIDE + k0 + 2*tig);
            uint32_t vb1 = *(const uint32_t*)(sVt + gid*VSTRIDE + k0 + 2*tig + 8);
            mma16816(o0, pa0, pa1, pa2, pa3, vb0, vb1);
            uint32_t vb2 = *(const uint32_t*)(sVt + (8+gid)*VSTRIDE + k0 + 2*tig);
            uint32_t vb3 = *(const uint32_t*)(sVt + (8+gid)*VSTRIDE + k0 + 2*tig + 8);
            mma16816(o1, pa0, pa1, pa2, pa3, vb2, vb3);
        }

        LA += __shfl_xor_sync(0xffffffffu, LA, 1);
        LA += __shfl_xor_sync(0xffffffffu, LA, 2);
        LB += __shfl_xor_sync(0xffffffffu, LB, 1);
        LB += __shfl_xor_sync(0xffffffffu, LB, 2);

        if (vA) {
            float inv = 1.f/(esA + LA);
            float* op = g_val + ((size_t)bt*Nn + qA)*Fn + h*16;
            float2 vs0 = *(const float2*)(gvs + qA*16 + 2*tig);
            float2 vs1 = *(const float2*)(gvs + qA*16 + 8 + 2*tig);
            float2 r0, r1;
            r0.x = fmaf(o0[0] - LA*vs0.x, inv, vs0.x);
            r0.y = fmaf(o0[1] - LA*vs0.y, inv, vs0.y);
            r1.x = fmaf(o1[0] - LA*vs1.x, inv, vs1.x);
            r1.y = fmaf(o1[1] - LA*vs1.y, inv, vs1.y);
            *(float2*)(op + 2*tig) = r0;
            *(float2*)(op + 8 + 2*tig) = r1;
        }
        if (vB) {
            float inv = 1.f/(esB + LB);
            float* op = g_val + ((size_t)bt*Nn + qB)*Fn + h*16;
            float2 vs0 = *(const float2*)(gvs + qB*16 + 2*tig);
            float2 vs1 = *(const float2*)(gvs + qB*16 + 8 + 2*tig);
            float2 r0, r1;
            r0.x = fmaf(o0[2] - LB*vs0.x, inv, vs0.x);
            r0.y = fmaf(o0[3] - LB*vs0.y, inv, vs0.y);
            r1.x = fmaf(o1[2] - LB*vs1.x, inv, vs1.x);
            r1.y = fmaf(o1[3] - LB*vs1.y, inv, vs1.y);
            *(float2*)(op + 2*tig) = r0;
            *(float2*)(op + 8 + 2*tig) = r1;
        }
    }
}

// ---------------- kernel 4: FFN(gelu) + residual + LayerNorm (persistent, grid 444) ----------------
__global__ __launch_bounds__(256) void ffn_kernel(
    const float* __restrict__ x,
    const float* __restrict__ Wf1, const float* __restrict__ bf1,
    const float* __restrict__ Wf2, const float* __restrict__ bf2,
    const float* __restrict__ gln, const float* __restrict__ bln,
    float* __restrict__ out)
{
    extern __shared__ float sm[];
    float* sW1 = sm;            // 4352
    float* sW2 = sm + 4352;     // 4352
    float* sb1 = sm + 8704;     // 64
    float* sb2 = sm + 8768;     // 64
    float* sg  = sm + 8832;     // 64
    float* sbl = sm + 8896;     // 64
    float* srow = sm + 8960;    // 8 * 512 = 4096

    for (int i = threadIdx.x; i < 4096; i += 256) {
        int f = i >> 6, c = i & 63;
        sW1[f*68+c] = Wf1[i];
        sW2[f*68+c] = Wf2[i];
    }
    if (threadIdx.x < 64) {
        sb1[threadIdx.x] = bf1[threadIdx.x];
        sb2[threadIdx.x] = bf2[threadIdx.x];
        sg [threadIdx.x] = gln[threadIdx.x];
        sbl[threadIdx.x] = bln[threadIdx.x];
    }
    __syncthreads();

    int warp = threadIdx.x >> 5, lane = threadIdx.x & 31;
    float* myrow = srow + warp*512;
    int f0 = lane, f1 = lane + 32;

    for (int blk = blockIdx.x; blk < 975; blk += 444) {
        int r0 = blk*64 + warp*8;
        {
            const float* vs = g_val + (size_t)r0*64;
            for (int i = lane; i < 512; i += 32) myrow[i] = vs[i];
        }
        __syncwarp();

        float t0[8], t1[8];
#pragma unroll
        for (int r = 0; r < 8; ++r) { t0[r] = sb1[f0]; t1[r] = sb1[f1]; }
#pragma unroll 4
        for (int c = 0; c < 64; c += 4) {
            float4 w0 = *(const float4*)(sW1 + f0*68 + c);
            float4 w1 = *(const float4*)(sW1 + f1*68 + c);
#pragma unroll
            for (int r = 0; r < 8; ++r) {
                float4 xv = *(const float4*)(myrow + r*64 + c);
                t0[r] = fmaf(xv.x, w0.x, t0[r]);  t1[r] = fmaf(xv.x, w1.x, t1[r]);
                t0[r] = fmaf(xv.y, w0.y, t0[r]);  t1[r] = fmaf(xv.y, w1.y, t1[r]);
                t0[r] = fmaf(xv.z, w0.z, t0[r]);  t1[r] = fmaf(xv.z, w1.z, t1[r]);
                t0[r] = fmaf(xv.w, w0.w, t0[r]);  t1[r] = fmaf(xv.w, w1.w, t1[r]);
            }
        }
#pragma unroll
        for (int r = 0; r < 8; ++r) {
            t0[r] = 0.5f*t0[r]*(1.f + erff(t0[r]*0.7071067811865476f));
            t1[r] = 0.5f*t1[r]*(1.f + erff(t1[r]*0.7071067811865476f));
        }
        __syncwarp();
#pragma unroll
        for (int r = 0; r < 8; ++r) { myrow[r*64+f0] = t0[r]; myrow[r*64+f1] = t1[r]; }
        __syncwarp();

        float h0[8], h1[8];
        const float* xr = x + (size_t)r0*64;
#pragma unroll
        for (int r = 0; r < 8; ++r) {
            h0[r] = sb2[f0] + xr[r*64+f0];
            h1[r] = sb2[f1] + xr[r*64+f1];
        }
#pragma unroll 4
        for (int c = 0; c < 64; c += 4) {
            float4 w0 = *(const float4*)(sW2 + f0*68 + c);
            float4 w1 = *(const float4*)(sW2 + f1*68 + c);
#pragma unroll
            for (int r = 0; r < 8; ++r) {
                float4 xv = *(const float4*)(myrow + r*64 + c);
                h0[r] = fmaf(xv.x, w0.x, h0[r]);  h1[r] = fmaf(xv.x, w1.x, h1[r]);
                h0[r] = fmaf(xv.y, w0.y, h0[r]);  h1[r] = fmaf(xv.y, w1.y, h1[r]);
                h0[r] = fmaf(xv.z, w0.z, h0[r]);  h1[r] = fmaf(xv.z, w1.z, h1[r]);
                h0[r] = fmaf(xv.w, w0.w, h0[r]);  h1[r] = fmaf(xv.w, w1.w, h1[r]);
            }
        }
#pragma unroll
        for (int r = 0; r < 8; ++r) {
            float s1 = h0[r] + h1[r];
            float s2 = fmaf(h0[r], h0[r], h1[r]*h1[r]);
#pragma unroll
            for (int oo = 16; oo; oo >>= 1) {
                s1 += __shfl_xor_sync(0xffffffffu, s1, oo);
                s2 += __shfl_xor_sync(0xffffffffu, s2, oo);
            }
            float mean = s1 * (1.f/64.f);
            float var  = s2 * (1.f/64.f) - mean*mean;
            float rs   = rsqrtf(var + 1e-5f);
            out[(size_t)(r0+r)*64 + f0] = fmaf(sg[f0], (h0[r]-mean)*rs, sbl[f0]);
            out[(size_t)(r0+r)*64 + f1] = fmaf(sg[f1], (h1[r]-mean)*rs, sbl[f1]);
        }
        __syncwarp();
    }
}

// ---------------- launch ----------------
extern "C" void kernel_launch(void* const* d_in, const int* in_sizes, int n_in,
                              void* d_out, int out_size)
{
    const float* x   = (const float*)d_in[0];
    const float* A   = (const float*)d_in[1];
    const float* AT  = (const float*)d_in[2];
    const float* Wq  = (const float*)d_in[3];
    const float* bq  = (const float*)d_in[4];
    const float* Wk  = (const float*)d_in[5];
    const float* bk  = (const float*)d_in[6];
    const float* Wks = (const float*)d_in[7];
    const float* bks = (const float*)d_in[8];
    const float* Wv  = (const float*)d_in[9];
    const float* bv  = (const float*)d_in[10];
    const float* Wvs = (const float*)d_in[11];
    const float* bvs = (const float*)d_in[12];
    const float* Wdi = (const float*)d_in[13];
    const float* Wdo = (const float*)d_in[14];
    const float* Wf1 = (const float*)d_in[15];
    const float* bf1 = (const float*)d_in[16];
    const float* Wf2 = (const float*)d_in[17];
    const float* bf2 = (const float*)d_in[18];
    const float* gln = (const float*)d_in[19];
    const float* bln = (const float*)d_in[20];
    float* out = (float*)d_out;

    cudaFuncSetAttribute(proj_kernel, cudaFuncAttributeMaxDynamicSharedMemorySize, 47360);
    cudaFuncSetAttribute(attn_kernel, cudaFuncAttributeMaxDynamicSharedMemorySize, 27136);
    cudaFuncSetAttribute(ffn_kernel,  cudaFuncAttributeMaxDynamicSharedMemorySize, 52224);

    bias_kernel<<<(KHn*NNn + 255)/256, 256>>>(A, AT, Wdi, Wdo);
    proj_kernel<<<244, 256, 47360>>>(x, Wq, bq, Wk, bk, Wks, bks, Wv, bv, Wvs, bvs);
    dim3 ag(BTn, KHn);
    attn_kernel<<<ag, ATH, 27136>>>();
    ffn_kernel<<<444, 256, 52224>>>(x, Wf1, bf1, Wf2, bf2, gln, bln, out);
}

// round 12
// speedup vs baseline: 2.3079x; 1.0998x over previous
#include <cuda_runtime.h>
#include <cuda_fp16.h>
#include <math.h>
#include <stdint.h>

#define Bn 16
#define Tn 12
#define Nn 325
#define Fn 64
#define KHn 4
#define Dn 16
#define KDn 3
#define BTn (Bn*Tn)            // 192
#define BTNn (BTn*Nn)          // 62400
#define NNn (Nn*Nn)            // 105625
#define QPAD 336               // padded node count (21*16)
#define BPAD 336
#define KSTRIDE 24             // halves per K row in smem
#define VSTRIDE 344            // halves per Vt row in smem
#define WSTRIDE 72             // halves per weight row in smem (bank-mult 4, conflict-free)

// ---------------- scratch (device globals; zero-initialized, no allocation) ----------------
__device__ float  g_q [KHn*BTNn*Dn + 256];
__device__ float  g_k [KHn*BTNn*Dn + 256];
__device__ float  g_ks[KHn*BTNn*Dn + 256];
__device__ float  g_v [KHn*BTNn*Dn + 256];
__device__ float  g_vs[KHn*BTNn*Dn + 256];
__device__ __half g_bias2[KHn*BPAD*BPAD];    // [h][q][k] fp16, pad region stays zero
__device__ float  g_val[BTNn*Fn];

// ---------------- mma helper: m16n8k16 row.col f32 += f16*f16 ----------------
__device__ __forceinline__ void mma16816(float d[4],
    uint32_t a0, uint32_t a1, uint32_t a2, uint32_t a3,
    uint32_t b0, uint32_t b1)
{
    asm volatile(
        "mma.sync.aligned.m16n8k16.row.col.f32.f16.f16.f32 "
        "{%0,%1,%2,%3}, {%4,%5,%6,%7}, {%8,%9}, {%0,%1,%2,%3};"
        : "+f"(d[0]), "+f"(d[1]), "+f"(d[2]), "+f"(d[3])
        : "r"(a0), "r"(a1), "r"(a2), "r"(a3), "r"(b0), "r"(b1));
}
__device__ __forceinline__ uint32_t f2h2(float x, float y) {
    __half2 h = __floats2half2_rn(x, y);
    return *(uint32_t*)&h;
}
__device__ __forceinline__ float gelu_exact(float v) {
    return 0.5f*v*(1.f + erff(v*0.7071067811865476f));
}

// ---------------- kernel 1: graph-diffusion bias -> fp16 padded [h][q][k] ----------------
__global__ void bias_kernel(const float* __restrict__ A, const float* __restrict__ AT,
                            const float* __restrict__ Wdi, const float* __restrict__ Wdo)
{
    int idx = blockIdx.x*blockDim.x + threadIdx.x;
    if (idx >= KHn*NNn) return;
    int h = idx / NNn, nm = idx - h*NNn;
    int n = nm / Nn, m = nm - n*Nn;
    float s = 0.f;
    if (h < 2) {
#pragma unroll
        for (int j = 0; j < KDn; ++j) s = fmaf(Wdi[(h*KDn+j)*NNn+nm], A[j*NNn+nm], s);
    } else {
#pragma unroll
        for (int j = 0; j < KDn; ++j) s = fmaf(Wdo[((h-2)*KDn+j)*NNn+nm], AT[j*NNn+nm], s);
    }
    g_bias2[((size_t)h*BPAD + n)*BPAD + m] = __float2half(s);
}

// ---------------- kernel 2: fused 5-way projection via tensor-core MMA ----------------
__global__ __launch_bounds__(256) void proj_kernel(
    const float* __restrict__ x,
    const float* __restrict__ Wq,  const float* __restrict__ bq,
    const float* __restrict__ Wk,  const float* __restrict__ bk,
    const float* __restrict__ Wks, const float* __restrict__ bks,
    const float* __restrict__ Wv,  const float* __restrict__ bv,
    const float* __restrict__ Wvs, const float* __restrict__ bvs)
{
    extern __shared__ char smraw[];
    __half* sW = (__half*)smraw;                  // 5 * 64*72 halves = 46080 B
    float* sbias = (float*)(smraw + 46080);       // 5 * 64 floats = 1280 B

    const float* Ws[5] = {Wq, Wk, Wks, Wv, Wvs};
    const float* bs[5] = {bq, bk, bks, bv, bvs};
    for (int i = threadIdx.x; i < 5*4096; i += 256) {
        int p = i >> 12, idx = i & 4095;
        int f = idx >> 6, c = idx & 63;
        sW[p*4608 + f*WSTRIDE + c] = __float2half(Ws[p][f*64 + c]);
    }
    for (int i = threadIdx.x; i < 5*64; i += 256)
        sbias[i] = bs[i >> 6][i & 63];
    __syncthreads();

    int warp = threadIdx.x >> 5, lane = threadIdx.x & 31;
    int gid = lane >> 2, tig = lane & 3;
    float* outp[5] = {g_q, g_k, g_ks, g_v, g_vs};

    int wglobal = blockIdx.x*8 + warp;
    for (int tile = wglobal; tile < 3900; tile += 244*8) {
        int r0 = tile*16;
        int rA = r0 + gid, rB = r0 + gid + 8;

        uint32_t a[4][4];
#pragma unroll
        for (int j = 0; j < 4; ++j) {
            float2 fA0 = *(const float2*)(x + (size_t)rA*64 + 16*j + 2*tig);
            float2 fB0 = *(const float2*)(x + (size_t)rB*64 + 16*j + 2*tig);
            float2 fA8 = *(const float2*)(x + (size_t)rA*64 + 16*j + 2*tig + 8);
            float2 fB8 = *(const float2*)(x + (size_t)rB*64 + 16*j + 2*tig + 8);
            a[j][0] = f2h2(fA0.x, fA0.y);
            a[j][1] = f2h2(fB0.x, fB0.y);
            a[j][2] = f2h2(fA8.x, fA8.y);
            a[j][3] = f2h2(fB8.x, fB8.y);
        }

#pragma unroll 1
        for (int p = 0; p < 5; ++p) {
            const __half* wp = sW + p*4608;
            float* o = outp[p];
#pragma unroll
            for (int nch = 0; nch < 8; ++nch) {
                float d[4] = {0.f, 0.f, 0.f, 0.f};
#pragma unroll
                for (int j = 0; j < 4; ++j) {
                    uint32_t b0 = *(const uint32_t*)(wp + (nch*8+gid)*WSTRIDE + 16*j + 2*tig);
                    uint32_t b1 = *(const uint32_t*)(wp + (nch*8+gid)*WSTRIDE + 16*j + 2*tig + 8);
                    mma16816(d, a[j][0], a[j][1], a[j][2], a[j][3], b0, b1);
                }
                int f = nch*8 + 2*tig;
                int hh = f >> 4, dd = f & 15;
                float bb0 = sbias[p*64 + f], bb1 = sbias[p*64 + f + 1];
                float2 rA2, rB2;
                rA2.x = d[0] + bb0;  rA2.y = d[1] + bb1;
                rB2.x = d[2] + bb0;  rB2.y = d[3] + bb1;
                *(float2*)(o + ((size_t)hh*BTNn + rA)*Dn + dd) = rA2;
                *(float2*)(o + ((size_t)hh*BTNn + rB)*Dn + dd) = rB2;
            }
        }
    }
}

// ---------------- kernel 3: attention via tensor-core mma (fp16 in, fp32 acc) ----------------
#define ATH 352
__global__ __launch_bounds__(ATH, 2) void attn_kernel()
{
    extern __shared__ char smem_raw[];
    __half* sKs = (__half*)smem_raw;                  // [336][24] halves = 16128 B
    __half* sVt = (__half*)(smem_raw + 16128);        // [16][344] halves = 11008 B

    int bt = blockIdx.x, h = blockIdx.y;
    size_t base = ((size_t)h*BTNn + (size_t)bt*Nn)*Dn;
    const float* gk  = g_k  + base;
    const float* gv  = g_v  + base;
    const float* gq  = g_q  + base;
    const float* gks = g_ks + base;
    const float* gvs = g_vs + base;
    int tid = threadIdx.x;

    for (int i = tid; i < QPAD*Dn; i += ATH) {
        int key = i >> 4, d = i & 15;
        __half kh = __float2half(0.f), vh = __float2half(0.f);
        if (key < Nn) {
            kh = __float2half(gk[key*16 + d]);
            vh = __float2half(gv[key*16 + d]);
        }
        sKs[key*KSTRIDE + d] = kh;
        sVt[d*VSTRIDE + key] = vh;
    }
    __syncthreads();

    int warp = tid >> 5, lane = tid & 31;
    int gid = lane >> 2, tig = lane & 3;
    const __half* bias = g_bias2 + (size_t)h*BPAD*BPAD;

    for (int rb = warp; rb <= 20; rb += 11) {
        int q0 = rb*16;
        int qA = q0 + gid, qB = q0 + gid + 8;
        bool vA = qA < Nn, vB = qB < Nn;

        uint32_t qa0 = 0, qa1 = 0, qa2 = 0, qa3 = 0;
        if (vA) {
            float2 f0 = *(const float2*)(gq + qA*16 + 2*tig);
            float2 f2 = *(const float2*)(gq + qA*16 + 2*tig + 8);
            qa0 = f2h2(f0.x, f0.y);  qa2 = f2h2(f2.x, f2.y);
        }
        if (vB) {
            float2 f1 = *(const float2*)(gq + qB*16 + 2*tig);
            float2 f3 = *(const float2*)(gq + qB*16 + 2*tig + 8);
            qa1 = f2h2(f1.x, f1.y);  qa3 = f2h2(f3.x, f3.y);
        }

        float esv = 1.f;
        {
            int q = q0 + lane;
            if (lane < 16 && q < Nn) {
                float s = 0.f;
#pragma unroll
                for (int d = 0; d < 16; ++d) s = fmaf(gq[q*16+d], gks[q*16+d], s);
                esv = 1.f/(1.f + __expf(-s*0.25f));
            }
        }
        float esA = __shfl_sync(0xffffffffu, esv, gid);
        float esB = __shfl_sync(0xffffffffu, esv, gid + 8);

        float o0[4] = {0.f,0.f,0.f,0.f};
        float o1[4] = {0.f,0.f,0.f,0.f};
        float LA = 0.f, LB = 0.f;

#pragma unroll 1
        for (int kb = 0; kb < 21; ++kb) {
            int k0 = kb*16;
            uint32_t b0a = *(const uint32_t*)(sKs + (k0+gid)*KSTRIDE + 2*tig);
            uint32_t b1a = *(const uint32_t*)(sKs + (k0+gid)*KSTRIDE + 2*tig + 8);
            uint32_t b0b = *(const uint32_t*)(sKs + (k0+8+gid)*KSTRIDE + 2*tig);
            uint32_t b1b = *(const uint32_t*)(sKs + (k0+8+gid)*KSTRIDE + 2*tig + 8);
            float c0[4] = {0.f,0.f,0.f,0.f};
            float c1[4] = {0.f,0.f,0.f,0.f};
            mma16816(c0, qa0, qa1, qa2, qa3, b0a, b1a);
            mma16816(c1, qa0, qa1, qa2, qa3, b0b, b1b);

            uint32_t pa0, pa1, pa2, pa3;
            {
                int kc = k0 + 2*tig;
                float2 bA2 = __half22float2(*(const __half2*)(bias + (size_t)qA*BPAD + kc));
                float2 bB2 = __half22float2(*(const __half2*)(bias + (size_t)qB*BPAD + kc));
                bool u0 = kc < Nn, u1 = (kc+1) < Nn;
                float p00 = u0 ? __expf(fmaf(c0[0], 0.25f, bA2.x)) : 0.f;
                float p01 = u1 ? __expf(fmaf(c0[1], 0.25f, bA2.y)) : 0.f;
                float p10 = u0 ? __expf(fmaf(c0[2], 0.25f, bB2.x)) : 0.f;
                float p11 = u1 ? __expf(fmaf(c0[3], 0.25f, bB2.y)) : 0.f;
                LA += p00 + p01;  LB += p10 + p11;
                pa0 = f2h2(p00, p01);  pa1 = f2h2(p10, p11);
            }
            {
                int kc = k0 + 8 + 2*tig;
                float2 bA2 = __half22float2(*(const __half2*)(bias + (size_t)qA*BPAD + kc));
                float2 bB2 = __half22float2(*(const __half2*)(bias + (size_t)qB*BPAD + kc));
                bool u0 = kc < Nn, u1 = (kc+1) < Nn;
                float p00 = u0 ? __expf(fmaf(c1[0], 0.25f, bA2.x)) : 0.f;
                float p01 = u1 ? __expf(fmaf(c1[1], 0.25f, bA2.y)) : 0.f;
                float p10 = u0 ? __expf(fmaf(c1[2], 0.25f, bB2.x)) : 0.f;
                float p11 = u1 ? __expf(fmaf(c1[3], 0.25f, bB2.y)) : 0.f;
                LA += p00 + p01;  LB += p10 + p11;
                pa2 = f2h2(p00, p01);  pa3 = f2h2(p10, p11);
            }

            uint32_t vb0 = *(const uint32_t*)(sVt + gid*VSTRIDE + k0 + 2*tig);
            uint32_t vb1 = *(const uint32_t*)(sVt + gid*VSTRIDE + k0 + 2*tig + 8);
            mma16816(o0, pa0, pa1, pa2, pa3, vb0, vb1);
            uint32_t vb2 = *(const uint32_t*)(sVt + (8+gid)*VSTRIDE + k0 + 2*tig);
            uint32_t vb3 = *(const uint32_t*)(sVt + (8+gid)*VSTRIDE + k0 + 2*tig + 8);
            mma16816(o1, pa0, pa1, pa2, pa3, vb2, vb3);
        }

        LA += __shfl_xor_sync(0xffffffffu, LA, 1);
        LA += __shfl_xor_sync(0xffffffffu, LA, 2);
        LB += __shfl_xor_sync(0xffffffffu, LB, 1);
        LB += __shfl_xor_sync(0xffffffffu, LB, 2);

        if (vA) {
            float inv = 1.f/(esA + LA);
            float* op = g_val + ((size_t)bt*Nn + qA)*Fn + h*16;
            float2 vs0 = *(const float2*)(gvs + qA*16 + 2*tig);
            float2 vs1 = *(const float2*)(gvs + qA*16 + 8 + 2*tig);
            float2 r0, r1;
            r0.x = fmaf(o0[0] - LA*vs0.x, inv, vs0.x);
            r0.y = fmaf(o0[1] - LA*vs0.y, inv, vs0.y);
            r1.x = fmaf(o1[0] - LA*vs1.x, inv, vs1.x);
            r1.y = fmaf(o1[1] - LA*vs1.y, inv, vs1.y);
            *(float2*)(op + 2*tig) = r0;
            *(float2*)(op + 8 + 2*tig) = r1;
        }
        if (vB) {
            float inv = 1.f/(esB + LB);
            float* op = g_val + ((size_t)bt*Nn + qB)*Fn + h*16;
            float2 vs0 = *(const float2*)(gvs + qB*16 + 2*tig);
            float2 vs1 = *(const float2*)(gvs + qB*16 + 8 + 2*tig);
            float2 r0, r1;
            r0.x = fmaf(o0[2] - LB*vs0.x, inv, vs0.x);
            r0.y = fmaf(o0[3] - LB*vs0.y, inv, vs0.y);
            r1.x = fmaf(o1[2] - LB*vs1.x, inv, vs1.x);
            r1.y = fmaf(o1[3] - LB*vs1.y, inv, vs1.y);
            *(float2*)(op + 2*tig) = r0;
            *(float2*)(op + 8 + 2*tig) = r1;
        }
    }
}

// ---------------- kernel 4: FFN via tensor-core MMA (gelu on fragments) + residual + LN ----------------
// Warp tile = 16 rows. GEMM1 chunk-pair C-frag == GEMM2 A-frag k-step (FlashAttention trick).
__global__ __launch_bounds__(256) void ffn_kernel(
    const float* __restrict__ x,
    const float* __restrict__ Wf1, const float* __restrict__ bf1,
    const float* __restrict__ Wf2, const float* __restrict__ bf2,
    const float* __restrict__ gln, const float* __restrict__ bln,
    float* __restrict__ out)
{
    extern __shared__ char smraw[];
    __half* sW1 = (__half*)smraw;                 // 64*72 halves = 9216 B
    __half* sW2 = (__half*)(smraw + 9216);        // 9216 B
    float* sb1 = (float*)(smraw + 18432);         // 64
    float* sb2 = sb1 + 64;
    float* sg  = sb1 + 128;
    float* sbl = sb1 + 192;

    for (int i = threadIdx.x; i < 4096; i += 256) {
        int f = i >> 6, c = i & 63;
        sW1[f*WSTRIDE + c] = __float2half(Wf1[i]);
        sW2[f*WSTRIDE + c] = __float2half(Wf2[i]);
    }
    if (threadIdx.x < 64) {
        sb1[threadIdx.x] = bf1[threadIdx.x];
        sb2[threadIdx.x] = bf2[threadIdx.x];
        sg [threadIdx.x] = gln[threadIdx.x];
        sbl[threadIdx.x] = bln[threadIdx.x];
    }
    __syncthreads();

    int warp = threadIdx.x >> 5, lane = threadIdx.x & 31;
    int gid = lane >> 2, tig = lane & 3;

    for (int tile = blockIdx.x*8 + warp; tile < 3900; tile += 244*8) {
        int rA = tile*16 + gid, rB = rA + 8;

        // A frags from g_val
        uint32_t a[4][4];
#pragma unroll
        for (int j = 0; j < 4; ++j) {
            float2 fA0 = *(const float2*)(g_val + (size_t)rA*64 + 16*j + 2*tig);
            float2 fB0 = *(const float2*)(g_val + (size_t)rB*64 + 16*j + 2*tig);
            float2 fA8 = *(const float2*)(g_val + (size_t)rA*64 + 16*j + 2*tig + 8);
            float2 fB8 = *(const float2*)(g_val + (size_t)rB*64 + 16*j + 2*tig + 8);
            a[j][0] = f2h2(fA0.x, fA0.y);
            a[j][1] = f2h2(fB0.x, fB0.y);
            a[j][2] = f2h2(fA8.x, fA8.y);
            a[j][3] = f2h2(fB8.x, fB8.y);
        }

        // GEMM1 (chunk pairs) + bias1 + gelu -> packed A-frags for GEMM2
        uint32_t pa[4][4];
#pragma unroll
        for (int j2 = 0; j2 < 4; ++j2) {
            float d0[4] = {0.f,0.f,0.f,0.f};   // cols 16*j2 + 2tig(+1)
            float d1[4] = {0.f,0.f,0.f,0.f};   // cols 16*j2 + 8 + 2tig(+1)
#pragma unroll
            for (int j = 0; j < 4; ++j) {
                uint32_t b0 = *(const uint32_t*)(sW1 + (16*j2+gid)*WSTRIDE + 16*j + 2*tig);
                uint32_t b1 = *(const uint32_t*)(sW1 + (16*j2+gid)*WSTRIDE + 16*j + 2*tig + 8);
                mma16816(d0, a[j][0], a[j][1], a[j][2], a[j][3], b0, b1);
                uint32_t c0 = *(const uint32_t*)(sW1 + (16*j2+8+gid)*WSTRIDE + 16*j + 2*tig);
                uint32_t c1 = *(const uint32_t*)(sW1 + (16*j2+8+gid)*WSTRIDE + 16*j + 2*tig + 8);
                mma16816(d1, a[j][0], a[j][1], a[j][2], a[j][3], c0, c1);
            }
            int fb = 16*j2 + 2*tig;
            float b00 = sb1[fb], b01 = sb1[fb+1], b08 = sb1[fb+8], b09 = sb1[fb+9];
            pa[j2][0] = f2h2(gelu_exact(d0[0]+b00), gelu_exact(d0[1]+b01));
            pa[j2][1] = f2h2(gelu_exact(d0[2]+b00), gelu_exact(d0[3]+b01));
            pa[j2][2] = f2h2(gelu_exact(d1[0]+b08), gelu_exact(d1[1]+b09));
            pa[j2][3] = f2h2(gelu_exact(d1[2]+b08), gelu_exact(d1[3]+b09));
        }

        // GEMM2 + bias2 + residual
        float hh[8][4];
#pragma unroll
        for (int nch = 0; nch < 8; ++nch) {
            float d[4] = {0.f,0.f,0.f,0.f};
#pragma unroll
            for (int j = 0; j < 4; ++j) {
                uint32_t b0 = *(const uint32_t*)(sW2 + (nch*8+gid)*WSTRIDE + 16*j + 2*tig);
                uint32_t b1 = *(const uint32_t*)(sW2 + (nch*8+gid)*WSTRIDE + 16*j + 2*tig + 8);
                mma16816(d, pa[j][0], pa[j][1], pa[j][2], pa[j][3], b0, b1);
            }
            int f = nch*8 + 2*tig;
            float2 xA = *(const float2*)(x + (size_t)rA*64 + f);
            float2 xB = *(const float2*)(x + (size_t)rB*64 + f);
            hh[nch][0] = d[0] + sb2[f]   + xA.x;
            hh[nch][1] = d[1] + sb2[f+1] + xA.y;
            hh[nch][2] = d[2] + sb2[f]   + xB.x;
            hh[nch][3] = d[3] + sb2[f+1] + xB.y;
        }

        // LayerNorm per row (quad holds all 64 cols of each row)
        float s1A = 0.f, s2A = 0.f, s1B = 0.f, s2B = 0.f;
#pragma unroll
        for (int nch = 0; nch < 8; ++nch) {
            s1A += hh[nch][0] + hh[nch][1];
            s2A += hh[nch][0]*hh[nch][0] + hh[nch][1]*hh[nch][1];
            s1B += hh[nch][2] + hh[nch][3];
            s2B += hh[nch][2]*hh[nch][2] + hh[nch][3]*hh[nch][3];
        }
        s1A += __shfl_xor_sync(0xffffffffu, s1A, 1);
        s2A += __shfl_xor_sync(0xffffffffu, s2A, 1);
        s1B += __shfl_xor_sync(0xffffffffu, s1B, 1);
        s2B += __shfl_xor_sync(0xffffffffu, s2B, 1);
        s1A += __shfl_xor_sync(0xffffffffu, s1A, 2);
        s2A += __shfl_xor_sync(0xffffffffu, s2A, 2);
        s1B += __shfl_xor_sync(0xffffffffu, s1B, 2);
        s2B += __shfl_xor_sync(0xffffffffu, s2B, 2);

        float mA = s1A*(1.f/64.f), mB = s1B*(1.f/64.f);
        float rsA = rsqrtf(s2A*(1.f/64.f) - mA*mA + 1e-5f);
        float rsB = rsqrtf(s2B*(1.f/64.f) - mB*mB + 1e-5f);

#pragma unroll
        for (int nch = 0; nch < 8; ++nch) {
            int f = nch*8 + 2*tig;
            float g0 = sg[f], g1 = sg[f+1], l0 = sbl[f], l1 = sbl[f+1];
            float2 oA, oB;
            oA.x = fmaf(g0, (hh[nch][0]-mA)*rsA, l0);
            oA.y = fmaf(g1, (hh[nch][1]-mA)*rsA, l1);
            oB.x = fmaf(g0, (hh[nch][2]-mB)*rsB, l0);
            oB.y = fmaf(g1, (hh[nch][3]-mB)*rsB, l1);
            *(float2*)(out + (size_t)rA*64 + f) = oA;
            *(float2*)(out + (size_t)rB*64 + f) = oB;
        }
    }
}

// ---------------- launch ----------------
extern "C" void kernel_launch(void* const* d_in, const int* in_sizes, int n_in,
                              void* d_out, int out_size)
{
    const float* x   = (const float*)d_in[0];
    const float* A   = (const float*)d_in[1];
    const float* AT  = (const float*)d_in[2];
    const float* Wq  = (const float*)d_in[3];
    const float* bq  = (const float*)d_in[4];
    const float* Wk  = (const float*)d_in[5];
    const float* bk  = (const float*)d_in[6];
    const float* Wks = (const float*)d_in[7];
    const float* bks = (const float*)d_in[8];
    const float* Wv  = (const float*)d_in[9];
    const float* bv  = (const float*)d_in[10];
    const float* Wvs = (const float*)d_in[11];
    const float* bvs = (const float*)d_in[12];
    const float* Wdi = (const float*)d_in[13];
    const float* Wdo = (const float*)d_in[14];
    const float* Wf1 = (const float*)d_in[15];
    const float* bf1 = (const float*)d_in[16];
    const float* Wf2 = (const float*)d_in[17];
    const float* bf2 = (const float*)d_in[18];
    const float* gln = (const float*)d_in[19];
    const float* bln = (const float*)d_in[20];
    float* out = (float*)d_out;

    cudaFuncSetAttribute(proj_kernel, cudaFuncAttributeMaxDynamicSharedMemorySize, 47360);
    cudaFuncSetAttribute(attn_kernel, cudaFuncAttributeMaxDynamicSharedMemorySize, 27136);
    cudaFuncSetAttribute(ffn_kernel,  cudaFuncAttributeMaxDynamicSharedMemorySize, 19712);

    bias_kernel<<<(KHn*NNn + 255)/256, 256>>>(A, AT, Wdi, Wdo);
    proj_kernel<<<244, 256, 47360>>>(x, Wq, bq, Wk, bk, Wks, bks, Wv, bv, Wvs, bvs);
    dim3 ag(BTn, KHn);
    attn_kernel<<<ag, ATH, 27136>>>();
    ffn_kernel<<<244, 256, 19712>>>(x, Wf1, bf1, Wf2, bf2, gln, bln, out);
}

// round 13
// speedup vs baseline: 2.4738x; 1.0719x over previous
#include <cuda_runtime.h>
#include <cuda_fp16.h>
#include <math.h>
#include <stdint.h>

#define Bn 16
#define Tn 12
#define Nn 325
#define Fn 64
#define KHn 4
#define Dn 16
#define KDn 3
#define BTn (Bn*Tn)            // 192
#define BTNn (BTn*Nn)          // 62400
#define NNn (Nn*Nn)            // 105625
#define QPAD 336               // padded node count (21*16)
#define BPAD 336
#define KSTRIDE 24             // halves per K row in smem
#define VSTRIDE 344            // halves per Vt row in smem
#define WSTRIDE 72             // halves per weight row in smem (bank-mult 4, conflict-free)

// ---------------- scratch (device globals; zero-initialized, no allocation) ----------------
__device__ float  g_q [KHn*BTNn*Dn + 256];
__device__ float  g_k [KHn*BTNn*Dn + 256];
__device__ float  g_ks[KHn*BTNn*Dn + 256];
__device__ float  g_v [KHn*BTNn*Dn + 256];
__device__ float  g_vs[KHn*BTNn*Dn + 256];
__device__ __half g_bias2[KHn*BPAD*BPAD];    // [h][q][k] fp16, pad region stays zero
__device__ float  g_val[BTNn*Fn];

// ---------------- mma helper: m16n8k16 row.col f32 += f16*f16 ----------------
__device__ __forceinline__ void mma16816(float d[4],
    uint32_t a0, uint32_t a1, uint32_t a2, uint32_t a3,
    uint32_t b0, uint32_t b1)
{
    asm volatile(
        "mma.sync.aligned.m16n8k16.row.col.f32.f16.f16.f32 "
        "{%0,%1,%2,%3}, {%4,%5,%6,%7}, {%8,%9}, {%0,%1,%2,%3};"
        : "+f"(d[0]), "+f"(d[1]), "+f"(d[2]), "+f"(d[3])
        : "r"(a0), "r"(a1), "r"(a2), "r"(a3), "r"(b0), "r"(b1));
}
__device__ __forceinline__ uint32_t f2h2(float x, float y) {
    __half2 h = __floats2half2_rn(x, y);
    return *(uint32_t*)&h;
}
__device__ __forceinline__ float gelu_exact(float v) {
    return 0.5f*v*(1.f + erff(v*0.7071067811865476f));
}

// ---------------- kernel 1: graph-diffusion bias -> fp16 padded [h][q][k] ----------------
__global__ void bias_kernel(const float* __restrict__ A, const float* __restrict__ AT,
                            const float* __restrict__ Wdi, const float* __restrict__ Wdo)
{
    int idx = blockIdx.x*blockDim.x + threadIdx.x;
    if (idx >= KHn*NNn) return;
    int h = idx / NNn, nm = idx - h*NNn;
    int n = nm / Nn, m = nm - n*Nn;
    float s = 0.f;
    if (h < 2) {
#pragma unroll
        for (int j = 0; j < KDn; ++j) s = fmaf(Wdi[(h*KDn+j)*NNn+nm], A[j*NNn+nm], s);
    } else {
#pragma unroll
        for (int j = 0; j < KDn; ++j) s = fmaf(Wdo[((h-2)*KDn+j)*NNn+nm], AT[j*NNn+nm], s);
    }
    g_bias2[((size_t)h*BPAD + n)*BPAD + m] = __float2half(s);
}

// ---------------- kernel 2: fused 5-way projection via tensor-core MMA ----------------
__global__ __launch_bounds__(256) void proj_kernel(
    const float* __restrict__ x,
    const float* __restrict__ Wq,  const float* __restrict__ bq,
    const float* __restrict__ Wk,  const float* __restrict__ bk,
    const float* __restrict__ Wks, const float* __restrict__ bks,
    const float* __restrict__ Wv,  const float* __restrict__ bv,
    const float* __restrict__ Wvs, const float* __restrict__ bvs)
{
    extern __shared__ char smraw[];
    __half* sW = (__half*)smraw;                  // 5 * 64*72 halves = 46080 B
    float* sbias = (float*)(smraw + 46080);       // 5 * 64 floats = 1280 B

    const float* Ws[5] = {Wq, Wk, Wks, Wv, Wvs};
    const float* bs[5] = {bq, bk, bks, bv, bvs};
    for (int i = threadIdx.x; i < 5*4096; i += 256) {
        int p = i >> 12, idx = i & 4095;
        int f = idx >> 6, c = idx & 63;
        sW[p*4608 + f*WSTRIDE + c] = __float2half(Ws[p][f*64 + c]);
    }
    for (int i = threadIdx.x; i < 5*64; i += 256)
        sbias[i] = bs[i >> 6][i & 63];
    __syncthreads();

    int warp = threadIdx.x >> 5, lane = threadIdx.x & 31;
    int gid = lane >> 2, tig = lane & 3;
    float* outp[5] = {g_q, g_k, g_ks, g_v, g_vs};

    int wglobal = blockIdx.x*8 + warp;
    for (int tile = wglobal; tile < 3900; tile += 488*8) {
        int r0 = tile*16;
        int rA = r0 + gid, rB = r0 + gid + 8;

        uint32_t a[4][4];
#pragma unroll
        for (int j = 0; j < 4; ++j) {
            float2 fA0 = *(const float2*)(x + (size_t)rA*64 + 16*j + 2*tig);
            float2 fB0 = *(const float2*)(x + (size_t)rB*64 + 16*j + 2*tig);
            float2 fA8 = *(const float2*)(x + (size_t)rA*64 + 16*j + 2*tig + 8);
            float2 fB8 = *(const float2*)(x + (size_t)rB*64 + 16*j + 2*tig + 8);
            a[j][0] = f2h2(fA0.x, fA0.y);
            a[j][1] = f2h2(fB0.x, fB0.y);
            a[j][2] = f2h2(fA8.x, fA8.y);
            a[j][3] = f2h2(fB8.x, fB8.y);
        }

#pragma unroll 1
        for (int p = 0; p < 5; ++p) {
            const __half* wp = sW + p*4608;
            float* o = outp[p];
#pragma unroll
            for (int nch = 0; nch < 8; ++nch) {
                float d[4] = {0.f, 0.f, 0.f, 0.f};
#pragma unroll
                for (int j = 0; j < 4; ++j) {
                    uint32_t b0 = *(const uint32_t*)(wp + (nch*8+gid)*WSTRIDE + 16*j + 2*tig);
                    uint32_t b1 = *(const uint32_t*)(wp + (nch*8+gid)*WSTRIDE + 16*j + 2*tig + 8);
                    mma16816(d, a[j][0], a[j][1], a[j][2], a[j][3], b0, b1);
                }
                int f = nch*8 + 2*tig;
                int hh = f >> 4, dd = f & 15;
                float bb0 = sbias[p*64 + f], bb1 = sbias[p*64 + f + 1];
                float2 rA2, rB2;
                rA2.x = d[0] + bb0;  rA2.y = d[1] + bb1;
                rB2.x = d[2] + bb0;  rB2.y = d[3] + bb1;
                *(float2*)(o + ((size_t)hh*BTNn + rA)*Dn + dd) = rA2;
                *(float2*)(o + ((size_t)hh*BTNn + rB)*Dn + dd) = rB2;
            }
        }
    }
}

// ---------------- kernel 3: attention via tensor-core mma (fp16 in, fp32 acc) ----------------
#define ATH 352
__global__ __launch_bounds__(ATH, 3) void attn_kernel()
{
    extern __shared__ char smem_raw[];
    __half* sKs = (__half*)smem_raw;                  // [336][24] halves = 16128 B
    __half* sVt = (__half*)(smem_raw + 16128);        // [16][344] halves = 11008 B

    int bt = blockIdx.x, h = blockIdx.y;
    size_t base = ((size_t)h*BTNn + (size_t)bt*Nn)*Dn;
    const float* gk  = g_k  + base;
    const float* gv  = g_v  + base;
    const float* gq  = g_q  + base;
    const float* gks = g_ks + base;
    const float* gvs = g_vs + base;
    int tid = threadIdx.x;

    for (int i = tid; i < QPAD*Dn; i += ATH) {
        int key = i >> 4, d = i & 15;
        __half kh = __float2half(0.f), vh = __float2half(0.f);
        if (key < Nn) {
            kh = __float2half(gk[key*16 + d]);
            vh = __float2half(gv[key*16 + d]);
        }
        sKs[key*KSTRIDE + d] = kh;
        sVt[d*VSTRIDE + key] = vh;
    }
    __syncthreads();

    int warp = tid >> 5, lane = tid & 31;
    int gid = lane >> 2, tig = lane & 3;
    const __half* bias = g_bias2 + (size_t)h*BPAD*BPAD;

    for (int rb = warp; rb <= 20; rb += 11) {
        int q0 = rb*16;
        int qA = q0 + gid, qB = q0 + gid + 8;
        bool vA = qA < Nn, vB = qB < Nn;

        uint32_t qa0 = 0, qa1 = 0, qa2 = 0, qa3 = 0;
        if (vA) {
            float2 f0 = *(const float2*)(gq + qA*16 + 2*tig);
            float2 f2 = *(const float2*)(gq + qA*16 + 2*tig + 8);
            qa0 = f2h2(f0.x, f0.y);  qa2 = f2h2(f2.x, f2.y);
        }
        if (vB) {
            float2 f1 = *(const float2*)(gq + qB*16 + 2*tig);
            float2 f3 = *(const float2*)(gq + qB*16 + 2*tig + 8);
            qa1 = f2h2(f1.x, f1.y);  qa3 = f2h2(f3.x, f3.y);
        }

        float esv = 1.f;
        {
            int q = q0 + lane;
            if (lane < 16 && q < Nn) {
                float s = 0.f;
#pragma unroll
                for (int d = 0; d < 16; ++d) s = fmaf(gq[q*16+d], gks[q*16+d], s);
                esv = 1.f/(1.f + __expf(-s*0.25f));
            }
        }
        float esA = __shfl_sync(0xffffffffu, esv, gid);
        float esB = __shfl_sync(0xffffffffu, esv, gid + 8);

        float o0[4] = {0.f,0.f,0.f,0.f};
        float o1[4] = {0.f,0.f,0.f,0.f};
        float LA = 0.f, LB = 0.f;

#pragma unroll 1
        for (int kb = 0; kb < 21; ++kb) {
            int k0 = kb*16;
            uint32_t b0a = *(const uint32_t*)(sKs + (k0+gid)*KSTRIDE + 2*tig);
            uint32_t b1a = *(const uint32_t*)(sKs + (k0+gid)*KSTRIDE + 2*tig + 8);
            uint32_t b0b = *(const uint32_t*)(sKs + (k0+8+gid)*KSTRIDE + 2*tig);
            uint32_t b1b = *(const uint32_t*)(sKs + (k0+8+gid)*KSTRIDE + 2*tig + 8);
            float c0[4] = {0.f,0.f,0.f,0.f};
            float c1[4] = {0.f,0.f,0.f,0.f};
            mma16816(c0, qa0, qa1, qa2, qa3, b0a, b1a);
            mma16816(c1, qa0, qa1, qa2, qa3, b0b, b1b);

            uint32_t pa0, pa1, pa2, pa3;
            {
                int kc = k0 + 2*tig;
                float2 bA2 = __half22float2(*(const __half2*)(bias + (size_t)qA*BPAD + kc));
                float2 bB2 = __half22float2(*(const __half2*)(bias + (size_t)qB*BPAD + kc));
                bool u0 = kc < Nn, u1 = (kc+1) < Nn;
                float p00 = u0 ? __expf(fmaf(c0[0], 0.25f, bA2.x)) : 0.f;
                float p01 = u1 ? __expf(fmaf(c0[1], 0.25f, bA2.y)) : 0.f;
                float p10 = u0 ? __expf(fmaf(c0[2], 0.25f, bB2.x)) : 0.f;
                float p11 = u1 ? __expf(fmaf(c0[3], 0.25f, bB2.y)) : 0.f;
                LA += p00 + p01;  LB += p10 + p11;
                pa0 = f2h2(p00, p01);  pa1 = f2h2(p10, p11);
            }
            {
                int kc = k0 + 8 + 2*tig;
                float2 bA2 = __half22float2(*(const __half2*)(bias + (size_t)qA*BPAD + kc));
                float2 bB2 = __half22float2(*(const __half2*)(bias + (size_t)qB*BPAD + kc));
                bool u0 = kc < Nn, u1 = (kc+1) < Nn;
                float p00 = u0 ? __expf(fmaf(c1[0], 0.25f, bA2.x)) : 0.f;
                float p01 = u1 ? __expf(fmaf(c1[1], 0.25f, bA2.y)) : 0.f;
                float p10 = u0 ? __expf(fmaf(c1[2], 0.25f, bB2.x)) : 0.f;
                float p11 = u1 ? __expf(fmaf(c1[3], 0.25f, bB2.y)) : 0.f;
                LA += p00 + p01;  LB += p10 + p11;
                pa2 = f2h2(p00, p01);  pa3 = f2h2(p10, p11);
            }

            uint32_t vb0 = *(const uint32_t*)(sVt + gid*VSTRIDE + k0 + 2*tig);
            uint32_t vb1 = *(const uint32_t*)(sVt + gid*VSTRIDE + k0 + 2*tig + 8);
            mma16816(o0, pa0, pa1, pa2, pa3, vb0, vb1);
            uint32_t vb2 = *(const uint32_t*)(sVt + (8+gid)*VSTRIDE + k0 + 2*tig);
            uint32_t vb3 = *(const uint32_t*)(sVt + (8+gid)*VSTRIDE + k0 + 2*tig + 8);
            mma16816(o1, pa0, pa1, pa2, pa3, vb2, vb3);
        }

        LA += __shfl_xor_sync(0xffffffffu, LA, 1);
        LA += __shfl_xor_sync(0xffffffffu, LA, 2);
        LB += __shfl_xor_sync(0xffffffffu, LB, 1);
        LB += __shfl_xor_sync(0xffffffffu, LB, 2);

        if (vA) {
            float inv = 1.f/(esA + LA);
            float* op = g_val + ((size_t)bt*Nn + qA)*Fn + h*16;
            float2 vs0 = *(const float2*)(gvs + qA*16 + 2*tig);
            float2 vs1 = *(const float2*)(gvs + qA*16 + 8 + 2*tig);
            float2 r0, r1;
            r0.x = fmaf(o0[0] - LA*vs0.x, inv, vs0.x);
            r0.y = fmaf(o0[1] - LA*vs0.y, inv, vs0.y);
            r1.x = fmaf(o1[0] - LA*vs1.x, inv, vs1.x);
            r1.y = fmaf(o1[1] - LA*vs1.y, inv, vs1.y);
            *(float2*)(op + 2*tig) = r0;
            *(float2*)(op + 8 + 2*tig) = r1;
        }
        if (vB) {
            float inv = 1.f/(esB + LB);
            float* op = g_val + ((size_t)bt*Nn + qB)*Fn + h*16;
            float2 vs0 = *(const float2*)(gvs + qB*16 + 2*tig);
            float2 vs1 = *(const float2*)(gvs + qB*16 + 8 + 2*tig);
            float2 r0, r1;
            r0.x = fmaf(o0[2] - LB*vs0.x, inv, vs0.x);
            r0.y = fmaf(o0[3] - LB*vs0.y, inv, vs0.y);
            r1.x = fmaf(o1[2] - LB*vs1.x, inv, vs1.x);
            r1.y = fmaf(o1[3] - LB*vs1.y, inv, vs1.y);
            *(float2*)(op + 2*tig) = r0;
            *(float2*)(op + 8 + 2*tig) = r1;
        }
    }
}

// ---------------- kernel 4: FFN via tensor-core MMA (gelu on fragments) + residual + LN ----------------
__global__ __launch_bounds__(256) void ffn_kernel(
    const float* __restrict__ x,
    const float* __restrict__ Wf1, const float* __restrict__ bf1,
    const float* __restrict__ Wf2, const float* __restrict__ bf2,
    const float* __restrict__ gln, const float* __restrict__ bln,
    float* __restrict__ out)
{
    extern __shared__ char smraw[];
    __half* sW1 = (__half*)smraw;                 // 64*72 halves = 9216 B
    __half* sW2 = (__half*)(smraw + 9216);        // 9216 B
    float* sb1 = (float*)(smraw + 18432);         // 64
    float* sb2 = sb1 + 64;
    float* sg  = sb1 + 128;
    float* sbl = sb1 + 192;

    for (int i = threadIdx.x; i < 4096; i += 256) {
        int f = i >> 6, c = i & 63;
        sW1[f*WSTRIDE + c] = __float2half(Wf1[i]);
        sW2[f*WSTRIDE + c] = __float2half(Wf2[i]);
    }
    if (threadIdx.x < 64) {
        sb1[threadIdx.x] = bf1[threadIdx.x];
        sb2[threadIdx.x] = bf2[threadIdx.x];
        sg [threadIdx.x] = gln[threadIdx.x];
        sbl[threadIdx.x] = bln[threadIdx.x];
    }
    __syncthreads();

    int warp = threadIdx.x >> 5, lane = threadIdx.x & 31;
    int gid = lane >> 2, tig = lane & 3;

    for (int tile = blockIdx.x*8 + warp; tile < 3900; tile += 488*8) {
        int rA = tile*16 + gid, rB = rA + 8;

        uint32_t a[4][4];
#pragma unroll
        for (int j = 0; j < 4; ++j) {
            float2 fA0 = *(const float2*)(g_val + (size_t)rA*64 + 16*j + 2*tig);
            float2 fB0 = *(const float2*)(g_val + (size_t)rB*64 + 16*j + 2*tig);
            float2 fA8 = *(const float2*)(g_val + (size_t)rA*64 + 16*j + 2*tig + 8);
            float2 fB8 = *(const float2*)(g_val + (size_t)rB*64 + 16*j + 2*tig + 8);
            a[j][0] = f2h2(fA0.x, fA0.y);
            a[j][1] = f2h2(fB0.x, fB0.y);
            a[j][2] = f2h2(fA8.x, fA8.y);
            a[j][3] = f2h2(fB8.x, fB8.y);
        }

        uint32_t pa[4][4];
#pragma unroll
        for (int j2 = 0; j2 < 4; ++j2) {
            float d0[4] = {0.f,0.f,0.f,0.f};
            float d1[4] = {0.f,0.f,0.f,0.f};
#pragma unroll
            for (int j = 0; j < 4; ++j) {
                uint32_t b0 = *(const uint32_t*)(sW1 + (16*j2+gid)*WSTRIDE + 16*j + 2*tig);
                uint32_t b1 = *(const uint32_t*)(sW1 + (16*j2+gid)*WSTRIDE + 16*j + 2*tig + 8);
                mma16816(d0, a[j][0], a[j][1], a[j][2], a[j][3], b0, b1);
                uint32_t c0 = *(const uint32_t*)(sW1 + (16*j2+8+gid)*WSTRIDE + 16*j + 2*tig);
                uint32_t c1 = *(const uint32_t*)(sW1 + (16*j2+8+gid)*WSTRIDE + 16*j + 2*tig + 8);
                mma16816(d1, a[j][0], a[j][1], a[j][2], a[j][3], c0, c1);
            }
            int fb = 16*j2 + 2*tig;
            float b00 = sb1[fb], b01 = sb1[fb+1], b08 = sb1[fb+8], b09 = sb1[fb+9];
            pa[j2][0] = f2h2(gelu_exact(d0[0]+b00), gelu_exact(d0[1]+b01));
            pa[j2][1] = f2h2(gelu_exact(d0[2]+b00), gelu_exact(d0[3]+b01));
            pa[j2][2] = f2h2(gelu_exact(d1[0]+b08), gelu_exact(d1[1]+b09));
            pa[j2][3] = f2h2(gelu_exact(d1[2]+b08), gelu_exact(d1[3]+b09));
        }

        float hh[8][4];
#pragma unroll
        for (int nch = 0; nch < 8; ++nch) {
            float d[4] = {0.f,0.f,0.f,0.f};
#pragma unroll
            for (int j = 0; j < 4; ++j) {
                uint32_t b0 = *(const uint32_t*)(sW2 + (nch*8+gid)*WSTRIDE + 16*j + 2*tig);
                uint32_t b1 = *(const uint32_t*)(sW2 + (nch*8+gid)*WSTRIDE + 16*j + 2*tig + 8);
                mma16816(d, pa[j][0], pa[j][1], pa[j][2], pa[j][3], b0, b1);
            }
            int f = nch*8 + 2*tig;
            float2 xA = *(const float2*)(x + (size_t)rA*64 + f);
            float2 xB = *(const float2*)(x + (size_t)rB*64 + f);
            hh[nch][0] = d[0] + sb2[f]   + xA.x;
            hh[nch][1] = d[1] + sb2[f+1] + xA.y;
            hh[nch][2] = d[2] + sb2[f]   + xB.x;
            hh[nch][3] = d[3] + sb2[f+1] + xB.y;
        }

        float s1A = 0.f, s2A = 0.f, s1B = 0.f, s2B = 0.f;
#pragma unroll
        for (int nch = 0; nch < 8; ++nch) {
            s1A += hh[nch][0] + hh[nch][1];
            s2A += hh[nch][0]*hh[nch][0] + hh[nch][1]*hh[nch][1];
            s1B += hh[nch][2] + hh[nch][3];
            s2B += hh[nch][2]*hh[nch][2] + hh[nch][3]*hh[nch][3];
        }
        s1A += __shfl_xor_sync(0xffffffffu, s1A, 1);
        s2A += __shfl_xor_sync(0xffffffffu, s2A, 1);
        s1B += __shfl_xor_sync(0xffffffffu, s1B, 1);
        s2B += __shfl_xor_sync(0xffffffffu, s2B, 1);
        s1A += __shfl_xor_sync(0xffffffffu, s1A, 2);
        s2A += __shfl_xor_sync(0xffffffffu, s2A, 2);
        s1B += __shfl_xor_sync(0xffffffffu, s1B, 2);
        s2B += __shfl_xor_sync(0xffffffffu, s2B, 2);

        float mA = s1A*(1.f/64.f), mB = s1B*(1.f/64.f);
        float rsA = rsqrtf(s2A*(1.f/64.f) - mA*mA + 1e-5f);
        float rsB = rsqrtf(s2B*(1.f/64.f) - mB*mB + 1e-5f);

#pragma unroll
        for (int nch = 0; nch < 8; ++nch) {
            int f = nch*8 + 2*tig;
            float g0 = sg[f], g1 = sg[f+1], l0 = sbl[f], l1 = sbl[f+1];
            float2 oA, oB;
            oA.x = fmaf(g0, (hh[nch][0]-mA)*rsA, l0);
            oA.y = fmaf(g1, (hh[nch][1]-mA)*rsA, l1);
            oB.x = fmaf(g0, (hh[nch][2]-mB)*rsB, l0);
            oB.y = fmaf(g1, (hh[nch][3]-mB)*rsB, l1);
            *(float2*)(out + (size_t)rA*64 + f) = oA;
            *(float2*)(out + (size_t)rB*64 + f) = oB;
        }
    }
}

// ---------------- launch ----------------
extern "C" void kernel_launch(void* const* d_in, const int* in_sizes, int n_in,
                              void* d_out, int out_size)
{
    const float* x   = (const float*)d_in[0];
    const float* A   = (const float*)d_in[1];
    const float* AT  = (const float*)d_in[2];
    const float* Wq  = (const float*)d_in[3];
    const float* bq  = (const float*)d_in[4];
    const float* Wk  = (const float*)d_in[5];
    const float* bk  = (const float*)d_in[6];
    const float* Wks = (const float*)d_in[7];
    const float* bks = (const float*)d_in[8];
    const float* Wv  = (const float*)d_in[9];
    const float* bv  = (const float*)d_in[10];
    const float* Wvs = (const float*)d_in[11];
    const float* bvs = (const float*)d_in[12];
    const float* Wdi = (const float*)d_in[13];
    const float* Wdo = (const float*)d_in[14];
    const float* Wf1 = (const float*)d_in[15];
    const float* bf1 = (const float*)d_in[16];
    const float* Wf2 = (const float*)d_in[17];
    const float* bf2 = (const float*)d_in[18];
    const float* gln = (const float*)d_in[19];
    const float* bln = (const float*)d_in[20];
    float* out = (float*)d_out;

    cudaFuncSetAttribute(proj_kernel, cudaFuncAttributeMaxDynamicSharedMemorySize, 47360);
    cudaFuncSetAttribute(attn_kernel, cudaFuncAttributeMaxDynamicSharedMemorySize, 27136);
    cudaFuncSetAttribute(ffn_kernel,  cudaFuncAttributeMaxDynamicSharedMemorySize, 19712);

    bias_kernel<<<(KHn*NNn + 255)/256, 256>>>(A, AT, Wdi, Wdo);
    proj_kernel<<<488, 256, 47360>>>(x, Wq, bq, Wk, bk, Wks, bks, Wv, bv, Wvs, bvs);
    dim3 ag(BTn, KHn);
    attn_kernel<<<ag, ATH, 27136>>>();
    ffn_kernel<<<488, 256, 19712>>>(x, Wf1, bf1, Wf2, bf2, gln, bln, out);
}

// round 14
// speedup vs baseline: 2.7506x; 1.1119x over previous
#include <cuda_runtime.h>
#include <cuda_fp16.h>
#include <math.h>
#include <stdint.h>

#define Bn 16
#define Tn 12
#define Nn 325
#define Fn 64
#define KHn 4
#define Dn 16
#define KDn 3
#define BTn (Bn*Tn)            // 192
#define BTNn (BTn*Nn)          // 62400
#define NNn (Nn*Nn)            // 105625
#define QPAD 336               // padded node count (21*16)
#define BPAD 336
#define KSTRIDE 24             // halves per K row in smem
#define VSTRIDE 344            // halves per Vt row in smem
#define WSTRIDE 72             // halves per weight row in smem (bank-mult 4, conflict-free)
#define SCLOG2 0.36067376022224085f   // 0.25 * log2(e)
#define L2E    1.4426950408889634f

// ---------------- scratch (device globals; zero-initialized, no allocation) ----------------
__device__ float  g_q [KHn*BTNn*Dn + 256];
__device__ float  g_k [KHn*BTNn*Dn + 256];
__device__ float  g_ks[KHn*BTNn*Dn + 256];
__device__ float  g_v [KHn*BTNn*Dn + 256];
__device__ float  g_vs[KHn*BTNn*Dn + 256];
__device__ __half g_bias2[KHn*BPAD*BPAD];    // [h][q][k] fp16, PRE-SCALED by log2(e); pad zero
__device__ float  g_val[BTNn*Fn];

// ---------------- mma helper: m16n8k16 row.col f32 += f16*f16 ----------------
__device__ __forceinline__ void mma16816(float d[4],
    uint32_t a0, uint32_t a1, uint32_t a2, uint32_t a3,
    uint32_t b0, uint32_t b1)
{
    asm volatile(
        "mma.sync.aligned.m16n8k16.row.col.f32.f16.f16.f32 "
        "{%0,%1,%2,%3}, {%4,%5,%6,%7}, {%8,%9}, {%0,%1,%2,%3};"
        : "+f"(d[0]), "+f"(d[1]), "+f"(d[2]), "+f"(d[3])
        : "r"(a0), "r"(a1), "r"(a2), "r"(a3), "r"(b0), "r"(b1));
}
__device__ __forceinline__ uint32_t f2h2(float x, float y) {
    __half2 h = __floats2half2_rn(x, y);
    return *(uint32_t*)&h;
}
__device__ __forceinline__ uint32_t ex2h2(uint32_t e) {
    uint32_t p;
    asm("ex2.approx.f16x2 %0, %1;" : "=r"(p) : "r"(e));
    return p;
}
__device__ __forceinline__ float gelu_exact(float v) {
    return 0.5f*v*(1.f + erff(v*0.7071067811865476f));
}

// ---------------- kernel 1: graph-diffusion bias -> fp16*log2e padded [h][q][k] ----------------
__global__ void bias_kernel(const float* __restrict__ A, const float* __restrict__ AT,
                            const float* __restrict__ Wdi, const float* __restrict__ Wdo)
{
    int idx = blockIdx.x*blockDim.x + threadIdx.x;
    if (idx >= KHn*NNn) return;
    int h = idx / NNn, nm = idx - h*NNn;
    int n = nm / Nn, m = nm - n*Nn;
    float s = 0.f;
    if (h < 2) {
#pragma unroll
        for (int j = 0; j < KDn; ++j) s = fmaf(Wdi[(h*KDn+j)*NNn+nm], A[j*NNn+nm], s);
    } else {
#pragma unroll
        for (int j = 0; j < KDn; ++j) s = fmaf(Wdo[((h-2)*KDn+j)*NNn+nm], AT[j*NNn+nm], s);
    }
    g_bias2[((size_t)h*BPAD + n)*BPAD + m] = __float2half(s * L2E);
}

// ---------------- kernel 2: fused 5-way projection via tensor-core MMA ----------------
__global__ __launch_bounds__(256) void proj_kernel(
    const float* __restrict__ x,
    const float* __restrict__ Wq,  const float* __restrict__ bq,
    const float* __restrict__ Wk,  const float* __restrict__ bk,
    const float* __restrict__ Wks, const float* __restrict__ bks,
    const float* __restrict__ Wv,  const float* __restrict__ bv,
    const float* __restrict__ Wvs, const float* __restrict__ bvs)
{
    extern __shared__ char smraw[];
    __half* sW = (__half*)smraw;                  // 5 * 64*72 halves = 46080 B
    float* sbias = (float*)(smraw + 46080);       // 5 * 64 floats = 1280 B

    const float* Ws[5] = {Wq, Wk, Wks, Wv, Wvs};
    const float* bs[5] = {bq, bk, bks, bv, bvs};
    for (int i = threadIdx.x; i < 5*4096; i += 256) {
        int p = i >> 12, idx = i & 4095;
        int f = idx >> 6, c = idx & 63;
        sW[p*4608 + f*WSTRIDE + c] = __float2half(Ws[p][f*64 + c]);
    }
    for (int i = threadIdx.x; i < 5*64; i += 256)
        sbias[i] = bs[i >> 6][i & 63];
    __syncthreads();

    int warp = threadIdx.x >> 5, lane = threadIdx.x & 31;
    int gid = lane >> 2, tig = lane & 3;
    float* outp[5] = {g_q, g_k, g_ks, g_v, g_vs};

    int wglobal = blockIdx.x*8 + warp;
    for (int tile = wglobal; tile < 3900; tile += 244*8) {
        int r0 = tile*16;
        int rA = r0 + gid, rB = r0 + gid + 8;

        uint32_t a[4][4];
#pragma unroll
        for (int j = 0; j < 4; ++j) {
            float2 fA0 = *(const float2*)(x + (size_t)rA*64 + 16*j + 2*tig);
            float2 fB0 = *(const float2*)(x + (size_t)rB*64 + 16*j + 2*tig);
            float2 fA8 = *(const float2*)(x + (size_t)rA*64 + 16*j + 2*tig + 8);
            float2 fB8 = *(const float2*)(x + (size_t)rB*64 + 16*j + 2*tig + 8);
            a[j][0] = f2h2(fA0.x, fA0.y);
            a[j][1] = f2h2(fB0.x, fB0.y);
            a[j][2] = f2h2(fA8.x, fA8.y);
            a[j][3] = f2h2(fB8.x, fB8.y);
        }

#pragma unroll 1
        for (int p = 0; p < 5; ++p) {
            const __half* wp = sW + p*4608;
            float* o = outp[p];
#pragma unroll
            for (int nch = 0; nch < 8; ++nch) {
                float d[4] = {0.f, 0.f, 0.f, 0.f};
#pragma unroll
                for (int j = 0; j < 4; ++j) {
                    uint32_t b0 = *(const uint32_t*)(wp + (nch*8+gid)*WSTRIDE + 16*j + 2*tig);
                    uint32_t b1 = *(const uint32_t*)(wp + (nch*8+gid)*WSTRIDE + 16*j + 2*tig + 8);
                    mma16816(d, a[j][0], a[j][1], a[j][2], a[j][3], b0, b1);
                }
                int f = nch*8 + 2*tig;
                int hh = f >> 4, dd = f & 15;
                float bb0 = sbias[p*64 + f], bb1 = sbias[p*64 + f + 1];
                float2 rA2, rB2;
                rA2.x = d[0] + bb0;  rA2.y = d[1] + bb1;
                rB2.x = d[2] + bb0;  rB2.y = d[3] + bb1;
                *(float2*)(o + ((size_t)hh*BTNn + rA)*Dn + dd) = rA2;
                *(float2*)(o + ((size_t)hh*BTNn + rB)*Dn + dd) = rB2;
            }
        }
    }
}

// ---------------- kernel 3: attention via tensor-core mma + ex2.f16x2 softmax ----------------
#define ATH 352
__global__ __launch_bounds__(ATH, 3) void attn_kernel()
{
    extern __shared__ char smem_raw[];
    __half* sKs = (__half*)smem_raw;                  // [336][24] halves = 16128 B
    __half* sVt = (__half*)(smem_raw + 16128);        // [16][344] halves = 11008 B

    int bt = blockIdx.x, h = blockIdx.y;
    size_t base = ((size_t)h*BTNn + (size_t)bt*Nn)*Dn;
    const float* gk  = g_k  + base;
    const float* gv  = g_v  + base;
    const float* gq  = g_q  + base;
    const float* gks = g_ks + base;
    const float* gvs = g_vs + base;
    int tid = threadIdx.x;

    for (int i = tid; i < QPAD*Dn; i += ATH) {
        int key = i >> 4, d = i & 15;
        __half kh = __float2half(0.f), vh = __float2half(0.f);
        if (key < Nn) {
            kh = __float2half(gk[key*16 + d]);
            vh = __float2half(gv[key*16 + d]);
        }
        sKs[key*KSTRIDE + d] = kh;
        sVt[d*VSTRIDE + key] = vh;
    }
    __syncthreads();

    int warp = tid >> 5, lane = tid & 31;
    int gid = lane >> 2, tig = lane & 3;
    const __half* bias = g_bias2 + (size_t)h*BPAD*BPAD;

    for (int rb = warp; rb <= 20; rb += 11) {
        int q0 = rb*16;
        int qA = q0 + gid, qB = q0 + gid + 8;
        bool vA = qA < Nn, vB = qB < Nn;

        uint32_t qa0 = 0, qa1 = 0, qa2 = 0, qa3 = 0;
        if (vA) {
            float2 f0 = *(const float2*)(gq + qA*16 + 2*tig);
            float2 f2 = *(const float2*)(gq + qA*16 + 2*tig + 8);
            qa0 = f2h2(f0.x, f0.y);  qa2 = f2h2(f2.x, f2.y);
        }
        if (vB) {
            float2 f1 = *(const float2*)(gq + qB*16 + 2*tig);
            float2 f3 = *(const float2*)(gq + qB*16 + 2*tig + 8);
            qa1 = f2h2(f1.x, f1.y);  qa3 = f2h2(f3.x, f3.y);
        }

        float esv = 1.f;
        {
            int q = q0 + lane;
            if (lane < 16 && q < Nn) {
                float s = 0.f;
#pragma unroll
                for (int d = 0; d < 16; ++d) s = fmaf(gq[q*16+d], gks[q*16+d], s);
                esv = 1.f/(1.f + __expf(-s*0.25f));
            }
        }
        float esA = __shfl_sync(0xffffffffu, esv, gid);
        float esB = __shfl_sync(0xffffffffu, esv, gid + 8);

        float o0[4] = {0.f,0.f,0.f,0.f};
        float o1[4] = {0.f,0.f,0.f,0.f};
        float LA = 0.f, LB = 0.f;

#pragma unroll 1
        for (int kb = 0; kb < 21; ++kb) {
            int k0 = kb*16;
            uint32_t b0a = *(const uint32_t*)(sKs + (k0+gid)*KSTRIDE + 2*tig);
            uint32_t b1a = *(const uint32_t*)(sKs + (k0+gid)*KSTRIDE + 2*tig + 8);
            uint32_t b0b = *(const uint32_t*)(sKs + (k0+8+gid)*KSTRIDE + 2*tig);
            uint32_t b1b = *(const uint32_t*)(sKs + (k0+8+gid)*KSTRIDE + 2*tig + 8);
            float c0[4] = {0.f,0.f,0.f,0.f};
            float c1[4] = {0.f,0.f,0.f,0.f};
            mma16816(c0, qa0, qa1, qa2, qa3, b0a, b1a);
            mma16816(c1, qa0, qa1, qa2, qa3, b0b, b1b);

            // softmax numerators in log2 domain: p = 2^(s*0.25*log2e + bias*log2e)
            uint32_t pa0, pa1, pa2, pa3;
            {
                int kc = k0 + 2*tig;
                float2 bA2 = __half22float2(*(const __half2*)(bias + (size_t)qA*BPAD + kc));
                float2 bB2 = __half22float2(*(const __half2*)(bias + (size_t)qB*BPAD + kc));
                bool u0 = kc < Nn, u1 = (kc+1) < Nn;
                float eA0 = u0 ? fmaf(c0[0], SCLOG2, bA2.x) : -30.f;
                float eA1 = u1 ? fmaf(c0[1], SCLOG2, bA2.y) : -30.f;
                float eB0 = u0 ? fmaf(c0[2], SCLOG2, bB2.x) : -30.f;
                float eB1 = u1 ? fmaf(c0[3], SCLOG2, bB2.y) : -30.f;
                pa0 = ex2h2(f2h2(eA0, eA1));
                pa1 = ex2h2(f2h2(eB0, eB1));
                float2 pA = __half22float2(*(__half2*)&pa0);
                float2 pB = __half22float2(*(__half2*)&pa1);
                LA += pA.x + pA.y;  LB += pB.x + pB.y;
            }
            {
                int kc = k0 + 8 + 2*tig;
                float2 bA2 = __half22float2(*(const __half2*)(bias + (size_t)qA*BPAD + kc));
                float2 bB2 = __half22float2(*(const __half2*)(bias + (size_t)qB*BPAD + kc));
                bool u0 = kc < Nn, u1 = (kc+1) < Nn;
                float eA0 = u0 ? fmaf(c1[0], SCLOG2, bA2.x) : -30.f;
                float eA1 = u1 ? fmaf(c1[1], SCLOG2, bA2.y) : -30.f;
                float eB0 = u0 ? fmaf(c1[2], SCLOG2, bB2.x) : -30.f;
                float eB1 = u1 ? fmaf(c1[3], SCLOG2, bB2.y) : -30.f;
                pa2 = ex2h2(f2h2(eA0, eA1));
                pa3 = ex2h2(f2h2(eB0, eB1));
                float2 pA = __half22float2(*(__half2*)&pa2);
                float2 pB = __half22float2(*(__half2*)&pa3);
                LA += pA.x + pA.y;  LB += pB.x + pB.y;
            }

            uint32_t vb0 = *(const uint32_t*)(sVt + gid*VSTRIDE + k0 + 2*tig);
            uint32_t vb1 = *(const uint32_t*)(sVt + gid*VSTRIDE + k0 + 2*tig + 8);
            mma16816(o0, pa0, pa1, pa2, pa3, vb0, vb1);
            uint32_t vb2 = *(const uint32_t*)(sVt + (8+gid)*VSTRIDE + k0 + 2*tig);
            uint32_t vb3 = *(const uint32_t*)(sVt + (8+gid)*VSTRIDE + k0 + 2*tig + 8);
            mma16816(o1, pa0, pa1, pa2, pa3, vb2, vb3);
        }

        LA += __shfl_xor_sync(0xffffffffu, LA, 1);
        LA += __shfl_xor_sync(0xffffffffu, LA, 2);
        LB += __shfl_xor_sync(0xffffffffu, LB, 1);
        LB += __shfl_xor_sync(0xffffffffu, LB, 2);

        if (vA) {
            float inv = 1.f/(esA + LA);
            float* op = g_val + ((size_t)bt*Nn + qA)*Fn + h*16;
            float2 vs0 = *(const float2*)(gvs + qA*16 + 2*tig);
            float2 vs1 = *(const float2*)(gvs + qA*16 + 8 + 2*tig);
            float2 r0, r1;
            r0.x = fmaf(o0[0] - LA*vs0.x, inv, vs0.x);
            r0.y = fmaf(o0[1] - LA*vs0.y, inv, vs0.y);
            r1.x = fmaf(o1[0] - LA*vs1.x, inv, vs1.x);
            r1.y = fmaf(o1[1] - LA*vs1.y, inv, vs1.y);
            *(float2*)(op + 2*tig) = r0;
            *(float2*)(op + 8 + 2*tig) = r1;
        }
        if (vB) {
            float inv = 1.f/(esB + LB);
            float* op = g_val + ((size_t)bt*Nn + qB)*Fn + h*16;
            float2 vs0 = *(const float2*)(gvs + qB*16 + 2*tig);
            float2 vs1 = *(const float2*)(gvs + qB*16 + 8 + 2*tig);
            float2 r0, r1;
            r0.x = fmaf(o0[2] - LB*vs0.x, inv, vs0.x);
            r0.y = fmaf(o0[3] - LB*vs0.y, inv, vs0.y);
            r1.x = fmaf(o1[2] - LB*vs1.x, inv, vs1.x);
            r1.y = fmaf(o1[3] - LB*vs1.y, inv, vs1.y);
            *(float2*)(op + 2*tig) = r0;
            *(float2*)(op + 8 + 2*tig) = r1;
        }
    }
}

// ---------------- kernel 4: FFN via tensor-core MMA (gelu on fragments) + residual + LN ----------------
__global__ __launch_bounds__(256) void ffn_kernel(
    const float* __restrict__ x,
    const float* __restrict__ Wf1, const float* __restrict__ bf1,
    const float* __restrict__ Wf2, const float* __restrict__ bf2,
    const float* __restrict__ gln, const float* __restrict__ bln,
    float* __restrict__ out)
{
    extern __shared__ char smraw[];
    __half* sW1 = (__half*)smraw;                 // 64*72 halves = 9216 B
    __half* sW2 = (__half*)(smraw + 9216);        // 9216 B
    float* sb1 = (float*)(smraw + 18432);         // 64
    float* sb2 = sb1 + 64;
    float* sg  = sb1 + 128;
    float* sbl = sb1 + 192;

    for (int i = threadIdx.x; i < 4096; i += 256) {
        int f = i >> 6, c = i & 63;
        sW1[f*WSTRIDE + c] = __float2half(Wf1[i]);
        sW2[f*WSTRIDE + c] = __float2half(Wf2[i]);
    }
    if (threadIdx.x < 64) {
        sb1[threadIdx.x] = bf1[threadIdx.x];
        sb2[threadIdx.x] = bf2[threadIdx.x];
        sg [threadIdx.x] = gln[threadIdx.x];
        sbl[threadIdx.x] = bln[threadIdx.x];
    }
    __syncthreads();

    int warp = threadIdx.x >> 5, lane = threadIdx.x & 31;
    int gid = lane >> 2, tig = lane & 3;

    for (int tile = blockIdx.x*8 + warp; tile < 3900; tile += 244*8) {
        int rA = tile*16 + gid, rB = rA + 8;

        uint32_t a[4][4];
#pragma unroll
        for (int j = 0; j < 4; ++j) {
            float2 fA0 = *(const float2*)(g_val + (size_t)rA*64 + 16*j + 2*tig);
            float2 fB0 = *(const float2*)(g_val + (size_t)rB*64 + 16*j + 2*tig);
            float2 fA8 = *(const float2*)(g_val + (size_t)rA*64 + 16*j + 2*tig + 8);
            float2 fB8 = *(const float2*)(g_val + (size_t)rB*64 + 16*j + 2*tig + 8);
            a[j][0] = f2h2(fA0.x, fA0.y);
            a[j][1] = f2h2(fB0.x, fB0.y);
            a[j][2] = f2h2(fA8.x, fA8.y);
            a[j][3] = f2h2(fB8.x, fB8.y);
        }

        uint32_t pa[4][4];
#pragma unroll
        for (int j2 = 0; j2 < 4; ++j2) {
            float d0[4] = {0.f,0.f,0.f,0.f};
            float d1[4] = {0.f,0.f,0.f,0.f};
#pragma unroll
            for (int j = 0; j < 4; ++j) {
                uint32_t b0 = *(const uint32_t*)(sW1 + (16*j2+gid)*WSTRIDE + 16*j + 2*tig);
                uint32_t b1 = *(const uint32_t*)(sW1 + (16*j2+gid)*WSTRIDE + 16*j + 2*tig + 8);
                mma16816(d0, a[j][0], a[j][1], a[j][2], a[j][3], b0, b1);
                uint32_t c0 = *(const uint32_t*)(sW1 + (16*j2+8+gid)*WSTRIDE + 16*j + 2*tig);
                uint32_t c1 = *(const uint32_t*)(sW1 + (16*j2+8+gid)*WSTRIDE + 16*j + 2*tig + 8);
                mma16816(d1, a[j][0], a[j][1], a[j][2], a[j][3], c0, c1);
            }
            int fb = 16*j2 + 2*tig;
            float b00 = sb1[fb], b01 = sb1[fb+1], b08 = sb1[fb+8], b09 = sb1[fb+9];
            pa[j2][0] = f2h2(gelu_exact(d0[0]+b00), gelu_exact(d0[1]+b01));
            pa[j2][1] = f2h2(gelu_exact(d0[2]+b00), gelu_exact(d0[3]+b01));
            pa[j2][2] = f2h2(gelu_exact(d1[0]+b08), gelu_exact(d1[1]+b09));
            pa[j2][3] = f2h2(gelu_exact(d1[2]+b08), gelu_exact(d1[3]+b09));
        }

        float hh[8][4];
#pragma unroll
        for (int nch = 0; nch < 8; ++nch) {
            float d[4] = {0.f,0.f,0.f,0.f};
#pragma unroll
            for (int j = 0; j < 4; ++j) {
                uint32_t b0 = *(const uint32_t*)(sW2 + (nch*8+gid)*WSTRIDE + 16*j + 2*tig);
                uint32_t b1 = *(const uint32_t*)(sW2 + (nch*8+gid)*WSTRIDE + 16*j + 2*tig + 8);
                mma16816(d, pa[j][0], pa[j][1], pa[j][2], pa[j][3], b0, b1);
            }
            int f = nch*8 + 2*tig;
            float2 xA = *(const float2*)(x + (size_t)rA*64 + f);
            float2 xB = *(const float2*)(x + (size_t)rB*64 + f);
            hh[nch][0] = d[0] + sb2[f]   + xA.x;
            hh[nch][1] = d[1] + sb2[f+1] + xA.y;
            hh[nch][2] = d[2] + sb2[f]   + xB.x;
            hh[nch][3] = d[3] + sb2[f+1] + xB.y;
        }

        float s1A = 0.f, s2A = 0.f, s1B = 0.f, s2B = 0.f;
#pragma unroll
        for (int nch = 0; nch < 8; ++nch) {
            s1A += hh[nch][0] + hh[nch][1];
            s2A += hh[nch][0]*hh[nch][0] + hh[nch][1]*hh[nch][1];
            s1B += hh[nch][2] + hh[nch][3];
            s2B += hh[nch][2]*hh[nch][2] + hh[nch][3]*hh[nch][3];
        }
        s1A += __shfl_xor_sync(0xffffffffu, s1A, 1);
        s2A += __shfl_xor_sync(0xffffffffu, s2A, 1);
        s1B += __shfl_xor_sync(0xffffffffu, s1B, 1);
        s2B += __shfl_xor_sync(0xffffffffu, s2B, 1);
        s1A += __shfl_xor_sync(0xffffffffu, s1A, 2);
        s2A += __shfl_xor_sync(0xffffffffu, s2A, 2);
        s1B += __shfl_xor_sync(0xffffffffu, s1B, 2);
        s2B += __shfl_xor_sync(0xffffffffu, s2B, 2);

        float mA = s1A*(1.f/64.f), mB = s1B*(1.f/64.f);
        float rsA = rsqrtf(s2A*(1.f/64.f) - mA*mA + 1e-5f);
        float rsB = rsqrtf(s2B*(1.f/64.f) - mB*mB + 1e-5f);

#pragma unroll
        for (int nch = 0; nch < 8; ++nch) {
            int f = nch*8 + 2*tig;
            float g0 = sg[f], g1 = sg[f+1], l0 = sbl[f], l1 = sbl[f+1];
            float2 oA, oB;
            oA.x = fmaf(g0, (hh[nch][0]-mA)*rsA, l0);
            oA.y = fmaf(g1, (hh[nch][1]-mA)*rsA, l1);
            oB.x = fmaf(g0, (hh[nch][2]-mB)*rsB, l0);
            oB.y = fmaf(g1, (hh[nch][3]-mB)*rsB, l1);
            *(float2*)(out + (size_t)rA*64 + f) = oA;
            *(float2*)(out + (size_t)rB*64 + f) = oB;
        }
    }
}

// ---------------- launch ----------------
extern "C" void kernel_launch(void* const* d_in, const int* in_sizes, int n_in,
                              void* d_out, int out_size)
{
    const float* x   = (const float*)d_in[0];
    const float* A   = (const float*)d_in[1];
    const float* AT  = (const float*)d_in[2];
    const float* Wq  = (const float*)d_in[3];
    const float* bq  = (const float*)d_in[4];
    const float* Wk  = (const float*)d_in[5];
    const float* bk  = (const float*)d_in[6];
    const float* Wks = (const float*)d_in[7];
    const float* bks = (const float*)d_in[8];
    const float* Wv  = (const float*)d_in[9];
    const float* bv  = (const float*)d_in[10];
    const float* Wvs = (const float*)d_in[11];
    const float* bvs = (const float*)d_in[12];
    const float* Wdi = (const float*)d_in[13];
    const float* Wdo = (const float*)d_in[14];
    const float* Wf1 = (const float*)d_in[15];
    const float* bf1 = (const float*)d_in[16];
    const float* Wf2 = (const float*)d_in[17];
    const float* bf2 = (const float*)d_in[18];
    const float* gln = (const float*)d_in[19];
    const float* bln = (const float*)d_in[20];
    float* out = (float*)d_out;

    cudaFuncSetAttribute(proj_kernel, cudaFuncAttributeMaxDynamicSharedMemorySize, 47360);
    cudaFuncSetAttribute(attn_kernel, cudaFuncAttributeMaxDynamicSharedMemorySize, 27136);
    cudaFuncSetAttribute(ffn_kernel,  cudaFuncAttributeMaxDynamicSharedMemorySize, 19712);

    bias_kernel<<<(KHn*NNn + 255)/256, 256>>>(A, AT, Wdi, Wdo);
    proj_kernel<<<244, 256, 47360>>>(x, Wq, bq, Wk, bk, Wks, bks, Wv, bv, Wvs, bvs);
    dim3 ag(BTn, KHn);
    attn_kernel<<<ag, ATH, 27136>>>();
    ffn_kernel<<<244, 256, 19712>>>(x, Wf1, bf1, Wf2, bf2, gln, bln, out);
}

// round 15
// speedup vs baseline: 3.2557x; 1.1837x over previous
#include <cuda_runtime.h>
#include <cuda_fp16.h>
#include <math.h>
#include <stdint.h>

#define Bn 16
#define Tn 12
#define Nn 325
#define Fn 64
#define KHn 4
#define Dn 16
#define KDn 3
#define BTn (Bn*Tn)            // 192
#define BTNn (BTn*Nn)          // 62400
#define NNn (Nn*Nn)            // 105625
#define QPAD 336               // padded node count (21*16)
#define BPAD 336
#define KSTRIDE 24             // halves per K row in smem
#define VSTRIDE 344            // halves per Vt row in smem
#define WSTRIDE 72             // halves per weight row in smem (bank-mult 4, conflict-free)
#define SCLOG2 0.36067376022224085f   // 0.25 * log2(e)
#define L2E    1.4426950408889634f

// ---------------- scratch (device globals; zero-initialized, no allocation) ----------------
__device__ float  g_q [KHn*BTNn*Dn + 256];
__device__ float  g_k [KHn*BTNn*Dn + 256];
__device__ float  g_ks[KHn*BTNn*Dn + 256];
__device__ float  g_v [KHn*BTNn*Dn + 256];
__device__ float  g_vs[KHn*BTNn*Dn + 256];
__device__ __half g_bias2[KHn*BPAD*BPAD];    // [h][q][k] fp16, PRE-SCALED by log2(e); pad zero
__device__ float  g_val[BTNn*Fn];

// ---------------- mma helper: m16n8k16 row.col f32 += f16*f16 ----------------
__device__ __forceinline__ void mma16816(float d[4],
    uint32_t a0, uint32_t a1, uint32_t a2, uint32_t a3,
    uint32_t b0, uint32_t b1)
{
    asm volatile(
        "mma.sync.aligned.m16n8k16.row.col.f32.f16.f16.f32 "
        "{%0,%1,%2,%3}, {%4,%5,%6,%7}, {%8,%9}, {%0,%1,%2,%3};"
        : "+f"(d[0]), "+f"(d[1]), "+f"(d[2]), "+f"(d[3])
        : "r"(a0), "r"(a1), "r"(a2), "r"(a3), "r"(b0), "r"(b1));
}
__device__ __forceinline__ uint32_t f2h2(float x, float y) {
    __half2 h = __floats2half2_rn(x, y);
    return *(uint32_t*)&h;
}
__device__ __forceinline__ uint32_t ex2h2(uint32_t e) {
    uint32_t p;
    asm("ex2.approx.f16x2 %0, %1;" : "=r"(p) : "r"(e));
    return p;
}
__device__ __forceinline__ float gelu_exact(float v) {
    return 0.5f*v*(1.f + erff(v*0.7071067811865476f));
}

// ---------------- kernel 1: graph-diffusion bias -> fp16*log2e padded [h][q][k] ----------------
__global__ void bias_kernel(const float* __restrict__ A, const float* __restrict__ AT,
                            const float* __restrict__ Wdi, const float* __restrict__ Wdo)
{
    int idx = blockIdx.x*blockDim.x + threadIdx.x;
    if (idx >= KHn*NNn) return;
    int h = idx / NNn, nm = idx - h*NNn;
    int n = nm / Nn, m = nm - n*Nn;
    float s = 0.f;
    if (h < 2) {
#pragma unroll
        for (int j = 0; j < KDn; ++j) s = fmaf(Wdi[(h*KDn+j)*NNn+nm], A[j*NNn+nm], s);
    } else {
#pragma unroll
        for (int j = 0; j < KDn; ++j) s = fmaf(Wdo[((h-2)*KDn+j)*NNn+nm], AT[j*NNn+nm], s);
    }
    g_bias2[((size_t)h*BPAD + n)*BPAD + m] = __float2half(s * L2E);
}

// ---------------- kernel 2: fused 5-way projection via tensor-core MMA (512 thr) ----------------
__global__ __launch_bounds__(512, 2) void proj_kernel(
    const float* __restrict__ x,
    const float* __restrict__ Wq,  const float* __restrict__ bq,
    const float* __restrict__ Wk,  const float* __restrict__ bk,
    const float* __restrict__ Wks, const float* __restrict__ bks,
    const float* __restrict__ Wv,  const float* __restrict__ bv,
    const float* __restrict__ Wvs, const float* __restrict__ bvs)
{
    extern __shared__ char smraw[];
    __half* sW = (__half*)smraw;                  // 5 * 64*72 halves = 46080 B
    float* sbias = (float*)(smraw + 46080);       // 5 * 64 floats = 1280 B

    const float* Ws[5] = {Wq, Wk, Wks, Wv, Wvs};
    const float* bs[5] = {bq, bk, bks, bv, bvs};
    for (int i = threadIdx.x; i < 5*4096; i += 512) {
        int p = i >> 12, idx = i & 4095;
        int f = idx >> 6, c = idx & 63;
        sW[p*4608 + f*WSTRIDE + c] = __float2half(Ws[p][f*64 + c]);
    }
    for (int i = threadIdx.x; i < 5*64; i += 512)
        sbias[i] = bs[i >> 6][i & 63];
    __syncthreads();

    int warp = threadIdx.x >> 5, lane = threadIdx.x & 31;
    int gid = lane >> 2, tig = lane & 3;
    float* outp[5] = {g_q, g_k, g_ks, g_v, g_vs};

    int tile = blockIdx.x*16 + warp;
    if (tile >= 3900) return;
    {
        int r0 = tile*16;
        int rA = r0 + gid, rB = r0 + gid + 8;

        uint32_t a[4][4];
#pragma unroll
        for (int j = 0; j < 4; ++j) {
            float2 fA0 = *(const float2*)(x + (size_t)rA*64 + 16*j + 2*tig);
            float2 fB0 = *(const float2*)(x + (size_t)rB*64 + 16*j + 2*tig);
            float2 fA8 = *(const float2*)(x + (size_t)rA*64 + 16*j + 2*tig + 8);
            float2 fB8 = *(const float2*)(x + (size_t)rB*64 + 16*j + 2*tig + 8);
            a[j][0] = f2h2(fA0.x, fA0.y);
            a[j][1] = f2h2(fB0.x, fB0.y);
            a[j][2] = f2h2(fA8.x, fA8.y);
            a[j][3] = f2h2(fB8.x, fB8.y);
        }

#pragma unroll 1
        for (int p = 0; p < 5; ++p) {
            const __half* wp = sW + p*4608;
            float* o = outp[p];
#pragma unroll
            for (int nch = 0; nch < 8; ++nch) {
                float d[4] = {0.f, 0.f, 0.f, 0.f};
#pragma unroll
                for (int j = 0; j < 4; ++j) {
                    uint32_t b0 = *(const uint32_t*)(wp + (nch*8+gid)*WSTRIDE + 16*j + 2*tig);
                    uint32_t b1 = *(const uint32_t*)(wp + (nch*8+gid)*WSTRIDE + 16*j + 2*tig + 8);
                    mma16816(d, a[j][0], a[j][1], a[j][2], a[j][3], b0, b1);
                }
                int f = nch*8 + 2*tig;
                int hh = f >> 4, dd = f & 15;
                float bb0 = sbias[p*64 + f], bb1 = sbias[p*64 + f + 1];
                float2 rA2, rB2;
                rA2.x = d[0] + bb0;  rA2.y = d[1] + bb1;
                rB2.x = d[2] + bb0;  rB2.y = d[3] + bb1;
                *(float2*)(o + ((size_t)hh*BTNn + rA)*Dn + dd) = rA2;
                *(float2*)(o + ((size_t)hh*BTNn + rB)*Dn + dd) = rB2;
            }
        }
    }
}

// ---------------- kernel 3: attention via tensor-core mma + ex2.f16x2 softmax ----------------
#define ATH 352
__global__ __launch_bounds__(ATH, 3) void attn_kernel()
{
    extern __shared__ char smem_raw[];
    __half* sKs = (__half*)smem_raw;                  // [336][24] halves = 16128 B
    __half* sVt = (__half*)(smem_raw + 16128);        // [16][344] halves = 11008 B

    int bt = blockIdx.x, h = blockIdx.y;
    size_t base = ((size_t)h*BTNn + (size_t)bt*Nn)*Dn;
    const float* gk  = g_k  + base;
    const float* gv  = g_v  + base;
    const float* gq  = g_q  + base;
    const float* gks = g_ks + base;
    const float* gvs = g_vs + base;
    int tid = threadIdx.x;

    // vectorized staging: float4 loads; K packed half2, V transposed scalar
    for (int i = tid; i < QPAD*4; i += ATH) {
        int key = i >> 2, dc = i & 3;
        float4 kv = make_float4(0.f,0.f,0.f,0.f);
        float4 vv = make_float4(0.f,0.f,0.f,0.f);
        if (key < Nn) {
            kv = *(const float4*)(gk + key*16 + dc*4);
            vv = *(const float4*)(gv + key*16 + dc*4);
        }
        *(uint32_t*)(sKs + key*KSTRIDE + dc*4)     = f2h2(kv.x, kv.y);
        *(uint32_t*)(sKs + key*KSTRIDE + dc*4 + 2) = f2h2(kv.z, kv.w);
        sVt[(dc*4+0)*VSTRIDE + key] = __float2half(vv.x);
        sVt[(dc*4+1)*VSTRIDE + key] = __float2half(vv.y);
        sVt[(dc*4+2)*VSTRIDE + key] = __float2half(vv.z);
        sVt[(dc*4+3)*VSTRIDE + key] = __float2half(vv.w);
    }
    __syncthreads();

    int warp = tid >> 5, lane = tid & 31;
    int gid = lane >> 2, tig = lane & 3;
    const __half* bias = g_bias2 + (size_t)h*BPAD*BPAD;

    for (int rb = warp; rb <= 20; rb += 11) {
        int q0 = rb*16;
        int qA = q0 + gid, qB = q0 + gid + 8;
        bool vA = qA < Nn, vB = qB < Nn;

        uint32_t qa0 = 0, qa1 = 0, qa2 = 0, qa3 = 0;
        if (vA) {
            float2 f0 = *(const float2*)(gq + qA*16 + 2*tig);
            float2 f2 = *(const float2*)(gq + qA*16 + 2*tig + 8);
            qa0 = f2h2(f0.x, f0.y);  qa2 = f2h2(f2.x, f2.y);
        }
        if (vB) {
            float2 f1 = *(const float2*)(gq + qB*16 + 2*tig);
            float2 f3 = *(const float2*)(gq + qB*16 + 2*tig + 8);
            qa1 = f2h2(f1.x, f1.y);  qa3 = f2h2(f3.x, f3.y);
        }

        float esv = 1.f;
        {
            int q = q0 + lane;
            if (lane < 16 && q < Nn) {
                float s = 0.f;
#pragma unroll
                for (int d = 0; d < 16; ++d) s = fmaf(gq[q*16+d], gks[q*16+d], s);
                esv = 1.f/(1.f + __expf(-s*0.25f));
            }
        }
        float esA = __shfl_sync(0xffffffffu, esv, gid);
        float esB = __shfl_sync(0xffffffffu, esv, gid + 8);

        float o0[4] = {0.f,0.f,0.f,0.f};
        float o1[4] = {0.f,0.f,0.f,0.f};
        float LA = 0.f, LB = 0.f;

#pragma unroll 1
        for (int kb = 0; kb < 21; ++kb) {
            int k0 = kb*16;
            uint32_t b0a = *(const uint32_t*)(sKs + (k0+gid)*KSTRIDE + 2*tig);
            uint32_t b1a = *(const uint32_t*)(sKs + (k0+gid)*KSTRIDE + 2*tig + 8);
            uint32_t b0b = *(const uint32_t*)(sKs + (k0+8+gid)*KSTRIDE + 2*tig);
            uint32_t b1b = *(const uint32_t*)(sKs + (k0+8+gid)*KSTRIDE + 2*tig + 8);
            float c0[4] = {0.f,0.f,0.f,0.f};
            float c1[4] = {0.f,0.f,0.f,0.f};
            mma16816(c0, qa0, qa1, qa2, qa3, b0a, b1a);
            mma16816(c1, qa0, qa1, qa2, qa3, b0b, b1b);

            uint32_t pa0, pa1, pa2, pa3;
            {
                int kc = k0 + 2*tig;
                float2 bA2 = __half22float2(*(const __half2*)(bias + (size_t)qA*BPAD + kc));
                float2 bB2 = __half22float2(*(const __half2*)(bias + (size_t)qB*BPAD + kc));
                bool u0 = kc < Nn, u1 = (kc+1) < Nn;
                float eA0 = u0 ? fmaf(c0[0], SCLOG2, bA2.x) : -30.f;
                float eA1 = u1 ? fmaf(c0[1], SCLOG2, bA2.y) : -30.f;
                float eB0 = u0 ? fmaf(c0[2], SCLOG2, bB2.x) : -30.f;
                float eB1 = u1 ? fmaf(c0[3], SCLOG2, bB2.y) : -30.f;
                pa0 = ex2h2(f2h2(eA0, eA1));
                pa1 = ex2h2(f2h2(eB0, eB1));
                float2 pA = __half22float2(*(__half2*)&pa0);
                float2 pB = __half22float2(*(__half2*)&pa1);
                LA += pA.x + pA.y;  LB += pB.x + pB.y;
            }
            {
                int kc = k0 + 8 + 2*tig;
                float2 bA2 = __half22float2(*(const __half2*)(bias + (size_t)qA*BPAD + kc));
                float2 bB2 = __half22float2(*(const __half2*)(bias + (size_t)qB*BPAD + kc));
                bool u0 = kc < Nn, u1 = (kc+1) < Nn;
                float eA0 = u0 ? fmaf(c1[0], SCLOG2, bA2.x) : -30.f;
                float eA1 = u1 ? fmaf(c1[1], SCLOG2, bA2.y) : -30.f;
                float eB0 = u0 ? fmaf(c1[2], SCLOG2, bB2.x) : -30.f;
                float eB1 = u1 ? fmaf(c1[3], SCLOG2, bB2.y) : -30.f;
                pa2 = ex2h2(f2h2(eA0, eA1));
                pa3 = ex2h2(f2h2(eB0, eB1));
                float2 pA = __half22float2(*(__half2*)&pa2);
                float2 pB = __half22float2(*(__half2*)&pa3);
                LA += pA.x + pA.y;  LB += pB.x + pB.y;
            }

            uint32_t vb0 = *(const uint32_t*)(sVt + gid*VSTRIDE + k0 + 2*tig);
            uint32_t vb1 = *(const uint32_t*)(sVt + gid*VSTRIDE + k0 + 2*tig + 8);
            mma16816(o0, pa0, pa1, pa2, pa3, vb0, vb1);
            uint32_t vb2 = *(const uint32_t*)(sVt + (8+gid)*VSTRIDE + k0 + 2*tig);
            uint32_t vb3 = *(const uint32_t*)(sVt + (8+gid)*VSTRIDE + k0 + 2*tig + 8);
            mma16816(o1, pa0, pa1, pa2, pa3, vb2, vb3);
        }

        LA += __shfl_xor_sync(0xffffffffu, LA, 1);
        LA += __shfl_xor_sync(0xffffffffu, LA, 2);
        LB += __shfl_xor_sync(0xffffffffu, LB, 1);
        LB += __shfl_xor_sync(0xffffffffu, LB, 2);

        if (vA) {
            float inv = 1.f/(esA + LA);
            float* op = g_val + ((size_t)bt*Nn + qA)*Fn + h*16;
            float2 vs0 = *(const float2*)(gvs + qA*16 + 2*tig);
            float2 vs1 = *(const float2*)(gvs + qA*16 + 8 + 2*tig);
            float2 r0, r1;
            r0.x = fmaf(o0[0] - LA*vs0.x, inv, vs0.x);
            r0.y = fmaf(o0[1] - LA*vs0.y, inv, vs0.y);
            r1.x = fmaf(o1[0] - LA*vs1.x, inv, vs1.x);
            r1.y = fmaf(o1[1] - LA*vs1.y, inv, vs1.y);
            *(float2*)(op + 2*tig) = r0;
            *(float2*)(op + 8 + 2*tig) = r1;
        }
        if (vB) {
            float inv = 1.f/(esB + LB);
            float* op = g_val + ((size_t)bt*Nn + qB)*Fn + h*16;
            float2 vs0 = *(const float2*)(gvs + qB*16 + 2*tig);
            float2 vs1 = *(const float2*)(gvs + qB*16 + 8 + 2*tig);
            float2 r0, r1;
            r0.x = fmaf(o0[2] - LB*vs0.x, inv, vs0.x);
            r0.y = fmaf(o0[3] - LB*vs0.y, inv, vs0.y);
            r1.x = fmaf(o1[2] - LB*vs1.x, inv, vs1.x);
            r1.y = fmaf(o1[3] - LB*vs1.y, inv, vs1.y);
            *(float2*)(op + 2*tig) = r0;
            *(float2*)(op + 8 + 2*tig) = r1;
        }
    }
}

// ---------------- kernel 4: FFN via tensor-core MMA (512 thr) ----------------
__global__ __launch_bounds__(512, 2) void ffn_kernel(
    const float* __restrict__ x,
    const float* __restrict__ Wf1, const float* __restrict__ bf1,
    const float* __restrict__ Wf2, const float* __restrict__ bf2,
    const float* __restrict__ gln, const float* __restrict__ bln,
    float* __restrict__ out)
{
    extern __shared__ char smraw[];
    __half* sW1 = (__half*)smraw;                 // 64*72 halves = 9216 B
    __half* sW2 = (__half*)(smraw + 9216);        // 9216 B
    float* sb1 = (float*)(smraw + 18432);         // 64
    float* sb2 = sb1 + 64;
    float* sg  = sb1 + 128;
    float* sbl = sb1 + 192;

    for (int i = threadIdx.x; i < 4096; i += 512) {
        int f = i >> 6, c = i & 63;
        sW1[f*WSTRIDE + c] = __float2half(Wf1[i]);
        sW2[f*WSTRIDE + c] = __float2half(Wf2[i]);
    }
    if (threadIdx.x < 64) {
        sb1[threadIdx.x] = bf1[threadIdx.x];
        sb2[threadIdx.x] = bf2[threadIdx.x];
        sg [threadIdx.x] = gln[threadIdx.x];
        sbl[threadIdx.x] = bln[threadIdx.x];
    }
    __syncthreads();

    int warp = threadIdx.x >> 5, lane = threadIdx.x & 31;
    int gid = lane >> 2, tig = lane & 3;

    int tile = blockIdx.x*16 + warp;
    if (tile >= 3900) return;
    {
        int rA = tile*16 + gid, rB = rA + 8;

        uint32_t a[4][4];
#pragma unroll
        for (int j = 0; j < 4; ++j) {
            float2 fA0 = *(const float2*)(g_val + (size_t)rA*64 + 16*j + 2*tig);
            float2 fB0 = *(const float2*)(g_val + (size_t)rB*64 + 16*j + 2*tig);
            float2 fA8 = *(const float2*)(g_val + (size_t)rA*64 + 16*j + 2*tig + 8);
            float2 fB8 = *(const float2*)(g_val + (size_t)rB*64 + 16*j + 2*tig + 8);
            a[j][0] = f2h2(fA0.x, fA0.y);
            a[j][1] = f2h2(fB0.x, fB0.y);
            a[j][2] = f2h2(fA8.x, fA8.y);
            a[j][3] = f2h2(fB8.x, fB8.y);
        }

        uint32_t pa[4][4];
#pragma unroll
        for (int j2 = 0; j2 < 4; ++j2) {
            float d0[4] = {0.f,0.f,0.f,0.f};
            float d1[4] = {0.f,0.f,0.f,0.f};
#pragma unroll
            for (int j = 0; j < 4; ++j) {
                uint32_t b0 = *(const uint32_t*)(sW1 + (16*j2+gid)*WSTRIDE + 16*j + 2*tig);
                uint32_t b1 = *(const uint32_t*)(sW1 + (16*j2+gid)*WSTRIDE + 16*j + 2*tig + 8);
                mma16816(d0, a[j][0], a[j][1], a[j][2], a[j][3], b0, b1);
                uint32_t c0 = *(const uint32_t*)(sW1 + (16*j2+8+gid)*WSTRIDE + 16*j + 2*tig);
                uint32_t c1 = *(const uint32_t*)(sW1 + (16*j2+8+gid)*WSTRIDE + 16*j + 2*tig + 8);
                mma16816(d1, a[j][0], a[j][1], a[j][2], a[j][3], c0, c1);
            }
            int fb = 16*j2 + 2*tig;
            float b00 = sb1[fb], b01 = sb1[fb+1], b08 = sb1[fb+8], b09 = sb1[fb+9];
            pa[j2][0] = f2h2(gelu_exact(d0[0]+b00), gelu_exact(d0[1]+b01));
            pa[j2][1] = f2h2(gelu_exact(d0[2]+b00), gelu_exact(d0[3]+b01));
            pa[j2][2] = f2h2(gelu_exact(d1[0]+b08), gelu_exact(d1[1]+b09));
            pa[j2][3] = f2h2(gelu_exact(d1[2]+b08), gelu_exact(d1[3]+b09));
        }

        float hh[8][4];
#pragma unroll
        for (int nch = 0; nch < 8; ++nch) {
            float d[4] = {0.f,0.f,0.f,0.f};
#pragma unroll
            for (int j = 0; j < 4; ++j) {
                uint32_t b0 = *(const uint32_t*)(sW2 + (nch*8+gid)*WSTRIDE + 16*j + 2*tig);
                uint32_t b1 = *(const uint32_t*)(sW2 + (nch*8+gid)*WSTRIDE + 16*j + 2*tig + 8);
                mma16816(d, pa[j][0], pa[j][1], pa[j][2], pa[j][3], b0, b1);
            }
            int f = nch*8 + 2*tig;
            float2 xA = *(const float2*)(x + (size_t)rA*64 + f);
            float2 xB = *(const float2*)(x + (size_t)rB*64 + f);
            hh[nch][0] = d[0] + sb2[f]   + xA.x;
            hh[nch][1] = d[1] + sb2[f+1] + xA.y;
            hh[nch][2] = d[2] + sb2[f]   + xB.x;
            hh[nch][3] = d[3] + sb2[f+1] + xB.y;
        }

        float s1A = 0.f, s2A = 0.f, s1B = 0.f, s2B = 0.f;
#pragma unroll
        for (int nch = 0; nch < 8; ++nch) {
            s1A += hh[nch][0] + hh[nch][1];
            s2A += hh[nch][0]*hh[nch][0] + hh[nch][1]*hh[nch][1];
            s1B += hh[nch][2] + hh[nch][3];
            s2B += hh[nch][2]*hh[nch][2] + hh[nch][3]*hh[nch][3];
        }
        s1A += __shfl_xor_sync(0xffffffffu, s1A, 1);
        s2A += __shfl_xor_sync(0xffffffffu, s2A, 1);
        s1B += __shfl_xor_sync(0xffffffffu, s1B, 1);
        s2B += __shfl_xor_sync(0xffffffffu, s2B, 1);
        s1A += __shfl_xor_sync(0xffffffffu, s1A, 2);
        s2A += __shfl_xor_sync(0xffffffffu, s2A, 2);
        s1B += __shfl_xor_sync(0xffffffffu, s1B, 2);
        s2B += __shfl_xor_sync(0xffffffffu, s2B, 2);

        float mA = s1A*(1.f/64.f), mB = s1B*(1.f/64.f);
        float rsA = rsqrtf(s2A*(1.f/64.f) - mA*mA + 1e-5f);
        float rsB = rsqrtf(s2B*(1.f/64.f) - mB*mB + 1e-5f);

#pragma unroll
        for (int nch = 0; nch < 8; ++nch) {
            int f = nch*8 + 2*tig;
            float g0 = sg[f], g1 = sg[f+1], l0 = sbl[f], l1 = sbl[f+1];
            float2 oA, oB;
            oA.x = fmaf(g0, (hh[nch][0]-mA)*rsA, l0);
            oA.y = fmaf(g1, (hh[nch][1]-mA)*rsA, l1);
            oB.x = fmaf(g0, (hh[nch][2]-mB)*rsB, l0);
            oB.y = fmaf(g1, (hh[nch][3]-mB)*rsB, l1);
            *(float2*)(out + (size_t)rA*64 + f) = oA;
            *(float2*)(out + (size_t)rB*64 + f) = oB;
        }
    }
}

// ---------------- launch ----------------
extern "C" void kernel_launch(void* const* d_in, const int* in_sizes, int n_in,
                              void* d_out, int out_size)
{
    const float* x   = (const float*)d_in[0];
    const float* A   = (const float*)d_in[1];
    const float* AT  = (const float*)d_in[2];
    const float* Wq  = (const float*)d_in[3];
    const float* bq  = (const float*)d_in[4];
    const float* Wk  = (const float*)d_in[5];
    const float* bk  = (const float*)d_in[6];
    const float* Wks = (const float*)d_in[7];
    const float* bks = (const float*)d_in[8];
    const float* Wv  = (const float*)d_in[9];
    const float* bv  = (const float*)d_in[10];
    const float* Wvs = (const float*)d_in[11];
    const float* bvs = (const float*)d_in[12];
    const float* Wdi = (const float*)d_in[13];
    const float* Wdo = (const float*)d_in[14];
    const float* Wf1 = (const float*)d_in[15];
    const float* bf1 = (const float*)d_in[16];
    const float* Wf2 = (const float*)d_in[17];
    const float* bf2 = (const float*)d_in[18];
    const float* gln = (const float*)d_in[19];
    const float* bln = (const float*)d_in[20];
    float* out = (float*)d_out;

    cudaFuncSetAttribute(proj_kernel, cudaFuncAttributeMaxDynamicSharedMemorySize, 47360);
    cudaFuncSetAttribute(attn_kernel, cudaFuncAttributeMaxDynamicSharedMemorySize, 27136);
    cudaFuncSetAttribute(ffn_kernel,  cudaFuncAttributeMaxDynamicSharedMemorySize, 19712);

    bias_kernel<<<(KHn*NNn + 255)/256, 256>>>(A, AT, Wdi, Wdo);
    proj_kernel<<<244, 512, 47360>>>(x, Wq, bq, Wk, bk, Wks, bks, Wv, bv, Wvs, bvs);
    dim3 ag(BTn, KHn);
    attn_kernel<<<ag, ATH, 27136>>>();
    ffn_kernel<<<244, 512, 19712>>>(x, Wf1, bf1, Wf2, bf2, gln, bln, out);
}

// round 16
// speedup vs baseline: 3.3104x; 1.0168x over previous
#include <cuda_runtime.h>
#include <cuda_fp16.h>
#include <math.h>
#include <stdint.h>

#define Bn 16
#define Tn 12
#define Nn 325
#define Fn 64
#define KHn 4
#define Dn 16
#define KDn 3
#define BTn (Bn*Tn)            // 192
#define BTNn (BTn*Nn)          // 62400
#define NNn (Nn*Nn)            // 105625
#define QPAD 336               // padded node count (21*16)
#define BPAD 336
#define KSTRIDE 24             // halves per K row in smem
#define VSTRIDE 344            // halves per Vt row in smem
#define WSTRIDE 72             // halves per weight row in smem (bank-mult 4, conflict-free)
#define SCLOG2 0.36067376022224085f   // 0.25 * log2(e)
#define L2E    1.4426950408889634f

// ---------------- scratch (device globals; zero-initialized, no allocation) ----------------
__device__ float  g_q [KHn*BTNn*Dn + 256];
__device__ __half g_kh[KHn*BTNn*Dn + 256];    // fp16 (consumed only via fp16 MMA)
__device__ float  g_ks[KHn*BTNn*Dn + 256];
__device__ __half g_vh[KHn*BTNn*Dn + 256];    // fp16
__device__ float  g_vs[KHn*BTNn*Dn + 256];
__device__ __half g_bias2[KHn*BPAD*BPAD];     // [h][q][k] fp16, PRE-SCALED by log2(e)
__device__ __half g_valh[BTNn*Fn + 256];      // fp16 (consumed only via fp16 MMA)

// ---------------- mma helper: m16n8k16 row.col f32 += f16*f16 ----------------
__device__ __forceinline__ void mma16816(float d[4],
    uint32_t a0, uint32_t a1, uint32_t a2, uint32_t a3,
    uint32_t b0, uint32_t b1)
{
    asm volatile(
        "mma.sync.aligned.m16n8k16.row.col.f32.f16.f16.f32 "
        "{%0,%1,%2,%3}, {%4,%5,%6,%7}, {%8,%9}, {%0,%1,%2,%3};"
        : "+f"(d[0]), "+f"(d[1]), "+f"(d[2]), "+f"(d[3])
        : "r"(a0), "r"(a1), "r"(a2), "r"(a3), "r"(b0), "r"(b1));
}
__device__ __forceinline__ uint32_t f2h2(float x, float y) {
    __half2 h = __floats2half2_rn(x, y);
    return *(uint32_t*)&h;
}
__device__ __forceinline__ uint32_t ex2h2(uint32_t e) {
    uint32_t p;
    asm("ex2.approx.f16x2 %0, %1;" : "=r"(p) : "r"(e));
    return p;
}
__device__ __forceinline__ float gelu_exact(float v) {
    return 0.5f*v*(1.f + erff(v*0.7071067811865476f));
}

// ---------------- kernel 1: graph-diffusion bias -> fp16*log2e padded [h][q][k] ----------------
__global__ void bias_kernel(const float* __restrict__ A, const float* __restrict__ AT,
                            const float* __restrict__ Wdi, const float* __restrict__ Wdo)
{
    int idx = blockIdx.x*blockDim.x + threadIdx.x;
    if (idx >= KHn*NNn) return;
    int h = idx / NNn, nm = idx - h*NNn;
    int n = nm / Nn, m = nm - n*Nn;
    float s = 0.f;
    if (h < 2) {
#pragma unroll
        for (int j = 0; j < KDn; ++j) s = fmaf(Wdi[(h*KDn+j)*NNn+nm], A[j*NNn+nm], s);
    } else {
#pragma unroll
        for (int j = 0; j < KDn; ++j) s = fmaf(Wdo[((h-2)*KDn+j)*NNn+nm], AT[j*NNn+nm], s);
    }
    g_bias2[((size_t)h*BPAD + n)*BPAD + m] = __float2half(s * L2E);
}

// ---------------- kernel 2: fused 5-way projection via tensor-core MMA (512 thr) ----------------
__global__ __launch_bounds__(512, 2) void proj_kernel(
    const float* __restrict__ x,
    const float* __restrict__ Wq,  const float* __restrict__ bq,
    const float* __restrict__ Wk,  const float* __restrict__ bk,
    const float* __restrict__ Wks, const float* __restrict__ bks,
    const float* __restrict__ Wv,  const float* __restrict__ bv,
    const float* __restrict__ Wvs, const float* __restrict__ bvs)
{
    extern __shared__ char smraw[];
    __half* sW = (__half*)smraw;                  // 5 * 64*72 halves = 46080 B
    float* sbias = (float*)(smraw + 46080);       // 5 * 64 floats = 1280 B

    const float* Ws[5] = {Wq, Wk, Wks, Wv, Wvs};
    const float* bs[5] = {bq, bk, bks, bv, bvs};
    for (int i = threadIdx.x; i < 5*4096; i += 512) {
        int p = i >> 12, idx = i & 4095;
        int f = idx >> 6, c = idx & 63;
        sW[p*4608 + f*WSTRIDE + c] = __float2half(Ws[p][f*64 + c]);
    }
    for (int i = threadIdx.x; i < 5*64; i += 512)
        sbias[i] = bs[i >> 6][i & 63];
    __syncthreads();

    int warp = threadIdx.x >> 5, lane = threadIdx.x & 31;
    int gid = lane >> 2, tig = lane & 3;
    float* outpF[5] = {g_q, 0, g_ks, 0, g_vs};

    int tile = blockIdx.x*16 + warp;
    if (tile >= 3900) return;
    {
        int r0 = tile*16;
        int rA = r0 + gid, rB = r0 + gid + 8;

        uint32_t a[4][4];
#pragma unroll
        for (int j = 0; j < 4; ++j) {
            float2 fA0 = *(const float2*)(x + (size_t)rA*64 + 16*j + 2*tig);
            float2 fB0 = *(const float2*)(x + (size_t)rB*64 + 16*j + 2*tig);
            float2 fA8 = *(const float2*)(x + (size_t)rA*64 + 16*j + 2*tig + 8);
            float2 fB8 = *(const float2*)(x + (size_t)rB*64 + 16*j + 2*tig + 8);
            a[j][0] = f2h2(fA0.x, fA0.y);
            a[j][1] = f2h2(fB0.x, fB0.y);
            a[j][2] = f2h2(fA8.x, fA8.y);
            a[j][3] = f2h2(fB8.x, fB8.y);
        }

#pragma unroll 1
        for (int p = 0; p < 5; ++p) {
            const __half* wp = sW + p*4608;
#pragma unroll
            for (int nch = 0; nch < 8; ++nch) {
                float d[4] = {0.f, 0.f, 0.f, 0.f};
#pragma unroll
                for (int j = 0; j < 4; ++j) {
                    uint32_t b0 = *(const uint32_t*)(wp + (nch*8+gid)*WSTRIDE + 16*j + 2*tig);
                    uint32_t b1 = *(const uint32_t*)(wp + (nch*8+gid)*WSTRIDE + 16*j + 2*tig + 8);
                    mma16816(d, a[j][0], a[j][1], a[j][2], a[j][3], b0, b1);
                }
                int f = nch*8 + 2*tig;
                int hh = f >> 4, dd = f & 15;
                float bb0 = sbias[p*64 + f], bb1 = sbias[p*64 + f + 1];
                if (p == 1 || p == 3) {
                    __half* oh = (p == 1) ? g_kh : g_vh;
                    *(uint32_t*)(oh + ((size_t)hh*BTNn + rA)*Dn + dd) = f2h2(d[0]+bb0, d[1]+bb1);
                    *(uint32_t*)(oh + ((size_t)hh*BTNn + rB)*Dn + dd) = f2h2(d[2]+bb0, d[3]+bb1);
                } else {
                    float* o = outpF[p];
                    float2 rA2, rB2;
                    rA2.x = d[0] + bb0;  rA2.y = d[1] + bb1;
                    rB2.x = d[2] + bb0;  rB2.y = d[3] + bb1;
                    *(float2*)(o + ((size_t)hh*BTNn + rA)*Dn + dd) = rA2;
                    *(float2*)(o + ((size_t)hh*BTNn + rB)*Dn + dd) = rB2;
                }
            }
        }
    }
}

// ---------------- kernel 3: attention via tensor-core mma + ex2.f16x2 softmax ----------------
#define ATH 352
__global__ __launch_bounds__(ATH, 3) void attn_kernel()
{
    extern __shared__ char smem_raw[];
    __half* sKs = (__half*)smem_raw;                  // [336][24] halves = 16128 B
    __half* sVt = (__half*)(smem_raw + 16128);        // [16][344] halves = 11008 B

    int bt = blockIdx.x, h = blockIdx.y;
    size_t base = ((size_t)h*BTNn + (size_t)bt*Nn)*Dn;
    const __half* gk  = g_kh + base;
    const __half* gv  = g_vh + base;
    const float*  gq  = g_q  + base;
    const float*  gks = g_ks + base;
    const float*  gvs = g_vs + base;
    int tid = threadIdx.x;

    // staging: 8 halves (uint4) per step; K copied packed, V transposed scalar
    for (int i = tid; i < QPAD*2; i += ATH) {
        int key = i >> 1, c = i & 1;
        uint4 kv = make_uint4(0,0,0,0), vv = make_uint4(0,0,0,0);
        if (key < Nn) {
            kv = *(const uint4*)(gk + key*16 + c*8);
            vv = *(const uint4*)(gv + key*16 + c*8);
        }
        *(uint4*)(sKs + key*KSTRIDE + c*8) = kv;
        const __half* vh = (const __half*)&vv;
#pragma unroll
        for (int t = 0; t < 8; ++t)
            sVt[(c*8+t)*VSTRIDE + key] = vh[t];
    }
    __syncthreads();

    int warp = tid >> 5, lane = tid & 31;
    int gid = lane >> 2, tig = lane & 3;
    const __half* bias = g_bias2 + (size_t)h*BPAD*BPAD;

    for (int rb = warp; rb <= 20; rb += 11) {
        int q0 = rb*16;
        int qA = q0 + gid, qB = q0 + gid + 8;
        bool vA = qA < Nn, vB = qB < Nn;

        uint32_t qa0 = 0, qa1 = 0, qa2 = 0, qa3 = 0;
        if (vA) {
            float2 f0 = *(const float2*)(gq + qA*16 + 2*tig);
            float2 f2 = *(const float2*)(gq + qA*16 + 2*tig + 8);
            qa0 = f2h2(f0.x, f0.y);  qa2 = f2h2(f2.x, f2.y);
        }
        if (vB) {
            float2 f1 = *(const float2*)(gq + qB*16 + 2*tig);
            float2 f3 = *(const float2*)(gq + qB*16 + 2*tig + 8);
            qa1 = f2h2(f1.x, f1.y);  qa3 = f2h2(f3.x, f3.y);
        }

        float esv = 1.f;
        {
            int q = q0 + lane;
            if (lane < 16 && q < Nn) {
                float s = 0.f;
#pragma unroll
                for (int d = 0; d < 16; ++d) s = fmaf(gq[q*16+d], gks[q*16+d], s);
                esv = 1.f/(1.f + __expf(-s*0.25f));
            }
        }
        float esA = __shfl_sync(0xffffffffu, esv, gid);
        float esB = __shfl_sync(0xffffffffu, esv, gid + 8);

        float o0[4] = {0.f,0.f,0.f,0.f};
        float o1[4] = {0.f,0.f,0.f,0.f};
        float LA = 0.f, LB = 0.f;

#pragma unroll 1
        for (int kb = 0; kb < 21; ++kb) {
            int k0 = kb*16;
            uint32_t b0a = *(const uint32_t*)(sKs + (k0+gid)*KSTRIDE + 2*tig);
            uint32_t b1a = *(const uint32_t*)(sKs + (k0+gid)*KSTRIDE + 2*tig + 8);
            uint32_t b0b = *(const uint32_t*)(sKs + (k0+8+gid)*KSTRIDE + 2*tig);
            uint32_t b1b = *(const uint32_t*)(sKs + (k0+8+gid)*KSTRIDE + 2*tig + 8);
            float c0[4] = {0.f,0.f,0.f,0.f};
            float c1[4] = {0.f,0.f,0.f,0.f};
            mma16816(c0, qa0, qa1, qa2, qa3, b0a, b1a);
            mma16816(c1, qa0, qa1, qa2, qa3, b0b, b1b);

            uint32_t pa0, pa1, pa2, pa3;
            {
                int kc = k0 + 2*tig;
                float2 bA2 = __half22float2(*(const __half2*)(bias + (size_t)qA*BPAD + kc));
                float2 bB2 = __half22float2(*(const __half2*)(bias + (size_t)qB*BPAD + kc));
                bool u0 = kc < Nn, u1 = (kc+1) < Nn;
                float eA0 = u0 ? fmaf(c0[0], SCLOG2, bA2.x) : -30.f;
                float eA1 = u1 ? fmaf(c0[1], SCLOG2, bA2.y) : -30.f;
                float eB0 = u0 ? fmaf(c0[2], SCLOG2, bB2.x) : -30.f;
                float eB1 = u1 ? fmaf(c0[3], SCLOG2, bB2.y) : -30.f;
                pa0 = ex2h2(f2h2(eA0, eA1));
                pa1 = ex2h2(f2h2(eB0, eB1));
                float2 pA = __half22float2(*(__half2*)&pa0);
                float2 pB = __half22float2(*(__half2*)&pa1);
                LA += pA.x + pA.y;  LB += pB.x + pB.y;
            }
            {
                int kc = k0 + 8 + 2*tig;
                float2 bA2 = __half22float2(*(const __half2*)(bias + (size_t)qA*BPAD + kc));
                float2 bB2 = __half22float2(*(const __half2*)(bias + (size_t)qB*BPAD + kc));
                bool u0 = kc < Nn, u1 = (kc+1) < Nn;
                float eA0 = u0 ? fmaf(c1[0], SCLOG2, bA2.x) : -30.f;
                float eA1 = u1 ? fmaf(c1[1], SCLOG2, bA2.y) : -30.f;
                float eB0 = u0 ? fmaf(c1[2], SCLOG2, bB2.x) : -30.f;
                float eB1 = u1 ? fmaf(c1[3], SCLOG2, bB2.y) : -30.f;
                pa2 = ex2h2(f2h2(eA0, eA1));
                pa3 = ex2h2(f2h2(eB0, eB1));
                float2 pA = __half22float2(*(__half2*)&pa2);
                float2 pB = __half22float2(*(__half2*)&pa3);
                LA += pA.x + pA.y;  LB += pB.x + pB.y;
            }

            uint32_t vb0 = *(const uint32_t*)(sVt + gid*VSTRIDE + k0 + 2*tig);
            uint32_t vb1 = *(const uint32_t*)(sVt + gid*VSTRIDE + k0 + 2*tig + 8);
            mma16816(o0, pa0, pa1, pa2, pa3, vb0, vb1);
            uint32_t vb2 = *(const uint32_t*)(sVt + (8+gid)*VSTRIDE + k0 + 2*tig);
            uint32_t vb3 = *(const uint32_t*)(sVt + (8+gid)*VSTRIDE + k0 + 2*tig + 8);
            mma16816(o1, pa0, pa1, pa2, pa3, vb2, vb3);
        }

        LA += __shfl_xor_sync(0xffffffffu, LA, 1);
        LA += __shfl_xor_sync(0xffffffffu, LA, 2);
        LB += __shfl_xor_sync(0xffffffffu, LB, 1);
        LB += __shfl_xor_sync(0xffffffffu, LB, 2);

        if (vA) {
            float inv = 1.f/(esA + LA);
            __half* op = g_valh + ((size_t)bt*Nn + qA)*Fn + h*16;
            float2 vs0 = *(const float2*)(gvs + qA*16 + 2*tig);
            float2 vs1 = *(const float2*)(gvs + qA*16 + 8 + 2*tig);
            *(uint32_t*)(op + 2*tig) = f2h2(
                fmaf(o0[0] - LA*vs0.x, inv, vs0.x),
                fmaf(o0[1] - LA*vs0.y, inv, vs0.y));
            *(uint32_t*)(op + 8 + 2*tig) = f2h2(
                fmaf(o1[0] - LA*vs1.x, inv, vs1.x),
                fmaf(o1[1] - LA*vs1.y, inv, vs1.y));
        }
        if (vB) {
            float inv = 1.f/(esB + LB);
            __half* op = g_valh + ((size_t)bt*Nn + qB)*Fn + h*16;
            float2 vs0 = *(const float2*)(gvs + qB*16 + 2*tig);
            float2 vs1 = *(const float2*)(gvs + qB*16 + 8 + 2*tig);
            *(uint32_t*)(op + 2*tig) = f2h2(
                fmaf(o0[2] - LB*vs0.x, inv, vs0.x),
                fmaf(o0[3] - LB*vs0.y, inv, vs0.y));
            *(uint32_t*)(op + 8 + 2*tig) = f2h2(
                fmaf(o1[2] - LB*vs1.x, inv, vs1.x),
                fmaf(o1[3] - LB*vs1.y, inv, vs1.y));
        }
    }
}

// ---------------- kernel 4: FFN via tensor-core MMA (512 thr) ----------------
__global__ __launch_bounds__(512, 2) void ffn_kernel(
    const float* __restrict__ x,
    const float* __restrict__ Wf1, const float* __restrict__ bf1,
    const float* __restrict__ Wf2, const float* __restrict__ bf2,
    const float* __restrict__ gln, const float* __restrict__ bln,
    float* __restrict__ out)
{
    extern __shared__ char smraw[];
    __half* sW1 = (__half*)smraw;                 // 64*72 halves = 9216 B
    __half* sW2 = (__half*)(smraw + 9216);        // 9216 B
    float* sb1 = (float*)(smraw + 18432);         // 64
    float* sb2 = sb1 + 64;
    float* sg  = sb1 + 128;
    float* sbl = sb1 + 192;

    for (int i = threadIdx.x; i < 4096; i += 512) {
        int f = i >> 6, c = i & 63;
        sW1[f*WSTRIDE + c] = __float2half(Wf1[i]);
        sW2[f*WSTRIDE + c] = __float2half(Wf2[i]);
    }
    if (threadIdx.x < 64) {
        sb1[threadIdx.x] = bf1[threadIdx.x];
        sb2[threadIdx.x] = bf2[threadIdx.x];
        sg [threadIdx.x] = gln[threadIdx.x];
        sbl[threadIdx.x] = bln[threadIdx.x];
    }
    __syncthreads();

    int warp = threadIdx.x >> 5, lane = threadIdx.x & 31;
    int gid = lane >> 2, tig = lane & 3;

    int tile = blockIdx.x*16 + warp;
    if (tile >= 3900) return;
    {
        int rA = tile*16 + gid, rB = rA + 8;

        // A frags: direct half2 loads from fp16 g_valh (no conversion)
        uint32_t a[4][4];
#pragma unroll
        for (int j = 0; j < 4; ++j) {
            a[j][0] = *(const uint32_t*)(g_valh + (size_t)rA*64 + 16*j + 2*tig);
            a[j][1] = *(const uint32_t*)(g_valh + (size_t)rB*64 + 16*j + 2*tig);
            a[j][2] = *(const uint32_t*)(g_valh + (size_t)rA*64 + 16*j + 2*tig + 8);
            a[j][3] = *(const uint32_t*)(g_valh + (size_t)rB*64 + 16*j + 2*tig + 8);
        }

        uint32_t pa[4][4];
#pragma unroll
        for (int j2 = 0; j2 < 4; ++j2) {
            float d0[4] = {0.f,0.f,0.f,0.f};
            float d1[4] = {0.f,0.f,0.f,0.f};
#pragma unroll
            for (int j = 0; j < 4; ++j) {
                uint32_t b0 = *(const uint32_t*)(sW1 + (16*j2+gid)*WSTRIDE + 16*j + 2*tig);
                uint32_t b1 = *(const uint32_t*)(sW1 + (16*j2+gid)*WSTRIDE + 16*j + 2*tig + 8);
                mma16816(d0, a[j][0], a[j][1], a[j][2], a[j][3], b0, b1);
                uint32_t c0 = *(const uint32_t*)(sW1 + (16*j2+8+gid)*WSTRIDE + 16*j + 2*tig);
                uint32_t c1 = *(const uint32_t*)(sW1 + (16*j2+8+gid)*WSTRIDE + 16*j + 2*tig + 8);
                mma16816(d1, a[j][0], a[j][1], a[j][2], a[j][3], c0, c1);
            }
            int fb = 16*j2 + 2*tig;
            float b00 = sb1[fb], b01 = sb1[fb+1], b08 = sb1[fb+8], b09 = sb1[fb+9];
            pa[j2][0] = f2h2(gelu_exact(d0[0]+b00), gelu_exact(d0[1]+b01));
            pa[j2][1] = f2h2(gelu_exact(d0[2]+b00), gelu_exact(d0[3]+b01));
            pa[j2][2] = f2h2(gelu_exact(d1[0]+b08), gelu_exact(d1[1]+b09));
            pa[j2][3] = f2h2(gelu_exact(d1[2]+b08), gelu_exact(d1[3]+b09));
        }

        float hh[8][4];
#pragma unroll
        for (int nch = 0; nch < 8; ++nch) {
            float d[4] = {0.f,0.f,0.f,0.f};
#pragma unroll
            for (int j = 0; j < 4; ++j) {
                uint32_t b0 = *(const uint32_t*)(sW2 + (nch*8+gid)*WSTRIDE + 16*j + 2*tig);
                uint32_t b1 = *(const uint32_t*)(sW2 + (nch*8+gid)*WSTRIDE + 16*j + 2*tig + 8);
                mma16816(d, pa[j][0], pa[j][1], pa[j][2], pa[j][3], b0, b1);
            }
            int f = nch*8 + 2*tig;
            float2 xA = *(const float2*)(x + (size_t)rA*64 + f);
            float2 xB = *(const float2*)(x + (size_t)rB*64 + f);
            hh[nch][0] = d[0] + sb2[f]   + xA.x;
            hh[nch][1] = d[1] + sb2[f+1] + xA.y;
            hh[nch][2] = d[2] + sb2[f]   + xB.x;
            hh[nch][3] = d[3] + sb2[f+1] + xB.y;
        }

        float s1A = 0.f, s2A = 0.f, s1B = 0.f, s2B = 0.f;
#pragma unroll
        for (int nch = 0; nch < 8; ++nch) {
            s1A += hh[nch][0] + hh[nch][1];
            s2A += hh[nch][0]*hh[nch][0] + hh[nch][1]*hh[nch][1];
            s1B += hh[nch][2] + hh[nch][3];
            s2B += hh[nch][2]*hh[nch][2] + hh[nch][3]*hh[nch][3];
        }
        s1A += __shfl_xor_sync(0xffffffffu, s1A, 1);
        s2A += __shfl_xor_sync(0xffffffffu, s2A, 1);
        s1B += __shfl_xor_sync(0xffffffffu, s1B, 1);
        s2B += __shfl_xor_sync(0xffffffffu, s2B, 1);
        s1A += __shfl_xor_sync(0xffffffffu, s1A, 2);
        s2A += __shfl_xor_sync(0xffffffffu, s2A, 2);
        s1B += __shfl_xor_sync(0xffffffffu, s1B, 2);
        s2B += __shfl_xor_sync(0xffffffffu, s2B, 2);

        float mA = s1A*(1.f/64.f), mB = s1B*(1.f/64.f);
        float rsA = rsqrtf(s2A*(1.f/64.f) - mA*mA + 1e-5f);
        float rsB = rsqrtf(s2B*(1.f/64.f) - mB*mB + 1e-5f);

#pragma unroll
        for (int nch = 0; nch < 8; ++nch) {
            int f = nch*8 + 2*tig;
            float g0 = sg[f], g1 = sg[f+1], l0 = sbl[f], l1 = sbl[f+1];
            float2 oA, oB;
            oA.x = fmaf(g0, (hh[nch][0]-mA)*rsA, l0);
            oA.y = fmaf(g1, (hh[nch][1]-mA)*rsA, l1);
            oB.x = fmaf(g0, (hh[nch][2]-mB)*rsB, l0);
            oB.y = fmaf(g1, (hh[nch][3]-mB)*rsB, l1);
            *(float2*)(out + (size_t)rA*64 + f) = oA;
            *(float2*)(out + (size_t)rB*64 + f) = oB;
        }
    }
}

// ---------------- launch ----------------
extern "C" void kernel_launch(void* const* d_in, const int* in_sizes, int n_in,
                              void* d_out, int out_size)
{
    const float* x   = (const float*)d_in[0];
    const float* A   = (const float*)d_in[1];
    const float* AT  = (const float*)d_in[2];
    const float* Wq  = (const float*)d_in[3];
    const float* bq  = (const float*)d_in[4];
    const float* Wk  = (const float*)d_in[5];
    const float* bk  = (const float*)d_in[6];
    const float* Wks = (const float*)d_in[7];
    const float* bks = (const float*)d_in[8];
    const float* Wv  = (const float*)d_in[9];
    const float* bv  = (const float*)d_in[10];
    const float* Wvs = (const float*)d_in[11];
    const float* bvs = (const float*)d_in[12];
    const float* Wdi = (const float*)d_in[13];
    const float* Wdo = (const float*)d_in[14];
    const float* Wf1 = (const float*)d_in[15];
    const float* bf1 = (const float*)d_in[16];
    const float* Wf2 = (const float*)d_in[17];
    const float* bf2 = (const float*)d_in[18];
    const float* gln = (const float*)d_in[19];
    const float* bln = (const float*)d_in[20];
    float* out = (float*)d_out;

    cudaFuncSetAttribute(proj_kernel, cudaFuncAttributeMaxDynamicSharedMemorySize, 47360);
    cudaFuncSetAttribute(attn_kernel, cudaFuncAttributeMaxDynamicSharedMemorySize, 27136);
    cudaFuncSetAttribute(ffn_kernel,  cudaFuncAttributeMaxDynamicSharedMemorySize, 19712);

    bias_kernel<<<(KHn*NNn + 255)/256, 256>>>(A, AT, Wdi, Wdo);
    proj_kernel<<<244, 512, 47360>>>(x, Wq, bq, Wk, bk, Wks, bks, Wv, bv, Wvs, bvs);
    dim3 ag(BTn, KHn);
    attn_kernel<<<ag, ATH, 27136>>>();
    ffn_kernel<<<244, 512, 19712>>>(x, Wf1, bf1, Wf2, bf2, gln, bln, out);
}

// round 17
// speedup vs baseline: 3.4127x; 1.0309x over previous
#include <cuda_runtime.h>
#include <cuda_fp16.h>
#include <math.h>
#include <stdint.h>

#define Bn 16
#define Tn 12
#define Nn 325
#define Fn 64
#define KHn 4
#define Dn 16
#define KDn 3
#define BTn (Bn*Tn)            // 192
#define BTNn (BTn*Nn)          // 62400
#define NNn (Nn*Nn)            // 105625
#define QPAD 336               // padded node count (21*16)
#define BPAD 336
#define KSTRIDE 24             // halves per K row in smem
#define VSTRIDE 344            // halves per Vt row in smem
#define WSTRIDE 72             // halves per weight row in smem (bank-mult 4, conflict-free)
#define SCLOG2 0.36067376022224085f   // 0.25 * log2(e)
#define L2E    1.4426950408889634f

// ---------------- scratch (device globals; zero-initialized, no allocation) ----------------
__device__ float  g_q [KHn*BTNn*Dn + 256];
__device__ __half g_kh[KHn*BTNn*Dn + 256];    // fp16 (consumed only via fp16 MMA)
__device__ float  g_ks[KHn*BTNn*Dn + 256];
__device__ __half g_vh[KHn*BTNn*Dn + 256];    // fp16
__device__ float  g_vs[KHn*BTNn*Dn + 256];
__device__ __half g_bias2[KHn*BPAD*BPAD];     // [h][q][k] fp16, PRE-SCALED by log2(e)
__device__ __half g_valh[BTNn*Fn + 256];      // fp16 (consumed only via fp16 MMA)

// ---------------- mma helper: m16n8k16 row.col f32 += f16*f16 ----------------
__device__ __forceinline__ void mma16816(float d[4],
    uint32_t a0, uint32_t a1, uint32_t a2, uint32_t a3,
    uint32_t b0, uint32_t b1)
{
    asm volatile(
        "mma.sync.aligned.m16n8k16.row.col.f32.f16.f16.f32 "
        "{%0,%1,%2,%3}, {%4,%5,%6,%7}, {%8,%9}, {%0,%1,%2,%3};"
        : "+f"(d[0]), "+f"(d[1]), "+f"(d[2]), "+f"(d[3])
        : "r"(a0), "r"(a1), "r"(a2), "r"(a3), "r"(b0), "r"(b1));
}
__device__ __forceinline__ uint32_t f2h2(float x, float y) {
    __half2 h = __floats2half2_rn(x, y);
    return *(uint32_t*)&h;
}
__device__ __forceinline__ uint32_t ex2h2(uint32_t e) {
    uint32_t p;
    asm("ex2.approx.f16x2 %0, %1;" : "=r"(p) : "r"(e));
    return p;
}
__device__ __forceinline__ float gelu_exact(float v) {
    return 0.5f*v*(1.f + erff(v*0.7071067811865476f));
}

// ---------------- kernel 1: fused projection (blocks 0..243) + bias (blocks 244..295) ----------------
__global__ __launch_bounds__(512, 2) void proj_kernel(
    const float* __restrict__ x,
    const float* __restrict__ Wq,  const float* __restrict__ bq,
    const float* __restrict__ Wk,  const float* __restrict__ bk,
    const float* __restrict__ Wks, const float* __restrict__ bks,
    const float* __restrict__ Wv,  const float* __restrict__ bv,
    const float* __restrict__ Wvs, const float* __restrict__ bvs,
    const float* __restrict__ A,   const float* __restrict__ AT,
    const float* __restrict__ Wdi, const float* __restrict__ Wdo)
{
    if (blockIdx.x >= 244) {
        // ---- bias branch: graph-diffusion bias -> fp16*log2e padded [h][q][k] ----
        for (int idx = (blockIdx.x - 244)*512 + threadIdx.x; idx < KHn*NNn; idx += 52*512) {
            int h = idx / NNn, nm = idx - h*NNn;
            int n = nm / Nn, m = nm - n*Nn;
            float s = 0.f;
            if (h < 2) {
#pragma unroll
                for (int j = 0; j < KDn; ++j) s = fmaf(Wdi[(h*KDn+j)*NNn+nm], A[j*NNn+nm], s);
            } else {
#pragma unroll
                for (int j = 0; j < KDn; ++j) s = fmaf(Wdo[((h-2)*KDn+j)*NNn+nm], AT[j*NNn+nm], s);
            }
            g_bias2[((size_t)h*BPAD + n)*BPAD + m] = __float2half(s * L2E);
        }
        return;
    }

    extern __shared__ char smraw[];
    __half* sW = (__half*)smraw;                  // 5 * 64*72 halves = 46080 B
    float* sbias = (float*)(smraw + 46080);       // 5 * 64 floats = 1280 B

    const float* Ws[5] = {Wq, Wk, Wks, Wv, Wvs};
    const float* bs[5] = {bq, bk, bks, bv, bvs};
    for (int i = threadIdx.x; i < 5*4096; i += 512) {
        int p = i >> 12, idx = i & 4095;
        int f = idx >> 6, c = idx & 63;
        sW[p*4608 + f*WSTRIDE + c] = __float2half(Ws[p][f*64 + c]);
    }
    for (int i = threadIdx.x; i < 5*64; i += 512)
        sbias[i] = bs[i >> 6][i & 63];
    __syncthreads();

    int warp = threadIdx.x >> 5, lane = threadIdx.x & 31;
    int gid = lane >> 2, tig = lane & 3;
    float* outpF[5] = {g_q, 0, g_ks, 0, g_vs};

    int tile = blockIdx.x*16 + warp;
    if (tile >= 3900) return;
    {
        int r0 = tile*16;
        int rA = r0 + gid, rB = r0 + gid + 8;

        uint32_t a[4][4];
#pragma unroll
        for (int j = 0; j < 4; ++j) {
            float2 fA0 = *(const float2*)(x + (size_t)rA*64 + 16*j + 2*tig);
            float2 fB0 = *(const float2*)(x + (size_t)rB*64 + 16*j + 2*tig);
            float2 fA8 = *(const float2*)(x + (size_t)rA*64 + 16*j + 2*tig + 8);
            float2 fB8 = *(const float2*)(x + (size_t)rB*64 + 16*j + 2*tig + 8);
            a[j][0] = f2h2(fA0.x, fA0.y);
            a[j][1] = f2h2(fB0.x, fB0.y);
            a[j][2] = f2h2(fA8.x, fA8.y);
            a[j][3] = f2h2(fB8.x, fB8.y);
        }

#pragma unroll 1
        for (int p = 0; p < 5; ++p) {
            const __half* wp = sW + p*4608;
#pragma unroll
            for (int nch = 0; nch < 8; ++nch) {
                float d[4] = {0.f, 0.f, 0.f, 0.f};
#pragma unroll
                for (int j = 0; j < 4; ++j) {
                    uint32_t b0 = *(const uint32_t*)(wp + (nch*8+gid)*WSTRIDE + 16*j + 2*tig);
                    uint32_t b1 = *(const uint32_t*)(wp + (nch*8+gid)*WSTRIDE + 16*j + 2*tig + 8);
                    mma16816(d, a[j][0], a[j][1], a[j][2], a[j][3], b0, b1);
                }
                int f = nch*8 + 2*tig;
                int hh = f >> 4, dd = f & 15;
                float bb0 = sbias[p*64 + f], bb1 = sbias[p*64 + f + 1];
                if (p == 1 || p == 3) {
                    __half* oh = (p == 1) ? g_kh : g_vh;
                    *(uint32_t*)(oh + ((size_t)hh*BTNn + rA)*Dn + dd) = f2h2(d[0]+bb0, d[1]+bb1);
                    *(uint32_t*)(oh + ((size_t)hh*BTNn + rB)*Dn + dd) = f2h2(d[2]+bb0, d[3]+bb1);
                } else {
                    float* o = outpF[p];
                    float2 rA2, rB2;
                    rA2.x = d[0] + bb0;  rA2.y = d[1] + bb1;
                    rB2.x = d[2] + bb0;  rB2.y = d[3] + bb1;
                    *(float2*)(o + ((size_t)hh*BTNn + rA)*Dn + dd) = rA2;
                    *(float2*)(o + ((size_t)hh*BTNn + rB)*Dn + dd) = rB2;
                }
            }
        }
    }
}

// ---------------- kernel 2: attention via tensor-core mma + ex2.f16x2 softmax ----------------
#define ATH 352
__global__ __launch_bounds__(ATH, 3) void attn_kernel()
{
    extern __shared__ char smem_raw[];
    __half* sKs = (__half*)smem_raw;                  // [336][24] halves = 16128 B
    __half* sVt = (__half*)(smem_raw + 16128);        // [16][344] halves = 11008 B

    int bt = blockIdx.x, h = blockIdx.y;
    size_t base = ((size_t)h*BTNn + (size_t)bt*Nn)*Dn;
    const __half* gk  = g_kh + base;
    const __half* gv  = g_vh + base;
    const float*  gq  = g_q  + base;
    const float*  gks = g_ks + base;
    const float*  gvs = g_vs + base;
    int tid = threadIdx.x;

    for (int i = tid; i < QPAD*2; i += ATH) {
        int key = i >> 1, c = i & 1;
        uint4 kv = make_uint4(0,0,0,0), vv = make_uint4(0,0,0,0);
        if (key < Nn) {
            kv = *(const uint4*)(gk + key*16 + c*8);
            vv = *(const uint4*)(gv + key*16 + c*8);
        }
        *(uint4*)(sKs + key*KSTRIDE + c*8) = kv;
        const __half* vh = (const __half*)&vv;
#pragma unroll
        for (int t = 0; t < 8; ++t)
            sVt[(c*8+t)*VSTRIDE + key] = vh[t];
    }
    __syncthreads();

    int warp = tid >> 5, lane = tid & 31;
    int gid = lane >> 2, tig = lane & 3;
    const __half* bias = g_bias2 + (size_t)h*BPAD*BPAD;

    for (int rb = warp; rb <= 20; rb += 11) {
        int q0 = rb*16;
        int qA = q0 + gid, qB = q0 + gid + 8;
        bool vA = qA < Nn, vB = qB < Nn;

        uint32_t qa0 = 0, qa1 = 0, qa2 = 0, qa3 = 0;
        if (vA) {
            float2 f0 = *(const float2*)(gq + qA*16 + 2*tig);
            float2 f2 = *(const float2*)(gq + qA*16 + 2*tig + 8);
            qa0 = f2h2(f0.x, f0.y);  qa2 = f2h2(f2.x, f2.y);
        }
        if (vB) {
            float2 f1 = *(const float2*)(gq + qB*16 + 2*tig);
            float2 f3 = *(const float2*)(gq + qB*16 + 2*tig + 8);
            qa1 = f2h2(f1.x, f1.y);  qa3 = f2h2(f3.x, f3.y);
        }

        float esv = 1.f;
        {
            int q = q0 + lane;
            if (lane < 16 && q < Nn) {
                float s = 0.f;
#pragma unroll
                for (int d = 0; d < 16; ++d) s = fmaf(gq[q*16+d], gks[q*16+d], s);
                esv = 1.f/(1.f + __expf(-s*0.25f));
            }
        }
        float esA = __shfl_sync(0xffffffffu, esv, gid);
        float esB = __shfl_sync(0xffffffffu, esv, gid + 8);

        float o0[4] = {0.f,0.f,0.f,0.f};
        float o1[4] = {0.f,0.f,0.f,0.f};
        float LA = 0.f, LB = 0.f;

#pragma unroll 2
        for (int kb = 0; kb < 21; ++kb) {
            int k0 = kb*16;
            uint32_t b0a = *(const uint32_t*)(sKs + (k0+gid)*KSTRIDE + 2*tig);
            uint32_t b1a = *(const uint32_t*)(sKs + (k0+gid)*KSTRIDE + 2*tig + 8);
            uint32_t b0b = *(const uint32_t*)(sKs + (k0+8+gid)*KSTRIDE + 2*tig);
            uint32_t b1b = *(const uint32_t*)(sKs + (k0+8+gid)*KSTRIDE + 2*tig + 8);
            float c0[4] = {0.f,0.f,0.f,0.f};
            float c1[4] = {0.f,0.f,0.f,0.f};
            mma16816(c0, qa0, qa1, qa2, qa3, b0a, b1a);
            mma16816(c1, qa0, qa1, qa2, qa3, b0b, b1b);

            uint32_t pa0, pa1, pa2, pa3;
            {
                int kc0 = k0 + 2*tig;
                int kc1 = k0 + 8 + 2*tig;
                float2 bA20 = __half22float2(*(const __half2*)(bias + (size_t)qA*BPAD + kc0));
                float2 bB20 = __half22float2(*(const __half2*)(bias + (size_t)qB*BPAD + kc0));
                float2 bA21 = __half22float2(*(const __half2*)(bias + (size_t)qA*BPAD + kc1));
                float2 bB21 = __half22float2(*(const __half2*)(bias + (size_t)qB*BPAD + kc1));
                bool u00 = kc0 < Nn, u01 = (kc0+1) < Nn;
                bool u10 = kc1 < Nn, u11 = (kc1+1) < Nn;
                float eA0 = u00 ? fmaf(c0[0], SCLOG2, bA20.x) : -30.f;
                float eA1 = u01 ? fmaf(c0[1], SCLOG2, bA20.y) : -30.f;
                float eB0 = u00 ? fmaf(c0[2], SCLOG2, bB20.x) : -30.f;
                float eB1 = u01 ? fmaf(c0[3], SCLOG2, bB20.y) : -30.f;
                float eA2 = u10 ? fmaf(c1[0], SCLOG2, bA21.x) : -30.f;
                float eA3 = u11 ? fmaf(c1[1], SCLOG2, bA21.y) : -30.f;
                float eB2 = u10 ? fmaf(c1[2], SCLOG2, bB21.x) : -30.f;
                float eB3 = u11 ? fmaf(c1[3], SCLOG2, bB21.y) : -30.f;
                pa0 = ex2h2(f2h2(eA0, eA1));
                pa1 = ex2h2(f2h2(eB0, eB1));
                pa2 = ex2h2(f2h2(eA2, eA3));
                pa3 = ex2h2(f2h2(eB2, eB3));
                // L accumulation via hadd2 pairs (fp16 single add, then fp32)
                __half2 sA = __hadd2(*(__half2*)&pa0, *(__half2*)&pa2);
                __half2 sB = __hadd2(*(__half2*)&pa1, *(__half2*)&pa3);
                float2 fA = __half22float2(sA);
                float2 fB = __half22float2(sB);
                LA += fA.x + fA.y;
                LB += fB.x + fB.y;
            }

            uint32_t vb0 = *(const uint32_t*)(sVt + gid*VSTRIDE + k0 + 2*tig);
            uint32_t vb1 = *(const uint32_t*)(sVt + gid*VSTRIDE + k0 + 2*tig + 8);
            mma16816(o0, pa0, pa1, pa2, pa3, vb0, vb1);
            uint32_t vb2 = *(const uint32_t*)(sVt + (8+gid)*VSTRIDE + k0 + 2*tig);
            uint32_t vb3 = *(const uint32_t*)(sVt + (8+gid)*VSTRIDE + k0 + 2*tig + 8);
            mma16816(o1, pa0, pa1, pa2, pa3, vb2, vb3);
        }

        LA += __shfl_xor_sync(0xffffffffu, LA, 1);
        LA += __shfl_xor_sync(0xffffffffu, LA, 2);
        LB += __shfl_xor_sync(0xffffffffu, LB, 1);
        LB += __shfl_xor_sync(0xffffffffu, LB, 2);

        if (vA) {
            float inv = 1.f/(esA + LA);
            __half* op = g_valh + ((size_t)bt*Nn + qA)*Fn + h*16;
            float2 vs0 = *(const float2*)(gvs + qA*16 + 2*tig);
            float2 vs1 = *(const float2*)(gvs + qA*16 + 8 + 2*tig);
            *(uint32_t*)(op + 2*tig) = f2h2(
                fmaf(o0[0] - LA*vs0.x, inv, vs0.x),
                fmaf(o0[1] - LA*vs0.y, inv, vs0.y));
            *(uint32_t*)(op + 8 + 2*tig) = f2h2(
                fmaf(o1[0] - LA*vs1.x, inv, vs1.x),
                fmaf(o1[1] - LA*vs1.y, inv, vs1.y));
        }
        if (vB) {
            float inv = 1.f/(esB + LB);
            __half* op = g_valh + ((size_t)bt*Nn + qB)*Fn + h*16;
            float2 vs0 = *(const float2*)(gvs + qB*16 + 2*tig);
            float2 vs1 = *(const float2*)(gvs + qB*16 + 8 + 2*tig);
            *(uint32_t*)(op + 2*tig) = f2h2(
                fmaf(o0[2] - LB*vs0.x, inv, vs0.x),
                fmaf(o0[3] - LB*vs0.y, inv, vs0.y));
            *(uint32_t*)(op + 8 + 2*tig) = f2h2(
                fmaf(o1[2] - LB*vs1.x, inv, vs1.x),
                fmaf(o1[3] - LB*vs1.y, inv, vs1.y));
        }
    }
}

// ---------------- kernel 3: FFN via tensor-core MMA (512 thr) ----------------
__global__ __launch_bounds__(512, 2) void ffn_kernel(
    const float* __restrict__ x,
    const float* __restrict__ Wf1, const float* __restrict__ bf1,
    const float* __restrict__ Wf2, const float* __restrict__ bf2,
    const float* __restrict__ gln, const float* __restrict__ bln,
    float* __restrict__ out)
{
    extern __shared__ char smraw[];
    __half* sW1 = (__half*)smraw;                 // 64*72 halves = 9216 B
    __half* sW2 = (__half*)(smraw + 9216);        // 9216 B
    float* sb1 = (float*)(smraw + 18432);         // 64
    float* sb2 = sb1 + 64;
    float* sg  = sb1 + 128;
    float* sbl = sb1 + 192;

    for (int i = threadIdx.x; i < 4096; i += 512) {
        int f = i >> 6, c = i & 63;
        sW1[f*WSTRIDE + c] = __float2half(Wf1[i]);
        sW2[f*WSTRIDE + c] = __float2half(Wf2[i]);
    }
    if (threadIdx.x < 64) {
        sb1[threadIdx.x] = bf1[threadIdx.x];
        sb2[threadIdx.x] = bf2[threadIdx.x];
        sg [threadIdx.x] = gln[threadIdx.x];
        sbl[threadIdx.x] = bln[threadIdx.x];
    }
    __syncthreads();

    int warp = threadIdx.x >> 5, lane = threadIdx.x & 31;
    int gid = lane >> 2, tig = lane & 3;

    int tile = blockIdx.x*16 + warp;
    if (tile >= 3900) return;
    {
        int rA = tile*16 + gid, rB = rA + 8;

        uint32_t a[4][4];
#pragma unroll
        for (int j = 0; j < 4; ++j) {
            a[j][0] = *(const uint32_t*)(g_valh + (size_t)rA*64 + 16*j + 2*tig);
            a[j][1] = *(const uint32_t*)(g_valh + (size_t)rB*64 + 16*j + 2*tig);
            a[j][2] = *(const uint32_t*)(g_valh + (size_t)rA*64 + 16*j + 2*tig + 8);
            a[j][3] = *(const uint32_t*)(g_valh + (size_t)rB*64 + 16*j + 2*tig + 8);
        }

        uint32_t pa[4][4];
#pragma unroll
        for (int j2 = 0; j2 < 4; ++j2) {
            float d0[4] = {0.f,0.f,0.f,0.f};
            float d1[4] = {0.f,0.f,0.f,0.f};
#pragma unroll
            for (int j = 0; j < 4; ++j) {
                uint32_t b0 = *(const uint32_t*)(sW1 + (16*j2+gid)*WSTRIDE + 16*j + 2*tig);
                uint32_t b1 = *(const uint32_t*)(sW1 + (16*j2+gid)*WSTRIDE + 16*j + 2*tig + 8);
                mma16816(d0, a[j][0], a[j][1], a[j][2], a[j][3], b0, b1);
                uint32_t c0 = *(const uint32_t*)(sW1 + (16*j2+8+gid)*WSTRIDE + 16*j + 2*tig);
                uint32_t c1 = *(const uint32_t*)(sW1 + (16*j2+8+gid)*WSTRIDE + 16*j + 2*tig + 8);
                mma16816(d1, a[j][0], a[j][1], a[j][2], a[j][3], c0, c1);
            }
            int fb = 16*j2 + 2*tig;
            float b00 = sb1[fb], b01 = sb1[fb+1], b08 = sb1[fb+8], b09 = sb1[fb+9];
            pa[j2][0] = f2h2(gelu_exact(d0[0]+b00), gelu_exact(d0[1]+b01));
            pa[j2][1] = f2h2(gelu_exact(d0[2]+b00), gelu_exact(d0[3]+b01));
            pa[j2][2] = f2h2(gelu_exact(d1[0]+b08), gelu_exact(d1[1]+b09));
            pa[j2][3] = f2h2(gelu_exact(d1[2]+b08), gelu_exact(d1[3]+b09));
        }

        float hh[8][4];
#pragma unroll
        for (int nch = 0; nch < 8; ++nch) {
            float d[4] = {0.f,0.f,0.f,0.f};
#pragma unroll
            for (int j = 0; j < 4; ++j) {
                uint32_t b0 = *(const uint32_t*)(sW2 + (nch*8+gid)*WSTRIDE + 16*j + 2*tig);
                uint32_t b1 = *(const uint32_t*)(sW2 + (nch*8+gid)*WSTRIDE + 16*j + 2*tig + 8);
                mma16816(d, pa[j][0], pa[j][1], pa[j][2], pa[j][3], b0, b1);
            }
            int f = nch*8 + 2*tig;
            float2 xA = *(const float2*)(x + (size_t)rA*64 + f);
            float2 xB = *(const float2*)(x + (size_t)rB*64 + f);
            hh[nch][0] = d[0] + sb2[f]   + xA.x;
            hh[nch][1] = d[1] + sb2[f+1] + xA.y;
            hh[nch][2] = d[2] + sb2[f]   + xB.x;
            hh[nch][3] = d[3] + sb2[f+1] + xB.y;
        }

        float s1A = 0.f, s2A = 0.f, s1B = 0.f, s2B = 0.f;
#pragma unroll
        for (int nch = 0; nch < 8; ++nch) {
            s1A += hh[nch][0] + hh[nch][1];
            s2A += hh[nch][0]*hh[nch][0] + hh[nch][1]*hh[nch][1];
            s1B += hh[nch][2] + hh[nch][3];
            s2B += hh[nch][2]*hh[nch][2] + hh[nch][3]*hh[nch][3];
        }
        s1A += __shfl_xor_sync(0xffffffffu, s1A, 1);
        s2A += __shfl_xor_sync(0xffffffffu, s2A, 1);
        s1B += __shfl_xor_sync(0xffffffffu, s1B, 1);
        s2B += __shfl_xor_sync(0xffffffffu, s2B, 1);
        s1A += __shfl_xor_sync(0xffffffffu, s1A, 2);
        s2A += __shfl_xor_sync(0xffffffffu, s2A, 2);
        s1B += __shfl_xor_sync(0xffffffffu, s1B, 2);
        s2B += __shfl_xor_sync(0xffffffffu, s2B, 2);

        float mA = s1A*(1.f/64.f), mB = s1B*(1.f/64.f);
        float rsA = rsqrtf(s2A*(1.f/64.f) - mA*mA + 1e-5f);
        float rsB = rsqrtf(s2B*(1.f/64.f) - mB*mB + 1e-5f);

#pragma unroll
        for (int nch = 0; nch < 8; ++nch) {
            int f = nch*8 + 2*tig;
            float g0 = sg[f], g1 = sg[f+1], l0 = sbl[f], l1 = sbl[f+1];
            float2 oA, oB;
            oA.x = fmaf(g0, (hh[nch][0]-mA)*rsA, l0);
            oA.y = fmaf(g1, (hh[nch][1]-mA)*rsA, l1);
            oB.x = fmaf(g0, (hh[nch][2]-mB)*rsB, l0);
            oB.y = fmaf(g1, (hh[nch][3]-mB)*rsB, l1);
            *(float2*)(out + (size_t)rA*64 + f) = oA;
            *(float2*)(out + (size_t)rB*64 + f) = oB;
        }
    }
}

// ---------------- launch ----------------
extern "C" void kernel_launch(void* const* d_in, const int* in_sizes, int n_in,
                              void* d_out, int out_size)
{
    const float* x   = (const float*)d_in[0];
    const float* A   = (const float*)d_in[1];
    const float* AT  = (const float*)d_in[2];
    const float* Wq  = (const float*)d_in[3];
    const float* bq  = (const float*)d_in[4];
    const float* Wk  = (const float*)d_in[5];
    const float* bk  = (const float*)d_in[6];
    const float* Wks = (const float*)d_in[7];
    const float* bks = (const float*)d_in[8];
    const float* Wv  = (const float*)d_in[9];
    const float* bv  = (const float*)d_in[10];
    const float* Wvs = (const float*)d_in[11];
    const float* bvs = (const float*)d_in[12];
    const float* Wdi = (const float*)d_in[13];
    const float* Wdo = (const float*)d_in[14];
    const float* Wf1 = (const float*)d_in[15];
    const float* bf1 = (const float*)d_in[16];
    const float* Wf2 = (const float*)d_in[17];
    const float* bf2 = (const float*)d_in[18];
    const float* gln = (const float*)d_in[19];
    const float* bln = (const float*)d_in[20];
    float* out = (float*)d_out;

    cudaFuncSetAttribute(proj_kernel, cudaFuncAttributeMaxDynamicSharedMemorySize, 47360);
    cudaFuncSetAttribute(attn_kernel, cudaFuncAttributeMaxDynamicSharedMemorySize, 27136);
    cudaFuncSetAttribute(ffn_kernel,  cudaFuncAttributeMaxDynamicSharedMemorySize, 19712);

    proj_kernel<<<296, 512, 47360>>>(x, Wq, bq, Wk, bk, Wks, bks, Wv, bv, Wvs, bvs,
                                     A, AT, Wdi, Wdo);
    dim3 ag(BTn, KHn);
    attn_kernel<<<ag, ATH, 27136>>>();
    ffn_kernel<<<244, 512, 19712>>>(x, Wf1, bf1, Wf2, bf2, gln, bln, out);
}